// round 3
// baseline (speedup 1.0000x reference)
#include <cuda_runtime.h>
#include <math.h>

#define MROWS 4096           // B*S
#define EDIM  1024
#define SLEN  2048
#define NHEAD 8

// ---------------- scratch (device globals: allocation-free) ----------------
__device__ float g_q[(size_t)MROWS * EDIM];
__device__ float g_k[(size_t)MROWS * EDIM];
__device__ float g_v[(size_t)MROWS * EDIM];
__device__ float g_o[(size_t)MROWS * EDIM];

// ======================================================================
// GEMM: C[M,N] = A[M,K] @ B[N,K]^T   (NT, both K-contiguous)
// optional epilogue: C = (C + bias[n]) * (1 - *dwp)
// BM=BN=128, BK=16, 256 threads, 8x8 microtile
// ======================================================================
__global__ void __launch_bounds__(256) gemm_nt_kernel(
    const float* __restrict__ A, const float* __restrict__ B, float* __restrict__ C,
    int M, int N, int K, const float* __restrict__ bias, const float* __restrict__ dwp)
{
    __shared__ float As[16][132];   // [k][m], padded
    __shared__ float Bs[16][132];   // [k][n], padded

    const int tid = threadIdx.x;
    const int bm = blockIdx.y * 128;
    const int bn = blockIdx.x * 128;
    const int ty = tid >> 4;        // 0..15
    const int tx = tid & 15;        // 0..15
    const int lrow = tid >> 2;      // 0..63
    const int lc   = (tid & 3) * 4; // 0,4,8,12

    float acc[8][8];
#pragma unroll
    for (int i = 0; i < 8; i++)
#pragma unroll
        for (int j = 0; j < 8; j++) acc[i][j] = 0.f;

    const float* Ag = A + (size_t)bm * K;
    const float* Bg = B + (size_t)bn * K;

    for (int kt = 0; kt < K; kt += 16) {
#pragma unroll
        for (int hh = 0; hh < 2; hh++) {
            int r = lrow + hh * 64;
            float4 av = *(const float4*)(Ag + (size_t)r * K + kt + lc);
            As[lc + 0][r] = av.x; As[lc + 1][r] = av.y;
            As[lc + 2][r] = av.z; As[lc + 3][r] = av.w;
            float4 bv = *(const float4*)(Bg + (size_t)r * K + kt + lc);
            Bs[lc + 0][r] = bv.x; Bs[lc + 1][r] = bv.y;
            Bs[lc + 2][r] = bv.z; Bs[lc + 3][r] = bv.w;
        }
        __syncthreads();
#pragma unroll
        for (int k = 0; k < 16; k++) {
            float a[8], b[8];
            float4 t0 = *(const float4*)&As[k][ty * 8];
            float4 t1 = *(const float4*)&As[k][ty * 8 + 4];
            a[0] = t0.x; a[1] = t0.y; a[2] = t0.z; a[3] = t0.w;
            a[4] = t1.x; a[5] = t1.y; a[6] = t1.z; a[7] = t1.w;
            float4 u0 = *(const float4*)&Bs[k][tx * 8];
            float4 u1 = *(const float4*)&Bs[k][tx * 8 + 4];
            b[0] = u0.x; b[1] = u0.y; b[2] = u0.z; b[3] = u0.w;
            b[4] = u1.x; b[5] = u1.y; b[6] = u1.z; b[7] = u1.w;
#pragma unroll
            for (int i = 0; i < 8; i++)
#pragma unroll
                for (int j = 0; j < 8; j++)
                    acc[i][j] = fmaf(a[i], b[j], acc[i][j]);
        }
        __syncthreads();
    }

    float sc = 1.0f;
    if (dwp) sc = 1.0f - *dwp;
#pragma unroll
    for (int i = 0; i < 8; i++) {
        int row = bm + ty * 8 + i;
        float* crow = C + (size_t)row * N + bn + tx * 8;
#pragma unroll
        for (int jj = 0; jj < 8; jj += 4) {
            float4 r4;
            float b0 = 0.f, b1 = 0.f, b2 = 0.f, b3 = 0.f;
            if (bias) {
                const float* bp = bias + bn + tx * 8 + jj;
                b0 = bp[0]; b1 = bp[1]; b2 = bp[2]; b3 = bp[3];
            }
            r4.x = (acc[i][jj + 0] + b0) * sc;
            r4.y = (acc[i][jj + 1] + b1) * sc;
            r4.z = (acc[i][jj + 2] + b2) * sc;
            r4.w = (acc[i][jj + 3] + b3) * sc;
            *(float4*)(crow + jj) = r4;
        }
    }
}

// ======================================================================
// Differential flash attention.
// One CTA per (b, h, 64-query tile). q/k rows hold [branch0 f0..63 | branch1 f0..63],
// v rows hold dh 0..127, at columns h*128 .. h*128+127 of the [4096,1024] buffers.
// Two online softmaxes over the 2048 keys, combined at the end:
//   o = O0/l0 - dw * O1/l1
// ======================================================================
#define BQ 64
#define BKT 64
#define QSTRIDE 132   // padded row stride (floats) for Qs/Ks/Vs
#define SSTRIDE 68    // padded row stride for score tiles
#define ATT_SMEM_FLOATS (3 * BQ * QSTRIDE + 2 * BQ * SSTRIDE + 6 * BQ)
#define ATT_SMEM_BYTES (ATT_SMEM_FLOATS * 4)

__global__ void __launch_bounds__(256) diff_attn_kernel(
    const float* __restrict__ q, const float* __restrict__ k, const float* __restrict__ v,
    float* __restrict__ o, const float* __restrict__ dwp)
{
    extern __shared__ float sm[];
    float* Qs = sm;                        // [64][132]
    float* Ks = Qs + BQ * QSTRIDE;         // [64][132]
    float* Vs = Ks + BQ * QSTRIDE;         // [64][132]
    float* S0 = Vs + BQ * QSTRIDE;         // [64][68]
    float* S1 = S0 + BQ * SSTRIDE;         // [64][68]
    float* m0s = S1 + BQ * SSTRIDE;
    float* l0s = m0s + BQ;
    float* m1s = l0s + BQ;
    float* l1s = m1s + BQ;
    float* c0s = l1s + BQ;
    float* c1s = c0s + BQ;

    const int tid = threadIdx.x;
    const int qt = blockIdx.x, h = blockIdx.y, b = blockIdx.z;
    const int q0 = qt * BQ;

    const float* qg = q + ((size_t)b * SLEN + q0) * EDIM + h * 128;
    const float* kg = k + ((size_t)b * SLEN) * EDIM + h * 128;
    const float* vg = v + ((size_t)b * SLEN) * EDIM + h * 128;

    // load Q tile (64 x 128)
#pragma unroll
    for (int j = 0; j < 8; j++) {
        int f = tid + j * 256;           // 0..2047 float4 ids
        int r = f >> 5, c4 = f & 31;
        float4 val = *(const float4*)(qg + (size_t)r * EDIM + c4 * 4);
        *(float4*)(Qs + r * QSTRIDE + c4 * 4) = val;
    }
    if (tid < BQ) {
        m0s[tid] = -1e30f; m1s[tid] = -1e30f;
        l0s[tid] = 0.f;    l1s[tid] = 0.f;
    }

    const int ty = tid >> 4, tx = tid & 15;      // score microtile mapping
    const int qo = tid & 63, g = tid >> 6;       // PV mapping: q row, d-group (g*32)
    const int rrow = tid >> 2, rpart = tid & 3;  // softmax-reduction mapping

    float acc0[32], acc1[32];
#pragma unroll
    for (int jj = 0; jj < 32; jj++) { acc0[jj] = 0.f; acc1[jj] = 0.f; }

    const float scale = 0.125f;  // F^-0.5, F=64

    for (int kt = 0; kt < SLEN; kt += BKT) {
        __syncthreads();   // previous-tile PV done before overwriting Ks/Vs
        // load K,V tiles (64 x 128 each)
#pragma unroll
        for (int j = 0; j < 8; j++) {
            int f = tid + j * 256;
            int r = f >> 5, c4 = f & 31;
            *(float4*)(Ks + r * QSTRIDE + c4 * 4) =
                *(const float4*)(kg + (size_t)(kt + r) * EDIM + c4 * 4);
            *(float4*)(Vs + r * QSTRIDE + c4 * 4) =
                *(const float4*)(vg + (size_t)(kt + r) * EDIM + c4 * 4);
        }
        __syncthreads();

        // ---- scores: S[qi][kk] for both branches, 4x4 microtile per thread ----
        {
            float s0[4][4], s1[4][4];
#pragma unroll
            for (int i = 0; i < 4; i++)
#pragma unroll
                for (int j = 0; j < 4; j++) { s0[i][j] = 0.f; s1[i][j] = 0.f; }

#pragma unroll
            for (int fc = 0; fc < 16; fc++) {          // branch 0: cols 0..63
                float4 qv[4], kv[4];
#pragma unroll
                for (int i = 0; i < 4; i++)
                    qv[i] = *(const float4*)(Qs + (ty * 4 + i) * QSTRIDE + fc * 4);
#pragma unroll
                for (int j = 0; j < 4; j++)
                    kv[j] = *(const float4*)(Ks + (tx + 16 * j) * QSTRIDE + fc * 4);
#pragma unroll
                for (int i = 0; i < 4; i++)
#pragma unroll
                    for (int j = 0; j < 4; j++) {
                        s0[i][j] = fmaf(qv[i].x, kv[j].x, s0[i][j]);
                        s0[i][j] = fmaf(qv[i].y, kv[j].y, s0[i][j]);
                        s0[i][j] = fmaf(qv[i].z, kv[j].z, s0[i][j]);
                        s0[i][j] = fmaf(qv[i].w, kv[j].w, s0[i][j]);
                    }
            }
#pragma unroll
            for (int fc = 16; fc < 32; fc++) {         // branch 1: cols 64..127
                float4 qv[4], kv[4];
#pragma unroll
                for (int i = 0; i < 4; i++)
                    qv[i] = *(const float4*)(Qs + (ty * 4 + i) * QSTRIDE + fc * 4);
#pragma unroll
                for (int j = 0; j < 4; j++)
                    kv[j] = *(const float4*)(Ks + (tx + 16 * j) * QSTRIDE + fc * 4);
#pragma unroll
                for (int i = 0; i < 4; i++)
#pragma unroll
                    for (int j = 0; j < 4; j++) {
                        s1[i][j] = fmaf(qv[i].x, kv[j].x, s1[i][j]);
                        s1[i][j] = fmaf(qv[i].y, kv[j].y, s1[i][j]);
                        s1[i][j] = fmaf(qv[i].z, kv[j].z, s1[i][j]);
                        s1[i][j] = fmaf(qv[i].w, kv[j].w, s1[i][j]);
                    }
            }
#pragma unroll
            for (int i = 0; i < 4; i++)
#pragma unroll
                for (int j = 0; j < 4; j++) {
                    S0[(ty * 4 + i) * SSTRIDE + (tx + 16 * j)] = s0[i][j] * scale;
                    S1[(ty * 4 + i) * SSTRIDE + (tx + 16 * j)] = s1[i][j] * scale;
                }
        }
        __syncthreads();

        // ---- online softmax update (4 threads per row, 16 keys each) ----
        {
            const int base0 = rrow * SSTRIDE + rpart * 16;
            // branch 0
            {
                float pv[16];
                float mloc = -1e30f;
#pragma unroll
                for (int jj = 0; jj < 16; jj++) { pv[jj] = S0[base0 + jj]; mloc = fmaxf(mloc, pv[jj]); }
                mloc = fmaxf(mloc, __shfl_xor_sync(0xffffffffu, mloc, 1));
                mloc = fmaxf(mloc, __shfl_xor_sync(0xffffffffu, mloc, 2));
                float mo = m0s[rrow];
                float mn = fmaxf(mo, mloc);
                float sum = 0.f;
#pragma unroll
                for (int jj = 0; jj < 16; jj++) {
                    float p = __expf(pv[jj] - mn);
                    S0[base0 + jj] = p;
                    sum += p;
                }
                sum += __shfl_xor_sync(0xffffffffu, sum, 1);
                sum += __shfl_xor_sync(0xffffffffu, sum, 2);
                if (rpart == 0) {
                    float cc = __expf(mo - mn);
                    c0s[rrow] = cc;
                    l0s[rrow] = l0s[rrow] * cc + sum;
                    m0s[rrow] = mn;
                }
            }
            // branch 1
            {
                float pv[16];
                float mloc = -1e30f;
#pragma unroll
                for (int jj = 0; jj < 16; jj++) { pv[jj] = S1[base0 + jj]; mloc = fmaxf(mloc, pv[jj]); }
                mloc = fmaxf(mloc, __shfl_xor_sync(0xffffffffu, mloc, 1));
                mloc = fmaxf(mloc, __shfl_xor_sync(0xffffffffu, mloc, 2));
                float mo = m1s[rrow];
                float mn = fmaxf(mo, mloc);
                float sum = 0.f;
#pragma unroll
                for (int jj = 0; jj < 16; jj++) {
                    float p = __expf(pv[jj] - mn);
                    S1[base0 + jj] = p;
                    sum += p;
                }
                sum += __shfl_xor_sync(0xffffffffu, sum, 1);
                sum += __shfl_xor_sync(0xffffffffu, sum, 2);
                if (rpart == 0) {
                    float cc = __expf(mo - mn);
                    c1s[rrow] = cc;
                    l1s[rrow] = l1s[rrow] * cc + sum;
                    m1s[rrow] = mn;
                }
            }
        }
        __syncthreads();

        // ---- PV accumulation: thread owns (qo, d = g*32 .. g*32+31) ----
        {
            float cc0 = c0s[qo], cc1 = c1s[qo];
#pragma unroll
            for (int jj = 0; jj < 32; jj++) { acc0[jj] *= cc0; acc1[jj] *= cc1; }
            const float* s0r = S0 + qo * SSTRIDE;
            const float* s1r = S1 + qo * SSTRIDE;
            const float* vbase = Vs + g * 32;
#pragma unroll 4
            for (int kk = 0; kk < BKT; kk++) {
                float p0 = s0r[kk], p1 = s1r[kk];
                const float4* vr = (const float4*)(vbase + kk * QSTRIDE);
#pragma unroll
                for (int w = 0; w < 8; w++) {
                    float4 vv = vr[w];
                    acc0[4 * w + 0] = fmaf(p0, vv.x, acc0[4 * w + 0]);
                    acc0[4 * w + 1] = fmaf(p0, vv.y, acc0[4 * w + 1]);
                    acc0[4 * w + 2] = fmaf(p0, vv.z, acc0[4 * w + 2]);
                    acc0[4 * w + 3] = fmaf(p0, vv.w, acc0[4 * w + 3]);
                    acc1[4 * w + 0] = fmaf(p1, vv.x, acc1[4 * w + 0]);
                    acc1[4 * w + 1] = fmaf(p1, vv.y, acc1[4 * w + 1]);
                    acc1[4 * w + 2] = fmaf(p1, vv.z, acc1[4 * w + 2]);
                    acc1[4 * w + 3] = fmaf(p1, vv.w, acc1[4 * w + 3]);
                }
            }
        }
    }
    __syncthreads();

    // ---- epilogue: o = O0/l0 - dw * O1/l1, stage via smem (reuse Ks) ----
    {
        float inv0 = 1.f / l0s[qo];
        float inv1 = 1.f / l1s[qo];
        float dw = *dwp;
        float* orow = Ks + qo * QSTRIDE + g * 32;
#pragma unroll
        for (int w = 0; w < 8; w++) {
            float4 r4;
            r4.x = acc0[4 * w + 0] * inv0 - dw * (acc1[4 * w + 0] * inv1);
            r4.y = acc0[4 * w + 1] * inv0 - dw * (acc1[4 * w + 1] * inv1);
            r4.z = acc0[4 * w + 2] * inv0 - dw * (acc1[4 * w + 2] * inv1);
            r4.w = acc0[4 * w + 3] * inv0 - dw * (acc1[4 * w + 3] * inv1);
            *(float4*)(orow + w * 4) = r4;
        }
    }
    __syncthreads();

    float* og = o + ((size_t)b * SLEN + q0) * EDIM + h * 128;
#pragma unroll
    for (int j = 0; j < 8; j++) {
        int f = tid + j * 256;
        int r = f >> 5, c4 = f & 31;
        *(float4*)(og + (size_t)r * EDIM + c4 * 4) = *(const float4*)(Ks + r * QSTRIDE + c4 * 4);
    }
}

// ======================================================================
// RMSNorm over full 1024-wide rows: y = x * rsqrt(mean(x^2) + eps) * w
// ======================================================================
__global__ void __launch_bounds__(256) rmsnorm_kernel(
    const float* __restrict__ x, const float* __restrict__ w, float* __restrict__ y)
{
    __shared__ float red[8];
    __shared__ float rtot;
    const int tid = threadIdx.x;
    const int row = blockIdx.x;
    const float* xr = x + (size_t)row * EDIM;

    float v[4];
    float s = 0.f;
#pragma unroll
    for (int j = 0; j < 4; j++) {
        v[j] = xr[tid + j * 256];
        s = fmaf(v[j], v[j], s);
    }
#pragma unroll
    for (int off = 16; off > 0; off >>= 1)
        s += __shfl_xor_sync(0xffffffffu, s, off);
    if ((tid & 31) == 0) red[tid >> 5] = s;
    __syncthreads();
    if (tid == 0) {
        float t = 0.f;
#pragma unroll
        for (int i = 0; i < 8; i++) t += red[i];
        rtot = rsqrtf(t * (1.0f / 1024.0f) + 1.1920929e-07f);
    }
    __syncthreads();
    float r = rtot;
    float* yr = y + (size_t)row * EDIM;
#pragma unroll
    for (int j = 0; j < 4; j++) {
        int c = tid + j * 256;
        yr[c] = v[j] * r * w[c];
    }
}

// ======================================================================
// launcher
// ======================================================================
extern "C" void kernel_launch(void* const* d_in, const int* in_sizes, int n_in,
                              void* d_out, int out_size)
{
    const float* x  = (const float*)d_in[0];
    const float* Wq = (const float*)d_in[1];
    const float* Wk = (const float*)d_in[2];
    const float* Wv = (const float*)d_in[3];
    const float* nw = (const float*)d_in[4];
    const float* Wo = (const float*)d_in[5];
    const float* bo = (const float*)d_in[6];
    const float* dw = (const float*)d_in[7];
    float* out = (float*)d_out;

    float *qp, *kp, *vp, *op;
    cudaGetSymbolAddress((void**)&qp, g_q);
    cudaGetSymbolAddress((void**)&kp, g_k);
    cudaGetSymbolAddress((void**)&vp, g_v);
    cudaGetSymbolAddress((void**)&op, g_o);

    cudaFuncSetAttribute(diff_attn_kernel,
                         cudaFuncAttributeMaxDynamicSharedMemorySize, ATT_SMEM_BYTES);

    dim3 gg(EDIM / 128, MROWS / 128);
    gemm_nt_kernel<<<gg, 256>>>(x, Wq, qp, MROWS, EDIM, EDIM, nullptr, nullptr);
    gemm_nt_kernel<<<gg, 256>>>(x, Wk, kp, MROWS, EDIM, EDIM, nullptr, nullptr);
    gemm_nt_kernel<<<gg, 256>>>(x, Wv, vp, MROWS, EDIM, EDIM, nullptr, nullptr);

    dim3 ga(SLEN / BQ, NHEAD, 2);
    diff_attn_kernel<<<ga, 256, ATT_SMEM_BYTES>>>(qp, kp, vp, op, dw);

    rmsnorm_kernel<<<MROWS, 256>>>(op, nw, qp);

    gemm_nt_kernel<<<gg, 256>>>(qp, Wo, out, MROWS, EDIM, EDIM, bo, dw);
}

// round 4
// speedup vs baseline: 1.1256x; 1.1256x over previous
#include <cuda_runtime.h>
#include <math.h>

#define MROWS 4096           // B*S
#define EDIM  1024
#define SLEN  2048
#define NHEAD 8

typedef unsigned long long u64;

// ---------------- packed f32x2 helpers (FFMA2 path, sm_103a) ----------------
__device__ __forceinline__ u64 pack2(float lo, float hi) {
    u64 r; asm("mov.b64 %0, {%1, %2};" : "=l"(r) : "f"(lo), "f"(hi)); return r;
}
__device__ __forceinline__ void fma2(u64& d, u64 a, u64 b) {
    asm("fma.rn.f32x2 %0, %1, %2, %0;" : "+l"(d) : "l"(a), "l"(b));
}
__device__ __forceinline__ void mul2(u64& d, u64 a) {
    asm("mul.rn.f32x2 %0, %0, %1;" : "+l"(d) : "l"(a));
}
__device__ __forceinline__ float2 unpack2(u64 v) {
    float lo, hi; asm("mov.b64 {%0, %1}, %2;" : "=f"(lo), "=f"(hi) : "l"(v));
    return make_float2(lo, hi);
}

// ---------------- scratch (device globals: allocation-free) ----------------
__device__ float g_q[(size_t)MROWS * EDIM];
__device__ float g_k[(size_t)MROWS * EDIM];
__device__ float g_v[(size_t)MROWS * EDIM];
__device__ float g_o[(size_t)MROWS * EDIM];

// ======================================================================
// GEMM: C[M,N] = A[M,K] @ B[N,K]^T   (NT, both K-contiguous)
// optional epilogue: C = (C + bias[n]) * (1 - *dwp)
// BM=BN=128, BK=16, 256 threads, 8x8 microtile, packed-f32x2 inner loop
// ======================================================================
__global__ void __launch_bounds__(256) gemm_nt_kernel(
    const float* __restrict__ A, const float* __restrict__ B, float* __restrict__ C,
    int M, int N, int K, const float* __restrict__ bias, const float* __restrict__ dwp)
{
    __shared__ float As[16][132];   // [k][m], padded
    __shared__ float Bs[16][132];   // [k][n], padded

    const int tid = threadIdx.x;
    const int bm = blockIdx.y * 128;
    const int bn = blockIdx.x * 128;
    const int ty = tid >> 4;        // 0..15
    const int tx = tid & 15;        // 0..15
    const int lrow = tid >> 2;      // 0..63
    const int lc   = (tid & 3) * 4; // 0,4,8,12

    // acc2[i][jp] = packed (acc[i][2jp], acc[i][2jp+1])
    u64 acc2[8][4];
#pragma unroll
    for (int i = 0; i < 8; i++)
#pragma unroll
        for (int jp = 0; jp < 4; jp++) acc2[i][jp] = 0ULL;

    const float* Ag = A + (size_t)bm * K;
    const float* Bg = B + (size_t)bn * K;

    for (int kt = 0; kt < K; kt += 16) {
#pragma unroll
        for (int hh = 0; hh < 2; hh++) {
            int r = lrow + hh * 64;
            float4 av = *(const float4*)(Ag + (size_t)r * K + kt + lc);
            As[lc + 0][r] = av.x; As[lc + 1][r] = av.y;
            As[lc + 2][r] = av.z; As[lc + 3][r] = av.w;
            float4 bv = *(const float4*)(Bg + (size_t)r * K + kt + lc);
            Bs[lc + 0][r] = bv.x; Bs[lc + 1][r] = bv.y;
            Bs[lc + 2][r] = bv.z; Bs[lc + 3][r] = bv.w;
        }
        __syncthreads();
#pragma unroll
        for (int k = 0; k < 16; k++) {
            float4 t0 = *(const float4*)&As[k][ty * 8];
            float4 t1 = *(const float4*)&As[k][ty * 8 + 4];
            u64 ab[8];
            ab[0] = pack2(t0.x, t0.x); ab[1] = pack2(t0.y, t0.y);
            ab[2] = pack2(t0.z, t0.z); ab[3] = pack2(t0.w, t0.w);
            ab[4] = pack2(t1.x, t1.x); ab[5] = pack2(t1.y, t1.y);
            ab[6] = pack2(t1.z, t1.z); ab[7] = pack2(t1.w, t1.w);
            ulonglong2 b0 = *(const ulonglong2*)&Bs[k][tx * 8];
            ulonglong2 b1 = *(const ulonglong2*)&Bs[k][tx * 8 + 4];
            u64 b2[4] = { b0.x, b0.y, b1.x, b1.y };
#pragma unroll
            for (int i = 0; i < 8; i++)
#pragma unroll
                for (int jp = 0; jp < 4; jp++)
                    fma2(acc2[i][jp], ab[i], b2[jp]);
        }
        __syncthreads();
    }

    float sc = 1.0f;
    if (dwp) sc = 1.0f - *dwp;
#pragma unroll
    for (int i = 0; i < 8; i++) {
        int row = bm + ty * 8 + i;
        float* crow = C + (size_t)row * N + bn + tx * 8;
#pragma unroll
        for (int jh = 0; jh < 2; jh++) {
            float2 e0 = unpack2(acc2[i][jh * 2 + 0]);
            float2 e1 = unpack2(acc2[i][jh * 2 + 1]);
            float b0 = 0.f, b1 = 0.f, b2v = 0.f, b3 = 0.f;
            if (bias) {
                const float* bp = bias + bn + tx * 8 + jh * 4;
                b0 = bp[0]; b1 = bp[1]; b2v = bp[2]; b3 = bp[3];
            }
            float4 r4;
            r4.x = (e0.x + b0) * sc;
            r4.y = (e0.y + b1) * sc;
            r4.z = (e1.x + b2v) * sc;
            r4.w = (e1.y + b3) * sc;
            *(float4*)(crow + jh * 4) = r4;
        }
    }
}

// ======================================================================
// Differential flash attention (packed-f32x2 QK and PV).
// One CTA per (b, h, 64-query tile). q/k rows hold [br0 f0..63 | br1 f0..63],
// v rows hold dh 0..127 at columns h*128.. of the [4096,1024] buffers.
//   o = O0/l0 - dw * O1/l1
// ======================================================================
#define BQ 64
#define BKT 64
#define QSTRIDE 132   // padded row stride (floats) for Qs/Ks/Vs
#define SSTRIDE 68    // padded row stride for score tiles
#define ATT_SMEM_FLOATS (3 * BQ * QSTRIDE + 2 * BQ * SSTRIDE + 6 * BQ)
#define ATT_SMEM_BYTES (ATT_SMEM_FLOATS * 4)

__global__ void __launch_bounds__(256) diff_attn_kernel(
    const float* __restrict__ q, const float* __restrict__ k, const float* __restrict__ v,
    float* __restrict__ o, const float* __restrict__ dwp)
{
    extern __shared__ float sm[];
    float* Qs = sm;                        // [64][132]
    float* Ks = Qs + BQ * QSTRIDE;         // [64][132]
    float* Vs = Ks + BQ * QSTRIDE;         // [64][132]
    float* S0 = Vs + BQ * QSTRIDE;         // [64][68]
    float* S1 = S0 + BQ * SSTRIDE;         // [64][68]
    float* m0s = S1 + BQ * SSTRIDE;
    float* l0s = m0s + BQ;
    float* m1s = l0s + BQ;
    float* l1s = m1s + BQ;
    float* c0s = l1s + BQ;
    float* c1s = c0s + BQ;

    const int tid = threadIdx.x;
    const int qt = blockIdx.x, h = blockIdx.y, b = blockIdx.z;
    const int q0 = qt * BQ;

    const float* qg = q + ((size_t)b * SLEN + q0) * EDIM + h * 128;
    const float* kg = k + ((size_t)b * SLEN) * EDIM + h * 128;
    const float* vg = v + ((size_t)b * SLEN) * EDIM + h * 128;

    // load Q tile (64 x 128)
#pragma unroll
    for (int j = 0; j < 8; j++) {
        int f = tid + j * 256;           // 0..2047 float4 ids
        int r = f >> 5, c4 = f & 31;
        float4 val = *(const float4*)(qg + (size_t)r * EDIM + c4 * 4);
        *(float4*)(Qs + r * QSTRIDE + c4 * 4) = val;
    }
    if (tid < BQ) {
        m0s[tid] = -1e30f; m1s[tid] = -1e30f;
        l0s[tid] = 0.f;    l1s[tid] = 0.f;
    }

    const int ty = tid >> 4, tx = tid & 15;      // score microtile mapping
    const int qo = tid & 63, g = tid >> 6;       // PV mapping: q row, d-group (g*32)
    const int rrow = tid >> 2, rpart = tid & 3;  // softmax-reduction mapping

    // packed PV accumulators: a0[2w]=(d0,d1), a0[2w+1]=(d2,d3) of float4 w
    u64 a0[16], a1[16];
#pragma unroll
    for (int jj = 0; jj < 16; jj++) { a0[jj] = 0ULL; a1[jj] = 0ULL; }

    const float scale = 0.125f;  // F^-0.5, F=64

    for (int kt = 0; kt < SLEN; kt += BKT) {
        __syncthreads();   // previous-tile PV done before overwriting Ks/Vs
        // load K,V tiles (64 x 128 each)
#pragma unroll
        for (int j = 0; j < 8; j++) {
            int f = tid + j * 256;
            int r = f >> 5, c4 = f & 31;
            *(float4*)(Ks + r * QSTRIDE + c4 * 4) =
                *(const float4*)(kg + (size_t)(kt + r) * EDIM + c4 * 4);
            *(float4*)(Vs + r * QSTRIDE + c4 * 4) =
                *(const float4*)(vg + (size_t)(kt + r) * EDIM + c4 * 4);
        }
        __syncthreads();

        // ---- scores: packed along reduction dim (even/odd f lanes) ----
        {
            u64 s0p[4][4], s1p[4][4];
#pragma unroll
            for (int i = 0; i < 4; i++)
#pragma unroll
                for (int j = 0; j < 4; j++) { s0p[i][j] = 0ULL; s1p[i][j] = 0ULL; }

#pragma unroll
            for (int fc = 0; fc < 16; fc++) {          // branch 0: cols 0..63
                ulonglong2 q2[4], k2[4];
#pragma unroll
                for (int i = 0; i < 4; i++)
                    q2[i] = *(const ulonglong2*)(Qs + (ty * 4 + i) * QSTRIDE + fc * 4);
#pragma unroll
                for (int j = 0; j < 4; j++)
                    k2[j] = *(const ulonglong2*)(Ks + (tx + 16 * j) * QSTRIDE + fc * 4);
#pragma unroll
                for (int i = 0; i < 4; i++)
#pragma unroll
                    for (int j = 0; j < 4; j++) {
                        fma2(s0p[i][j], q2[i].x, k2[j].x);
                        fma2(s0p[i][j], q2[i].y, k2[j].y);
                    }
            }
#pragma unroll
            for (int fc = 16; fc < 32; fc++) {         // branch 1: cols 64..127
                ulonglong2 q2[4], k2[4];
#pragma unroll
                for (int i = 0; i < 4; i++)
                    q2[i] = *(const ulonglong2*)(Qs + (ty * 4 + i) * QSTRIDE + fc * 4);
#pragma unroll
                for (int j = 0; j < 4; j++)
                    k2[j] = *(const ulonglong2*)(Ks + (tx + 16 * j) * QSTRIDE + fc * 4);
#pragma unroll
                for (int i = 0; i < 4; i++)
#pragma unroll
                    for (int j = 0; j < 4; j++) {
                        fma2(s1p[i][j], q2[i].x, k2[j].x);
                        fma2(s1p[i][j], q2[i].y, k2[j].y);
                    }
            }
#pragma unroll
            for (int i = 0; i < 4; i++)
#pragma unroll
                for (int j = 0; j < 4; j++) {
                    float2 e0 = unpack2(s0p[i][j]);
                    float2 e1 = unpack2(s1p[i][j]);
                    S0[(ty * 4 + i) * SSTRIDE + (tx + 16 * j)] = (e0.x + e0.y) * scale;
                    S1[(ty * 4 + i) * SSTRIDE + (tx + 16 * j)] = (e1.x + e1.y) * scale;
                }
        }
        __syncthreads();

        // ---- online softmax update (4 threads per row, 16 keys each) ----
        {
            const int base0 = rrow * SSTRIDE + rpart * 16;
            // branch 0
            {
                float pv[16];
                float mloc = -1e30f;
#pragma unroll
                for (int jj = 0; jj < 16; jj++) { pv[jj] = S0[base0 + jj]; mloc = fmaxf(mloc, pv[jj]); }
                mloc = fmaxf(mloc, __shfl_xor_sync(0xffffffffu, mloc, 1));
                mloc = fmaxf(mloc, __shfl_xor_sync(0xffffffffu, mloc, 2));
                float mo = m0s[rrow];
                float mn = fmaxf(mo, mloc);
                float sum = 0.f;
#pragma unroll
                for (int jj = 0; jj < 16; jj++) {
                    float p = __expf(pv[jj] - mn);
                    S0[base0 + jj] = p;
                    sum += p;
                }
                sum += __shfl_xor_sync(0xffffffffu, sum, 1);
                sum += __shfl_xor_sync(0xffffffffu, sum, 2);
                if (rpart == 0) {
                    float cc = __expf(mo - mn);
                    c0s[rrow] = cc;
                    l0s[rrow] = l0s[rrow] * cc + sum;
                    m0s[rrow] = mn;
                }
            }
            // branch 1
            {
                float pv[16];
                float mloc = -1e30f;
#pragma unroll
                for (int jj = 0; jj < 16; jj++) { pv[jj] = S1[base0 + jj]; mloc = fmaxf(mloc, pv[jj]); }
                mloc = fmaxf(mloc, __shfl_xor_sync(0xffffffffu, mloc, 1));
                mloc = fmaxf(mloc, __shfl_xor_sync(0xffffffffu, mloc, 2));
                float mo = m1s[rrow];
                float mn = fmaxf(mo, mloc);
                float sum = 0.f;
#pragma unroll
                for (int jj = 0; jj < 16; jj++) {
                    float p = __expf(pv[jj] - mn);
                    S1[base0 + jj] = p;
                    sum += p;
                }
                sum += __shfl_xor_sync(0xffffffffu, sum, 1);
                sum += __shfl_xor_sync(0xffffffffu, sum, 2);
                if (rpart == 0) {
                    float cc = __expf(mo - mn);
                    c1s[rrow] = cc;
                    l1s[rrow] = l1s[rrow] * cc + sum;
                    m1s[rrow] = mn;
                }
            }
        }
        __syncthreads();

        // ---- PV accumulation (packed): thread owns (qo, d = g*32 .. g*32+31) ----
        {
            u64 c0p = pack2(c0s[qo], c0s[qo]);
            u64 c1p = pack2(c1s[qo], c1s[qo]);
#pragma unroll
            for (int jj = 0; jj < 16; jj++) { mul2(a0[jj], c0p); mul2(a1[jj], c1p); }
            const float* s0r = S0 + qo * SSTRIDE;
            const float* s1r = S1 + qo * SSTRIDE;
            const float* vbase = Vs + g * 32;
#pragma unroll 4
            for (int kk = 0; kk < BKT; kk++) {
                float p0 = s0r[kk], p1 = s1r[kk];
                u64 p0p = pack2(p0, p0);
                u64 p1p = pack2(p1, p1);
                const ulonglong2* vr = (const ulonglong2*)(vbase + kk * QSTRIDE);
#pragma unroll
                for (int w = 0; w < 8; w++) {
                    ulonglong2 vv = vr[w];
                    fma2(a0[2 * w + 0], p0p, vv.x);
                    fma2(a0[2 * w + 1], p0p, vv.y);
                    fma2(a1[2 * w + 0], p1p, vv.x);
                    fma2(a1[2 * w + 1], p1p, vv.y);
                }
            }
        }
    }
    __syncthreads();

    // ---- epilogue: o = O0/l0 - dw * O1/l1, stage via smem (reuse Ks) ----
    {
        float inv0 = 1.f / l0s[qo];
        float inv1 = 1.f / l1s[qo];
        float dw = *dwp;
        float* orow = Ks + qo * QSTRIDE + g * 32;
#pragma unroll
        for (int w = 0; w < 8; w++) {
            float2 e0a = unpack2(a0[2 * w + 0]);
            float2 e0b = unpack2(a0[2 * w + 1]);
            float2 e1a = unpack2(a1[2 * w + 0]);
            float2 e1b = unpack2(a1[2 * w + 1]);
            float4 r4;
            r4.x = e0a.x * inv0 - dw * (e1a.x * inv1);
            r4.y = e0a.y * inv0 - dw * (e1a.y * inv1);
            r4.z = e0b.x * inv0 - dw * (e1b.x * inv1);
            r4.w = e0b.y * inv0 - dw * (e1b.y * inv1);
            *(float4*)(orow + w * 4) = r4;
        }
    }
    __syncthreads();

    float* og = o + ((size_t)b * SLEN + q0) * EDIM + h * 128;
#pragma unroll
    for (int j = 0; j < 8; j++) {
        int f = tid + j * 256;
        int r = f >> 5, c4 = f & 31;
        *(float4*)(og + (size_t)r * EDIM + c4 * 4) = *(const float4*)(Ks + r * QSTRIDE + c4 * 4);
    }
}

// ======================================================================
// RMSNorm over full 1024-wide rows: y = x * rsqrt(mean(x^2) + eps) * w
// ======================================================================
__global__ void __launch_bounds__(256) rmsnorm_kernel(
    const float* __restrict__ x, const float* __restrict__ w, float* __restrict__ y)
{
    __shared__ float red[8];
    __shared__ float rtot;
    const int tid = threadIdx.x;
    const int row = blockIdx.x;
    const float* xr = x + (size_t)row * EDIM;

    float v[4];
    float s = 0.f;
#pragma unroll
    for (int j = 0; j < 4; j++) {
        v[j] = xr[tid + j * 256];
        s = fmaf(v[j], v[j], s);
    }
#pragma unroll
    for (int off = 16; off > 0; off >>= 1)
        s += __shfl_xor_sync(0xffffffffu, s, off);
    if ((tid & 31) == 0) red[tid >> 5] = s;
    __syncthreads();
    if (tid == 0) {
        float t = 0.f;
#pragma unroll
        for (int i = 0; i < 8; i++) t += red[i];
        rtot = rsqrtf(t * (1.0f / 1024.0f) + 1.1920929e-07f);
    }
    __syncthreads();
    float r = rtot;
    float* yr = y + (size_t)row * EDIM;
#pragma unroll
    for (int j = 0; j < 4; j++) {
        int c = tid + j * 256;
        yr[c] = v[j] * r * w[c];
    }
}

// ======================================================================
// launcher
// ======================================================================
extern "C" void kernel_launch(void* const* d_in, const int* in_sizes, int n_in,
                              void* d_out, int out_size)
{
    const float* x  = (const float*)d_in[0];
    const float* Wq = (const float*)d_in[1];
    const float* Wk = (const float*)d_in[2];
    const float* Wv = (const float*)d_in[3];
    const float* nw = (const float*)d_in[4];
    const float* Wo = (const float*)d_in[5];
    const float* bo = (const float*)d_in[6];
    const float* dw = (const float*)d_in[7];
    float* out = (float*)d_out;

    float *qp, *kp, *vp, *op;
    cudaGetSymbolAddress((void**)&qp, g_q);
    cudaGetSymbolAddress((void**)&kp, g_k);
    cudaGetSymbolAddress((void**)&vp, g_v);
    cudaGetSymbolAddress((void**)&op, g_o);

    cudaFuncSetAttribute(diff_attn_kernel,
                         cudaFuncAttributeMaxDynamicSharedMemorySize, ATT_SMEM_BYTES);

    dim3 gg(EDIM / 128, MROWS / 128);
    gemm_nt_kernel<<<gg, 256>>>(x, Wq, qp, MROWS, EDIM, EDIM, nullptr, nullptr);
    gemm_nt_kernel<<<gg, 256>>>(x, Wk, kp, MROWS, EDIM, EDIM, nullptr, nullptr);
    gemm_nt_kernel<<<gg, 256>>>(x, Wv, vp, MROWS, EDIM, EDIM, nullptr, nullptr);

    dim3 ga(SLEN / BQ, NHEAD, 2);
    diff_attn_kernel<<<ga, 256, ATT_SMEM_BYTES>>>(qp, kp, vp, op, dw);

    rmsnorm_kernel<<<MROWS, 256>>>(op, nw, qp);

    gemm_nt_kernel<<<gg, 256>>>(qp, Wo, out, MROWS, EDIM, EDIM, bo, dw);
}

// round 7
// speedup vs baseline: 1.3824x; 1.2281x over previous
#include <cuda_runtime.h>
#include <cuda_bf16.h>
#include <cstdint>
#include <cstddef>
#include <math.h>

#define MROWS 4096           // B*S
#define EDIM  1024
#define SLEN  2048
#define NHEAD 8

typedef unsigned long long u64;

// ---------------- packed f32x2 helpers (FFMA2 path, sm_103a) ----------------
__device__ __forceinline__ u64 pack2(float lo, float hi) {
    u64 r; asm("mov.b64 %0, {%1, %2};" : "=l"(r) : "f"(lo), "f"(hi)); return r;
}
__device__ __forceinline__ void fma2(u64& d, u64 a, u64 b) {
    asm("fma.rn.f32x2 %0, %1, %2, %0;" : "+l"(d) : "l"(a), "l"(b));
}
__device__ __forceinline__ void mul2(u64& d, u64 a) {
    asm("mul.rn.f32x2 %0, %0, %1;" : "+l"(d) : "l"(a));
}
__device__ __forceinline__ float2 unpack2(u64 v) {
    float lo, hi; asm("mov.b64 {%0, %1}, %2;" : "=f"(lo), "=f"(hi) : "l"(v));
    return make_float2(lo, hi);
}

// ---------------- warp-level bf16 MMA (m16n8k16, fp32 accum) ----------------
__device__ __forceinline__ void mma16816(
    float* c, const unsigned* a, const unsigned* b)
{
    asm volatile(
        "mma.sync.aligned.m16n8k16.row.col.f32.bf16.bf16.f32 "
        "{%0,%1,%2,%3}, {%4,%5,%6,%7}, {%8,%9}, {%0,%1,%2,%3};"
        : "+f"(c[0]), "+f"(c[1]), "+f"(c[2]), "+f"(c[3])
        : "r"(a[0]), "r"(a[1]), "r"(a[2]), "r"(a[3]), "r"(b[0]), "r"(b[1]));
}

// ---------------- scratch (device globals: allocation-free) ----------------
__device__ float g_q[(size_t)MROWS * EDIM];
__device__ float g_k[(size_t)MROWS * EDIM];
__device__ float g_v[(size_t)MROWS * EDIM];
__device__ float g_o[(size_t)MROWS * EDIM];
__device__ __nv_bfloat16 g_xhi[(size_t)MROWS * EDIM];
__device__ __nv_bfloat16 g_xlo[(size_t)MROWS * EDIM];
__device__ __nv_bfloat16 g_nhi[(size_t)MROWS * EDIM];
__device__ __nv_bfloat16 g_nlo[(size_t)MROWS * EDIM];
__device__ __nv_bfloat16 g_wqhi[(size_t)EDIM * EDIM];
__device__ __nv_bfloat16 g_wqlo[(size_t)EDIM * EDIM];
__device__ __nv_bfloat16 g_wkhi[(size_t)EDIM * EDIM];
__device__ __nv_bfloat16 g_wklo[(size_t)EDIM * EDIM];
__device__ __nv_bfloat16 g_wvhi[(size_t)EDIM * EDIM];
__device__ __nv_bfloat16 g_wvlo[(size_t)EDIM * EDIM];
__device__ __nv_bfloat16 g_wohi[(size_t)EDIM * EDIM];
__device__ __nv_bfloat16 g_wolo[(size_t)EDIM * EDIM];

// ======================================================================
// fp32 -> (bf16 hi, bf16 lo) split, vectorized float4
// ======================================================================
__global__ void __launch_bounds__(256) split_bf16_kernel(
    const float* __restrict__ x, __nv_bfloat16* __restrict__ hi,
    __nv_bfloat16* __restrict__ lo, int n4)
{
    int i = blockIdx.x * 256 + threadIdx.x;
    if (i >= n4) return;
    float4 v = ((const float4*)x)[i];
    float vv[4] = { v.x, v.y, v.z, v.w };
    __nv_bfloat16 h[4], l[4];
#pragma unroll
    for (int j = 0; j < 4; j++) {
        h[j] = __float2bfloat16_rn(vv[j]);
        l[j] = __float2bfloat16_rn(vv[j] - __bfloat162float(h[j]));
    }
    __nv_bfloat162* hp = (__nv_bfloat162*)hi;
    __nv_bfloat162* lp = (__nv_bfloat162*)lo;
    hp[i * 2 + 0] = __nv_bfloat162(h[0], h[1]);
    hp[i * 2 + 1] = __nv_bfloat162(h[2], h[3]);
    lp[i * 2 + 0] = __nv_bfloat162(l[0], l[1]);
    lp[i * 2 + 1] = __nv_bfloat162(l[2], l[3]);
}

// ======================================================================
// HMMA split-bf16 GEMM: C[M,N] = A[M,K] @ B[N,K]^T  (fp32-grade accuracy)
// CTA 128x128, BK=16, 8 warps each 64x32, mma.sync m16n8k16.
// 3 MMAs per tile pair: ahi*bhi + ahi*blo + alo*bhi, fp32 accum.
// Epilogue: optional (C + bias[n]) * (1 - *dwp)
// ======================================================================
#define TS 24   // smem row stride in bf16 (48B) -> conflict-free fragment loads

__global__ void __launch_bounds__(256) mma_gemm_kernel(
    const __nv_bfloat16* __restrict__ Ahi, const __nv_bfloat16* __restrict__ Alo,
    const __nv_bfloat16* __restrict__ Bhi, const __nv_bfloat16* __restrict__ Blo,
    float* __restrict__ C, int M, int N, int K,
    const float* __restrict__ bias, const float* __restrict__ dwp)
{
    __shared__ __nv_bfloat16 sAhi[128 * TS];
    __shared__ __nv_bfloat16 sAlo[128 * TS];
    __shared__ __nv_bfloat16 sBhi[128 * TS];
    __shared__ __nv_bfloat16 sBlo[128 * TS];

    const int tid = threadIdx.x;
    const int wid = tid >> 5, L = tid & 31;
    const int bm = blockIdx.y * 128, bn = blockIdx.x * 128;
    const int wm = (wid >> 2) * 64, wn = (wid & 3) * 32;

    const int lrow = tid >> 1;            // 0..127
    const int lseg = (tid & 1) * 8;       // 0 or 8 (bf16)

    const int fr = L >> 2;                // fragment row/col group 0..7
    const int fc = (L & 3) * 2;           // k pair base 0,2,4,6

    float acc[4][4][4];
#pragma unroll
    for (int mt = 0; mt < 4; mt++)
#pragma unroll
        for (int nt = 0; nt < 4; nt++)
#pragma unroll
            for (int e = 0; e < 4; e++) acc[mt][nt][e] = 0.f;

    for (int kc = 0; kc < K; kc += 16) {
        __syncthreads();
        // stage 4 tiles: 128 rows x 16 bf16 each; one float4 per thread per tile
        *(float4*)&sAhi[lrow * TS + lseg] =
            *(const float4*)(Ahi + (size_t)(bm + lrow) * K + kc + lseg);
        *(float4*)&sAlo[lrow * TS + lseg] =
            *(const float4*)(Alo + (size_t)(bm + lrow) * K + kc + lseg);
        *(float4*)&sBhi[lrow * TS + lseg] =
            *(const float4*)(Bhi + (size_t)(bn + lrow) * K + kc + lseg);
        *(float4*)&sBlo[lrow * TS + lseg] =
            *(const float4*)(Blo + (size_t)(bn + lrow) * K + kc + lseg);
        __syncthreads();

        // B fragments for this warp's 4 n-tiles
        unsigned bh[4][2], bl[4][2];
#pragma unroll
        for (int nt = 0; nt < 4; nt++) {
            int n = wn + nt * 8 + fr;
            bh[nt][0] = *(const unsigned*)&sBhi[n * TS + fc];
            bh[nt][1] = *(const unsigned*)&sBhi[n * TS + fc + 8];
            bl[nt][0] = *(const unsigned*)&sBlo[n * TS + fc];
            bl[nt][1] = *(const unsigned*)&sBlo[n * TS + fc + 8];
        }
#pragma unroll
        for (int mt = 0; mt < 4; mt++) {
            int m = wm + mt * 16 + fr;
            unsigned ah[4], al[4];
            ah[0] = *(const unsigned*)&sAhi[m * TS + fc];
            ah[1] = *(const unsigned*)&sAhi[(m + 8) * TS + fc];
            ah[2] = *(const unsigned*)&sAhi[m * TS + fc + 8];
            ah[3] = *(const unsigned*)&sAhi[(m + 8) * TS + fc + 8];
            al[0] = *(const unsigned*)&sAlo[m * TS + fc];
            al[1] = *(const unsigned*)&sAlo[(m + 8) * TS + fc];
            al[2] = *(const unsigned*)&sAlo[m * TS + fc + 8];
            al[3] = *(const unsigned*)&sAlo[(m + 8) * TS + fc + 8];
#pragma unroll
            for (int nt = 0; nt < 4; nt++) {
                mma16816(acc[mt][nt], ah, bh[nt]);
                mma16816(acc[mt][nt], ah, bl[nt]);
                mma16816(acc[mt][nt], al, bh[nt]);
            }
        }
    }

    float sc = 1.0f;
    if (dwp) sc = 1.0f - *dwp;

#pragma unroll
    for (int mt = 0; mt < 4; mt++) {
#pragma unroll
        for (int nt = 0; nt < 4; nt++) {
            int row = bm + wm + mt * 16 + fr;
            int col = bn + wn + nt * 8 + fc;
            float b0 = 0.f, b1 = 0.f;
            if (bias) { b0 = bias[col]; b1 = bias[col + 1]; }
            float2 r0, r1;
            r0.x = (acc[mt][nt][0] + b0) * sc;
            r0.y = (acc[mt][nt][1] + b1) * sc;
            r1.x = (acc[mt][nt][2] + b0) * sc;
            r1.y = (acc[mt][nt][3] + b1) * sc;
            *(float2*)(C + (size_t)row * N + col) = r0;
            *(float2*)(C + (size_t)(row + 8) * N + col) = r1;
        }
    }
}

// ======================================================================
// Differential flash attention (packed-f32x2 QK and PV; conflict-free PV loads)
// ======================================================================
#define BQ 64
#define BKT 64
#define QSTRIDE 132   // padded row stride (floats) for Qs/Ks/Vs
#define SSTRIDE 68    // padded row stride for score tiles
#define ATT_SMEM_FLOATS (3 * BQ * QSTRIDE + 2 * BQ * SSTRIDE + 6 * BQ)
#define ATT_SMEM_BYTES (ATT_SMEM_FLOATS * 4)

__global__ void __launch_bounds__(256) diff_attn_kernel(
    const float* __restrict__ q, const float* __restrict__ k, const float* __restrict__ v,
    float* __restrict__ o, const float* __restrict__ dwp)
{
    extern __shared__ float sm[];
    float* Qs = sm;                        // [64][132]
    float* Ks = Qs + BQ * QSTRIDE;         // [64][132]
    float* Vs = Ks + BQ * QSTRIDE;         // [64][132]
    float* S0 = Vs + BQ * QSTRIDE;         // [64][68]
    float* S1 = S0 + BQ * SSTRIDE;         // [64][68]
    float* m0s = S1 + BQ * SSTRIDE;
    float* l0s = m0s + BQ;
    float* m1s = l0s + BQ;
    float* l1s = m1s + BQ;
    float* c0s = l1s + BQ;
    float* c1s = c0s + BQ;

    const int tid = threadIdx.x;
    const int qt = blockIdx.x, h = blockIdx.y, b = blockIdx.z;
    const int q0 = qt * BQ;

    const float* qg = q + ((size_t)b * SLEN + q0) * EDIM + h * 128;
    const float* kg = k + ((size_t)b * SLEN) * EDIM + h * 128;
    const float* vg = v + ((size_t)b * SLEN) * EDIM + h * 128;

    // load Q tile (64 x 128)
#pragma unroll
    for (int j = 0; j < 8; j++) {
        int f = tid + j * 256;           // 0..2047 float4 ids
        int r = f >> 5, c4 = f & 31;
        float4 val = *(const float4*)(qg + (size_t)r * EDIM + c4 * 4);
        *(float4*)(Qs + r * QSTRIDE + c4 * 4) = val;
    }
    if (tid < BQ) {
        m0s[tid] = -1e30f; m1s[tid] = -1e30f;
        l0s[tid] = 0.f;    l1s[tid] = 0.f;
    }

    const int ty = tid >> 4, tx = tid & 15;      // score microtile mapping
    const int qo = tid & 63, g = tid >> 6;       // PV mapping: q row, d-group (g*32)
    const int rrow = tid >> 2, rpart = tid & 3;  // softmax-reduction mapping

    // packed PV accumulators: a0[2w]=(d0,d1), a0[2w+1]=(d2,d3) of float4 w
    u64 a0[16], a1[16];
#pragma unroll
    for (int jj = 0; jj < 16; jj++) { a0[jj] = 0ULL; a1[jj] = 0ULL; }

    const float scale = 0.125f;  // F^-0.5, F=64

    for (int kt = 0; kt < SLEN; kt += BKT) {
        __syncthreads();   // previous-tile PV done before overwriting Ks/Vs
        // load K,V tiles (64 x 128 each)
#pragma unroll
        for (int j = 0; j < 8; j++) {
            int f = tid + j * 256;
            int r = f >> 5, c4 = f & 31;
            *(float4*)(Ks + r * QSTRIDE + c4 * 4) =
                *(const float4*)(kg + (size_t)(kt + r) * EDIM + c4 * 4);
            *(float4*)(Vs + r * QSTRIDE + c4 * 4) =
                *(const float4*)(vg + (size_t)(kt + r) * EDIM + c4 * 4);
        }
        __syncthreads();

        // ---- scores: packed along reduction dim (even/odd f lanes) ----
        {
            u64 s0p[4][4], s1p[4][4];
#pragma unroll
            for (int i = 0; i < 4; i++)
#pragma unroll
                for (int j = 0; j < 4; j++) { s0p[i][j] = 0ULL; s1p[i][j] = 0ULL; }

#pragma unroll
            for (int fc = 0; fc < 16; fc++) {          // branch 0: cols 0..63
                ulonglong2 q2[4], k2[4];
#pragma unroll
                for (int i = 0; i < 4; i++)
                    q2[i] = *(const ulonglong2*)(Qs + (ty * 4 + i) * QSTRIDE + fc * 4);
#pragma unroll
                for (int j = 0; j < 4; j++)
                    k2[j] = *(const ulonglong2*)(Ks + (tx + 16 * j) * QSTRIDE + fc * 4);
#pragma unroll
                for (int i = 0; i < 4; i++)
#pragma unroll
                    for (int j = 0; j < 4; j++) {
                        fma2(s0p[i][j], q2[i].x, k2[j].x);
                        fma2(s0p[i][j], q2[i].y, k2[j].y);
                    }
            }
#pragma unroll
            for (int fc = 16; fc < 32; fc++) {         // branch 1: cols 64..127
                ulonglong2 q2[4], k2[4];
#pragma unroll
                for (int i = 0; i < 4; i++)
                    q2[i] = *(const ulonglong2*)(Qs + (ty * 4 + i) * QSTRIDE + fc * 4);
#pragma unroll
                for (int j = 0; j < 4; j++)
                    k2[j] = *(const ulonglong2*)(Ks + (tx + 16 * j) * QSTRIDE + fc * 4);
#pragma unroll
                for (int i = 0; i < 4; i++)
#pragma unroll
                    for (int j = 0; j < 4; j++) {
                        fma2(s1p[i][j], q2[i].x, k2[j].x);
                        fma2(s1p[i][j], q2[i].y, k2[j].y);
                    }
            }
#pragma unroll
            for (int i = 0; i < 4; i++)
#pragma unroll
                for (int j = 0; j < 4; j++) {
                    float2 e0 = unpack2(s0p[i][j]);
                    float2 e1 = unpack2(s1p[i][j]);
                    S0[(ty * 4 + i) * SSTRIDE + (tx + 16 * j)] = (e0.x + e0.y) * scale;
                    S1[(ty * 4 + i) * SSTRIDE + (tx + 16 * j)] = (e1.x + e1.y) * scale;
                }
        }
        __syncthreads();

        // ---- online softmax update (4 threads per row, 16 keys each) ----
        {
            const int base0 = rrow * SSTRIDE + rpart * 16;
            // branch 0
            {
                float pv[16];
                float mloc = -1e30f;
#pragma unroll
                for (int jj = 0; jj < 16; jj++) { pv[jj] = S0[base0 + jj]; mloc = fmaxf(mloc, pv[jj]); }
                mloc = fmaxf(mloc, __shfl_xor_sync(0xffffffffu, mloc, 1));
                mloc = fmaxf(mloc, __shfl_xor_sync(0xffffffffu, mloc, 2));
                float mo = m0s[rrow];
                float mn = fmaxf(mo, mloc);
                float sum = 0.f;
#pragma unroll
                for (int jj = 0; jj < 16; jj++) {
                    float p = __expf(pv[jj] - mn);
                    S0[base0 + jj] = p;
                    sum += p;
                }
                sum += __shfl_xor_sync(0xffffffffu, sum, 1);
                sum += __shfl_xor_sync(0xffffffffu, sum, 2);
                if (rpart == 0) {
                    float cc = __expf(mo - mn);
                    c0s[rrow] = cc;
                    l0s[rrow] = l0s[rrow] * cc + sum;
                    m0s[rrow] = mn;
                }
            }
            // branch 1
            {
                float pv[16];
                float mloc = -1e30f;
#pragma unroll
                for (int jj = 0; jj < 16; jj++) { pv[jj] = S1[base0 + jj]; mloc = fmaxf(mloc, pv[jj]); }
                mloc = fmaxf(mloc, __shfl_xor_sync(0xffffffffu, mloc, 1));
                mloc = fmaxf(mloc, __shfl_xor_sync(0xffffffffu, mloc, 2));
                float mo = m1s[rrow];
                float mn = fmaxf(mo, mloc);
                float sum = 0.f;
#pragma unroll
                for (int jj = 0; jj < 16; jj++) {
                    float p = __expf(pv[jj] - mn);
                    S1[base0 + jj] = p;
                    sum += p;
                }
                sum += __shfl_xor_sync(0xffffffffu, sum, 1);
                sum += __shfl_xor_sync(0xffffffffu, sum, 2);
                if (rpart == 0) {
                    float cc = __expf(mo - mn);
                    c1s[rrow] = cc;
                    l1s[rrow] = l1s[rrow] * cc + sum;
                    m1s[rrow] = mn;
                }
            }
        }
        __syncthreads();

        // ---- PV accumulation (packed, float4 score loads = conflict-free) ----
        {
            u64 c0p = pack2(c0s[qo], c0s[qo]);
            u64 c1p = pack2(c1s[qo], c1s[qo]);
#pragma unroll
            for (int jj = 0; jj < 16; jj++) { mul2(a0[jj], c0p); mul2(a1[jj], c1p); }
            const float* s0r = S0 + qo * SSTRIDE;
            const float* s1r = S1 + qo * SSTRIDE;
            const float* vbase = Vs + g * 32;
            for (int kk = 0; kk < BKT; kk += 4) {
                float4 p0q = *(const float4*)(s0r + kk);
                float4 p1q = *(const float4*)(s1r + kk);
                float p0a[4] = { p0q.x, p0q.y, p0q.z, p0q.w };
                float p1a[4] = { p1q.x, p1q.y, p1q.z, p1q.w };
#pragma unroll
                for (int s = 0; s < 4; s++) {
                    u64 p0p = pack2(p0a[s], p0a[s]);
                    u64 p1p = pack2(p1a[s], p1a[s]);
                    const ulonglong2* vr = (const ulonglong2*)(vbase + (kk + s) * QSTRIDE);
#pragma unroll
                    for (int w = 0; w < 8; w++) {
                        ulonglong2 vv = vr[w];
                        fma2(a0[2 * w + 0], p0p, vv.x);
                        fma2(a0[2 * w + 1], p0p, vv.y);
                        fma2(a1[2 * w + 0], p1p, vv.x);
                        fma2(a1[2 * w + 1], p1p, vv.y);
                    }
                }
            }
        }
    }
    __syncthreads();

    // ---- epilogue: o = O0/l0 - dw * O1/l1, stage via smem (reuse Ks) ----
    {
        float inv0 = 1.f / l0s[qo];
        float inv1 = 1.f / l1s[qo];
        float dw = *dwp;
        float* orow = Ks + qo * QSTRIDE + g * 32;
#pragma unroll
        for (int w = 0; w < 8; w++) {
            float2 e0a = unpack2(a0[2 * w + 0]);
            float2 e0b = unpack2(a0[2 * w + 1]);
            float2 e1a = unpack2(a1[2 * w + 0]);
            float2 e1b = unpack2(a1[2 * w + 1]);
            float4 r4;
            r4.x = e0a.x * inv0 - dw * (e1a.x * inv1);
            r4.y = e0a.y * inv0 - dw * (e1a.y * inv1);
            r4.z = e0b.x * inv0 - dw * (e1b.x * inv1);
            r4.w = e0b.y * inv0 - dw * (e1b.y * inv1);
            *(float4*)(orow + w * 4) = r4;
        }
    }
    __syncthreads();

    float* og = o + ((size_t)b * SLEN + q0) * EDIM + h * 128;
#pragma unroll
    for (int j = 0; j < 8; j++) {
        int f = tid + j * 256;
        int r = f >> 5, c4 = f & 31;
        *(float4*)(og + (size_t)r * EDIM + c4 * 4) = *(const float4*)(Ks + r * QSTRIDE + c4 * 4);
    }
}

// ======================================================================
// RMSNorm over 1024-wide rows, fused split-bf16 output:
//   y = x * rsqrt(mean(x^2)+eps) * w  ->  (yhi, ylo) bf16 pair
// ======================================================================
__global__ void __launch_bounds__(256) rmsnorm_split_kernel(
    const float* __restrict__ x, const float* __restrict__ w,
    __nv_bfloat16* __restrict__ yhi, __nv_bfloat16* __restrict__ ylo)
{
    __shared__ float red[8];
    __shared__ float rtot;
    const int tid = threadIdx.x;
    const int row = blockIdx.x;
    const float* xr = x + (size_t)row * EDIM;

    float v[4];
    float s = 0.f;
#pragma unroll
    for (int j = 0; j < 4; j++) {
        v[j] = xr[tid + j * 256];
        s = fmaf(v[j], v[j], s);
    }
#pragma unroll
    for (int off = 16; off > 0; off >>= 1)
        s += __shfl_xor_sync(0xffffffffu, s, off);
    if ((tid & 31) == 0) red[tid >> 5] = s;
    __syncthreads();
    if (tid == 0) {
        float t = 0.f;
#pragma unroll
        for (int i = 0; i < 8; i++) t += red[i];
        rtot = rsqrtf(t * (1.0f / 1024.0f) + 1.1920929e-07f);
    }
    __syncthreads();
    float r = rtot;
#pragma unroll
    for (int j = 0; j < 4; j++) {
        int c = tid + j * 256;
        float f = v[j] * r * w[c];
        __nv_bfloat16 h = __float2bfloat16_rn(f);
        __nv_bfloat16 l = __float2bfloat16_rn(f - __bfloat162float(h));
        yhi[(size_t)row * EDIM + c] = h;
        ylo[(size_t)row * EDIM + c] = l;
    }
}

// ======================================================================
// launcher
// ======================================================================
extern "C" void kernel_launch(void* const* d_in, const int* in_sizes, int n_in,
                              void* d_out, int out_size)
{
    const float* x  = (const float*)d_in[0];
    const float* Wq = (const float*)d_in[1];
    const float* Wk = (const float*)d_in[2];
    const float* Wv = (const float*)d_in[3];
    const float* nw = (const float*)d_in[4];
    const float* Wo = (const float*)d_in[5];
    const float* bo = (const float*)d_in[6];
    const float* dw = (const float*)d_in[7];
    float* out = (float*)d_out;

    float *qp, *kp, *vp, *op;
    cudaGetSymbolAddress((void**)&qp, g_q);
    cudaGetSymbolAddress((void**)&kp, g_k);
    cudaGetSymbolAddress((void**)&vp, g_v);
    cudaGetSymbolAddress((void**)&op, g_o);
    __nv_bfloat16 *xh, *xl, *nh, *nl;
    cudaGetSymbolAddress((void**)&xh, g_xhi);
    cudaGetSymbolAddress((void**)&xl, g_xlo);
    cudaGetSymbolAddress((void**)&nh, g_nhi);
    cudaGetSymbolAddress((void**)&nl, g_nlo);
    __nv_bfloat16 *wqh, *wql, *wkh, *wkl, *wvh, *wvl, *woh, *wol;
    cudaGetSymbolAddress((void**)&wqh, g_wqhi);
    cudaGetSymbolAddress((void**)&wql, g_wqlo);
    cudaGetSymbolAddress((void**)&wkh, g_wkhi);
    cudaGetSymbolAddress((void**)&wkl, g_wklo);
    cudaGetSymbolAddress((void**)&wvh, g_wvhi);
    cudaGetSymbolAddress((void**)&wvl, g_wvlo);
    cudaGetSymbolAddress((void**)&woh, g_wohi);
    cudaGetSymbolAddress((void**)&wol, g_wolo);

    cudaFuncSetAttribute(diff_attn_kernel,
                         cudaFuncAttributeMaxDynamicSharedMemorySize, ATT_SMEM_BYTES);

    // split conversions
    const int xn4 = MROWS * EDIM / 4;   // 1,048,576
    const int wn4 = EDIM * EDIM / 4;    // 262,144
    split_bf16_kernel<<<xn4 / 256, 256>>>(x,  xh, xl, xn4);
    split_bf16_kernel<<<wn4 / 256, 256>>>(Wq, wqh, wql, wn4);
    split_bf16_kernel<<<wn4 / 256, 256>>>(Wk, wkh, wkl, wn4);
    split_bf16_kernel<<<wn4 / 256, 256>>>(Wv, wvh, wvl, wn4);
    split_bf16_kernel<<<wn4 / 256, 256>>>(Wo, woh, wol, wn4);

    // projections (HMMA split-bf16)
    dim3 gg(EDIM / 128, MROWS / 128);
    mma_gemm_kernel<<<gg, 256>>>(xh, xl, wqh, wql, qp, MROWS, EDIM, EDIM, nullptr, nullptr);
    mma_gemm_kernel<<<gg, 256>>>(xh, xl, wkh, wkl, kp, MROWS, EDIM, EDIM, nullptr, nullptr);
    mma_gemm_kernel<<<gg, 256>>>(xh, xl, wvh, wvl, vp, MROWS, EDIM, EDIM, nullptr, nullptr);

    // attention
    dim3 ga(SLEN / BQ, NHEAD, 2);
    diff_attn_kernel<<<ga, 256, ATT_SMEM_BYTES>>>(qp, kp, vp, op, dw);

    // rmsnorm + split
    rmsnorm_split_kernel<<<MROWS, 256>>>(op, nw, nh, nl);

    // output projection with bias + (1-dw) scale
    mma_gemm_kernel<<<gg, 256>>>(nh, nl, woh, wol, out, MROWS, EDIM, EDIM, bo, dw);
}

// round 8
// speedup vs baseline: 1.8721x; 1.3542x over previous
#include <cuda_runtime.h>
#include <cuda_bf16.h>
#include <cstdint>
#include <cstddef>
#include <math.h>

#define MROWS 4096           // B*S
#define EDIM  1024
#define SLEN  2048
#define NHEAD 8

// ---------------- warp-level bf16 MMA (m16n8k16, fp32 accum) ----------------
__device__ __forceinline__ void mma16816(
    float* c, const unsigned* a, const unsigned* b)
{
    asm volatile(
        "mma.sync.aligned.m16n8k16.row.col.f32.bf16.bf16.f32 "
        "{%0,%1,%2,%3}, {%4,%5,%6,%7}, {%8,%9}, {%0,%1,%2,%3};"
        : "+f"(c[0]), "+f"(c[1]), "+f"(c[2]), "+f"(c[3])
        : "r"(a[0]), "r"(a[1]), "r"(a[2]), "r"(a[3]), "r"(b[0]), "r"(b[1]));
}

// ---------------- scratch (device globals: allocation-free) ----------------
__device__ float g_o[(size_t)MROWS * EDIM];
__device__ __nv_bfloat16 g_xhi[(size_t)MROWS * EDIM];
__device__ __nv_bfloat16 g_xlo[(size_t)MROWS * EDIM];
__device__ __nv_bfloat16 g_nhi[(size_t)MROWS * EDIM];
__device__ __nv_bfloat16 g_nlo[(size_t)MROWS * EDIM];
__device__ __nv_bfloat16 g_qh[(size_t)MROWS * EDIM];
__device__ __nv_bfloat16 g_ql[(size_t)MROWS * EDIM];
__device__ __nv_bfloat16 g_kh[(size_t)MROWS * EDIM];
__device__ __nv_bfloat16 g_kl[(size_t)MROWS * EDIM];
__device__ __nv_bfloat16 g_vh[(size_t)MROWS * EDIM];
__device__ __nv_bfloat16 g_vl[(size_t)MROWS * EDIM];
__device__ __nv_bfloat16 g_wqhi[(size_t)EDIM * EDIM];
__device__ __nv_bfloat16 g_wqlo[(size_t)EDIM * EDIM];
__device__ __nv_bfloat16 g_wkhi[(size_t)EDIM * EDIM];
__device__ __nv_bfloat16 g_wklo[(size_t)EDIM * EDIM];
__device__ __nv_bfloat16 g_wvhi[(size_t)EDIM * EDIM];
__device__ __nv_bfloat16 g_wvlo[(size_t)EDIM * EDIM];
__device__ __nv_bfloat16 g_wohi[(size_t)EDIM * EDIM];
__device__ __nv_bfloat16 g_wolo[(size_t)EDIM * EDIM];

// ======================================================================
// fp32 -> (bf16 hi, bf16 lo) split, vectorized float4
// ======================================================================
__global__ void __launch_bounds__(256) split_bf16_kernel(
    const float* __restrict__ x, __nv_bfloat16* __restrict__ hi,
    __nv_bfloat16* __restrict__ lo, int n4)
{
    int i = blockIdx.x * 256 + threadIdx.x;
    if (i >= n4) return;
    float4 v = ((const float4*)x)[i];
    float vv[4] = { v.x, v.y, v.z, v.w };
    __nv_bfloat16 h[4], l[4];
#pragma unroll
    for (int j = 0; j < 4; j++) {
        h[j] = __float2bfloat16_rn(vv[j]);
        l[j] = __float2bfloat16_rn(vv[j] - __bfloat162float(h[j]));
    }
    __nv_bfloat162* hp = (__nv_bfloat162*)hi;
    __nv_bfloat162* lp = (__nv_bfloat162*)lo;
    hp[i * 2 + 0] = __nv_bfloat162(h[0], h[1]);
    hp[i * 2 + 1] = __nv_bfloat162(h[2], h[3]);
    lp[i * 2 + 0] = __nv_bfloat162(l[0], l[1]);
    lp[i * 2 + 1] = __nv_bfloat162(l[2], l[3]);
}

// ======================================================================
// HMMA split-bf16 GEMM: C = A[M,K] @ B[N,K]^T
// Output either fp32 (bias + (1-dw) scale) or bf16 hi/lo pair.
// ======================================================================
#define TS 24   // smem row stride in bf16 (48B) -> conflict-free fragment loads

__global__ void __launch_bounds__(256) mma_gemm_kernel(
    const __nv_bfloat16* __restrict__ Ahi, const __nv_bfloat16* __restrict__ Alo,
    const __nv_bfloat16* __restrict__ Bhi, const __nv_bfloat16* __restrict__ Blo,
    float* __restrict__ Cf, __nv_bfloat16* __restrict__ Chi, __nv_bfloat16* __restrict__ Clo,
    int M, int N, int K,
    const float* __restrict__ bias, const float* __restrict__ dwp)
{
    __shared__ __nv_bfloat16 sAhi[128 * TS];
    __shared__ __nv_bfloat16 sAlo[128 * TS];
    __shared__ __nv_bfloat16 sBhi[128 * TS];
    __shared__ __nv_bfloat16 sBlo[128 * TS];

    const int tid = threadIdx.x;
    const int wid = tid >> 5, L = tid & 31;
    const int bm = blockIdx.y * 128, bn = blockIdx.x * 128;
    const int wm = (wid >> 2) * 64, wn = (wid & 3) * 32;

    const int lrow = tid >> 1;            // 0..127
    const int lseg = (tid & 1) * 8;       // 0 or 8 (bf16)

    const int fr = L >> 2;                // 0..7
    const int fc = (L & 3) * 2;           // 0,2,4,6

    float acc[4][4][4];
#pragma unroll
    for (int mt = 0; mt < 4; mt++)
#pragma unroll
        for (int nt = 0; nt < 4; nt++)
#pragma unroll
            for (int e = 0; e < 4; e++) acc[mt][nt][e] = 0.f;

    for (int kc = 0; kc < K; kc += 16) {
        __syncthreads();
        *(float4*)&sAhi[lrow * TS + lseg] =
            *(const float4*)(Ahi + (size_t)(bm + lrow) * K + kc + lseg);
        *(float4*)&sAlo[lrow * TS + lseg] =
            *(const float4*)(Alo + (size_t)(bm + lrow) * K + kc + lseg);
        *(float4*)&sBhi[lrow * TS + lseg] =
            *(const float4*)(Bhi + (size_t)(bn + lrow) * K + kc + lseg);
        *(float4*)&sBlo[lrow * TS + lseg] =
            *(const float4*)(Blo + (size_t)(bn + lrow) * K + kc + lseg);
        __syncthreads();

        unsigned bh[4][2], bl[4][2];
#pragma unroll
        for (int nt = 0; nt < 4; nt++) {
            int n = wn + nt * 8 + fr;
            bh[nt][0] = *(const unsigned*)&sBhi[n * TS + fc];
            bh[nt][1] = *(const unsigned*)&sBhi[n * TS + fc + 8];
            bl[nt][0] = *(const unsigned*)&sBlo[n * TS + fc];
            bl[nt][1] = *(const unsigned*)&sBlo[n * TS + fc + 8];
        }
#pragma unroll
        for (int mt = 0; mt < 4; mt++) {
            int m = wm + mt * 16 + fr;
            unsigned ah[4], al[4];
            ah[0] = *(const unsigned*)&sAhi[m * TS + fc];
            ah[1] = *(const unsigned*)&sAhi[(m + 8) * TS + fc];
            ah[2] = *(const unsigned*)&sAhi[m * TS + fc + 8];
            ah[3] = *(const unsigned*)&sAhi[(m + 8) * TS + fc + 8];
            al[0] = *(const unsigned*)&sAlo[m * TS + fc];
            al[1] = *(const unsigned*)&sAlo[(m + 8) * TS + fc];
            al[2] = *(const unsigned*)&sAlo[m * TS + fc + 8];
            al[3] = *(const unsigned*)&sAlo[(m + 8) * TS + fc + 8];
#pragma unroll
            for (int nt = 0; nt < 4; nt++) {
                mma16816(acc[mt][nt], ah, bh[nt]);
                mma16816(acc[mt][nt], ah, bl[nt]);
                mma16816(acc[mt][nt], al, bh[nt]);
            }
        }
    }

    if (Cf) {
        float sc = 1.0f;
        if (dwp) sc = 1.0f - *dwp;
#pragma unroll
        for (int mt = 0; mt < 4; mt++) {
#pragma unroll
            for (int nt = 0; nt < 4; nt++) {
                int row = bm + wm + mt * 16 + fr;
                int col = bn + wn + nt * 8 + fc;
                float b0 = 0.f, b1 = 0.f;
                if (bias) { b0 = bias[col]; b1 = bias[col + 1]; }
                float2 r0, r1;
                r0.x = (acc[mt][nt][0] + b0) * sc;
                r0.y = (acc[mt][nt][1] + b1) * sc;
                r1.x = (acc[mt][nt][2] + b0) * sc;
                r1.y = (acc[mt][nt][3] + b1) * sc;
                *(float2*)(Cf + (size_t)row * N + col) = r0;
                *(float2*)(Cf + (size_t)(row + 8) * N + col) = r1;
            }
        }
    } else {
#pragma unroll
        for (int mt = 0; mt < 4; mt++) {
#pragma unroll
            for (int nt = 0; nt < 4; nt++) {
                int row = bm + wm + mt * 16 + fr;
                int col = bn + wn + nt * 8 + fc;
#pragma unroll
                for (int half = 0; half < 2; half++) {
                    float v0 = acc[mt][nt][half * 2 + 0];
                    float v1 = acc[mt][nt][half * 2 + 1];
                    __nv_bfloat16 h0 = __float2bfloat16_rn(v0);
                    __nv_bfloat16 h1 = __float2bfloat16_rn(v1);
                    __nv_bfloat16 l0 = __float2bfloat16_rn(v0 - __bfloat162float(h0));
                    __nv_bfloat16 l1 = __float2bfloat16_rn(v1 - __bfloat162float(h1));
                    size_t off = (size_t)(row + half * 8) * N + col;
                    *(__nv_bfloat162*)(Chi + off) = __nv_bfloat162(h0, h1);
                    *(__nv_bfloat162*)(Clo + off) = __nv_bfloat162(l0, l1);
                }
            }
        }
    }
}

// ======================================================================
// HMMA differential flash attention.
// CTA: (b, h, 64-q tile), 256 threads = 8 warps.
// Warps 0-3: branch0 (features 0..63), warps 4-7: branch1 (features 64..127).
// QK: warp w computes 16x64 score strip (3-term split MMA).
// PV: O^T[d][q] = Vt[d][k] * P[q][k], V transposed in smem, P bf16 hi/lo.
// ======================================================================
#define BQ 64
#define BKT 64
#define QS  136   // bf16 stride for Q/K smem tiles
#define VTS 72    // bf16 stride for Vt
#define SSR 68    // fp32 stride for score tiles
#define PS  72    // bf16 stride for P tiles
#define OTS 68    // fp32 stride for Ot staging
#define OFS 132   // fp32 stride for final O staging

#define OFF_QHI  0
#define OFF_QLO  17408
#define OFF_KHI  34816
#define OFF_KLO  52224
#define OFF_VTHI 69632
#define OFF_VTLO 88064
#define OFF_S0   106496
#define OFF_S1   123904
#define OFF_PHI0 141312
#define OFF_PLO0 150528
#define OFF_PHI1 159744
#define OFF_PLO1 168960
#define OFF_STAT 178176
#define ATT_SMEM_BYTES (OFF_STAT + 6 * 64 * 4)   // 179712

__global__ void __launch_bounds__(256) diff_attn_mma_kernel(
    const __nv_bfloat16* __restrict__ qh_g, const __nv_bfloat16* __restrict__ ql_g,
    const __nv_bfloat16* __restrict__ kh_g, const __nv_bfloat16* __restrict__ kl_g,
    const __nv_bfloat16* __restrict__ vh_g, const __nv_bfloat16* __restrict__ vl_g,
    float* __restrict__ o, const float* __restrict__ dwp)
{
    extern __shared__ char smem[];
    __nv_bfloat16* Qhi  = (__nv_bfloat16*)(smem + OFF_QHI);
    __nv_bfloat16* Qlo  = (__nv_bfloat16*)(smem + OFF_QLO);
    __nv_bfloat16* Khi  = (__nv_bfloat16*)(smem + OFF_KHI);
    __nv_bfloat16* Klo  = (__nv_bfloat16*)(smem + OFF_KLO);
    __nv_bfloat16* Vthi = (__nv_bfloat16*)(smem + OFF_VTHI);
    __nv_bfloat16* Vtlo = (__nv_bfloat16*)(smem + OFF_VTLO);
    float* S0 = (float*)(smem + OFF_S0);
    float* S1 = (float*)(smem + OFF_S1);
    __nv_bfloat16* Phi0 = (__nv_bfloat16*)(smem + OFF_PHI0);
    __nv_bfloat16* Plo0 = (__nv_bfloat16*)(smem + OFF_PLO0);
    __nv_bfloat16* Phi1 = (__nv_bfloat16*)(smem + OFF_PHI1);
    __nv_bfloat16* Plo1 = (__nv_bfloat16*)(smem + OFF_PLO1);
    float* m0s = (float*)(smem + OFF_STAT);
    float* l0s = m0s + 64;
    float* m1s = l0s + 64;
    float* l1s = m1s + 64;
    float* c0s = l1s + 64;
    float* c1s = c0s + 64;
    float* Ot = (float*)(smem + OFF_KHI);   // reused after main loop
    float* Of = (float*)(smem + OFF_S0);    // reused after main loop

    const int tid = threadIdx.x;
    const int wid = tid >> 5, L = tid & 31;
    const int fr = L >> 2;           // 0..7
    const int fc2 = (L & 3) * 2;     // 0,2,4,6
    const int qt = blockIdx.x, hd = blockIdx.y, b = blockIdx.z;
    const int q0 = qt * BQ;
    const int bidx = wid >> 2;       // branch
    const int ws = wid & 3;          // warp slot within branch

    const size_t rowbase = (size_t)b * SLEN;

    // ---- load Q tile (hi/lo), 64 x 128 bf16 each ----
#pragma unroll
    for (int i = 0; i < 4; i++) {
        int f = tid + i * 256;               // 0..1023
        int r = f >> 4, c = f & 15;
        size_t src = (rowbase + q0 + r) * EDIM + hd * 128 + c * 8;
        *(uint4*)(smem + OFF_QHI + r * (QS * 2) + c * 16) = *(const uint4*)(qh_g + src);
        *(uint4*)(smem + OFF_QLO + r * (QS * 2) + c * 16) = *(const uint4*)(ql_g + src);
    }
    if (tid < BQ) {
        m0s[tid] = -1e30f; m1s[tid] = -1e30f;
        l0s[tid] = 0.f;    l1s[tid] = 0.f;
    }

    const int rrow = tid >> 2, rpart = tid & 3;   // softmax mapping

    float pacc[2][8][4];
#pragma unroll
    for (int s = 0; s < 2; s++)
#pragma unroll
        for (int nt = 0; nt < 8; nt++)
#pragma unroll
            for (int e = 0; e < 4; e++) pacc[s][nt][e] = 0.f;

    const float scale = 0.125f;

    for (int kt = 0; kt < SLEN; kt += BKT) {
        __syncthreads();
        // ---- load K tile (hi/lo) ----
#pragma unroll
        for (int i = 0; i < 4; i++) {
            int f = tid + i * 256;
            int r = f >> 4, c = f & 15;
            size_t src = (rowbase + kt + r) * EDIM + hd * 128 + c * 8;
            *(uint4*)(smem + OFF_KHI + r * (QS * 2) + c * 16) = *(const uint4*)(kh_g + src);
            *(uint4*)(smem + OFF_KLO + r * (QS * 2) + c * 16) = *(const uint4*)(kl_g + src);
        }
        // ---- load V tile transposed (staggered scalar stores) ----
#pragma unroll
        for (int i = 0; i < 4; i++) {
            int idx = tid + i * 256;          // 0..1023
            int kk = idx >> 4, dg = idx & 15, d0 = dg * 8;
            size_t src = (rowbase + kt + kk) * EDIM + hd * 128 + d0;
            union { uint4 u; __nv_bfloat16 h[8]; } vh_, vl_;
            vh_.u = *(const uint4*)(vh_g + src);
            vl_.u = *(const uint4*)(vl_g + src);
#pragma unroll
            for (int j = 0; j < 8; j++) {
                int jj = (j + dg) & 7;
                Vthi[(d0 + jj) * VTS + kk] = vh_.h[jj];
                Vtlo[(d0 + jj) * VTS + kk] = vl_.h[jj];
            }
        }
        __syncthreads();

        // ---- QK^T: 16x64 strip per warp, 3-term split ----
        {
            float sacc[8][4];
#pragma unroll
            for (int nt = 0; nt < 8; nt++)
#pragma unroll
                for (int e = 0; e < 4; e++) sacc[nt][e] = 0.f;

            const int ms = ws * 16;
#pragma unroll
            for (int ks = 0; ks < 4; ks++) {
                int koff = bidx * 64 + ks * 16;
                unsigned ah[4], al[4];
                ah[0] = *(const unsigned*)&Qhi[(ms + fr) * QS + koff + fc2];
                ah[1] = *(const unsigned*)&Qhi[(ms + fr + 8) * QS + koff + fc2];
                ah[2] = *(const unsigned*)&Qhi[(ms + fr) * QS + koff + fc2 + 8];
                ah[3] = *(const unsigned*)&Qhi[(ms + fr + 8) * QS + koff + fc2 + 8];
                al[0] = *(const unsigned*)&Qlo[(ms + fr) * QS + koff + fc2];
                al[1] = *(const unsigned*)&Qlo[(ms + fr + 8) * QS + koff + fc2];
                al[2] = *(const unsigned*)&Qlo[(ms + fr) * QS + koff + fc2 + 8];
                al[3] = *(const unsigned*)&Qlo[(ms + fr + 8) * QS + koff + fc2 + 8];
#pragma unroll
                for (int nt = 0; nt < 8; nt++) {
                    unsigned bh[2], bl[2];
                    bh[0] = *(const unsigned*)&Khi[(nt * 8 + fr) * QS + koff + fc2];
                    bh[1] = *(const unsigned*)&Khi[(nt * 8 + fr) * QS + koff + fc2 + 8];
                    bl[0] = *(const unsigned*)&Klo[(nt * 8 + fr) * QS + koff + fc2];
                    bl[1] = *(const unsigned*)&Klo[(nt * 8 + fr) * QS + koff + fc2 + 8];
                    mma16816(sacc[nt], ah, bh);
                    mma16816(sacc[nt], ah, bl);
                    mma16816(sacc[nt], al, bh);
                }
            }
            float* Sb = bidx ? S1 : S0;
#pragma unroll
            for (int nt = 0; nt < 8; nt++) {
                float2 r0 = make_float2(sacc[nt][0] * scale, sacc[nt][1] * scale);
                float2 r1 = make_float2(sacc[nt][2] * scale, sacc[nt][3] * scale);
                *(float2*)&Sb[(ms + fr) * SSR + nt * 8 + fc2] = r0;
                *(float2*)&Sb[(ms + fr + 8) * SSR + nt * 8 + fc2] = r1;
            }
        }
        __syncthreads();

        // ---- online softmax: 4 threads/row, 16 keys each; emit P hi/lo ----
        {
            const int base0 = rrow * SSR + rpart * 16;
            // branch 0
            {
                float pv[16];
                float mloc = -1e30f;
#pragma unroll
                for (int jj = 0; jj < 16; jj++) { pv[jj] = S0[base0 + jj]; mloc = fmaxf(mloc, pv[jj]); }
                mloc = fmaxf(mloc, __shfl_xor_sync(0xffffffffu, mloc, 1));
                mloc = fmaxf(mloc, __shfl_xor_sync(0xffffffffu, mloc, 2));
                float mo = m0s[rrow];
                float mn = fmaxf(mo, mloc);
                float sum = 0.f;
#pragma unroll
                for (int jj = 0; jj < 16; jj++) {
                    pv[jj] = __expf(pv[jj] - mn);
                    sum += pv[jj];
                }
#pragma unroll
                for (int t = 0; t < 8; t++) {
                    float v0 = pv[2 * t], v1 = pv[2 * t + 1];
                    __nv_bfloat16 h0 = __float2bfloat16_rn(v0);
                    __nv_bfloat16 h1 = __float2bfloat16_rn(v1);
                    __nv_bfloat16 e0 = __float2bfloat16_rn(v0 - __bfloat162float(h0));
                    __nv_bfloat16 e1 = __float2bfloat16_rn(v1 - __bfloat162float(h1));
                    int off = rrow * PS + rpart * 16 + 2 * t;
                    *(__nv_bfloat162*)&Phi0[off] = __nv_bfloat162(h0, h1);
                    *(__nv_bfloat162*)&Plo0[off] = __nv_bfloat162(e0, e1);
                }
                sum += __shfl_xor_sync(0xffffffffu, sum, 1);
                sum += __shfl_xor_sync(0xffffffffu, sum, 2);
                if (rpart == 0) {
                    float cc = __expf(mo - mn);
                    c0s[rrow] = cc;
                    l0s[rrow] = l0s[rrow] * cc + sum;
                    m0s[rrow] = mn;
                }
            }
            // branch 1
            {
                float pv[16];
                float mloc = -1e30f;
#pragma unroll
                for (int jj = 0; jj < 16; jj++) { pv[jj] = S1[base0 + jj]; mloc = fmaxf(mloc, pv[jj]); }
                mloc = fmaxf(mloc, __shfl_xor_sync(0xffffffffu, mloc, 1));
                mloc = fmaxf(mloc, __shfl_xor_sync(0xffffffffu, mloc, 2));
                float mo = m1s[rrow];
                float mn = fmaxf(mo, mloc);
                float sum = 0.f;
#pragma unroll
                for (int jj = 0; jj < 16; jj++) {
                    pv[jj] = __expf(pv[jj] - mn);
                    sum += pv[jj];
                }
#pragma unroll
                for (int t = 0; t < 8; t++) {
                    float v0 = pv[2 * t], v1 = pv[2 * t + 1];
                    __nv_bfloat16 h0 = __float2bfloat16_rn(v0);
                    __nv_bfloat16 h1 = __float2bfloat16_rn(v1);
                    __nv_bfloat16 e0 = __float2bfloat16_rn(v0 - __bfloat162float(h0));
                    __nv_bfloat16 e1 = __float2bfloat16_rn(v1 - __bfloat162float(h1));
                    int off = rrow * PS + rpart * 16 + 2 * t;
                    *(__nv_bfloat162*)&Phi1[off] = __nv_bfloat162(h0, h1);
                    *(__nv_bfloat162*)&Plo1[off] = __nv_bfloat162(e0, e1);
                }
                sum += __shfl_xor_sync(0xffffffffu, sum, 1);
                sum += __shfl_xor_sync(0xffffffffu, sum, 2);
                if (rpart == 0) {
                    float cc = __expf(mo - mn);
                    c1s[rrow] = cc;
                    l1s[rrow] = l1s[rrow] * cc + sum;
                    m1s[rrow] = mn;
                }
            }
        }
        __syncthreads();

        // ---- PV: O^T[d][q] += Vt[d][k] * P[q][k] (3-term split) ----
        {
            const float* cs = bidx ? c1s : c0s;
            const __nv_bfloat16* Ph = bidx ? Phi1 : Phi0;
            const __nv_bfloat16* Pl = bidx ? Plo1 : Plo0;
            float cc0[8], cc1[8];
#pragma unroll
            for (int nt = 0; nt < 8; nt++) {
                cc0[nt] = cs[nt * 8 + fc2];
                cc1[nt] = cs[nt * 8 + fc2 + 1];
            }
#pragma unroll
            for (int s = 0; s < 2; s++)
#pragma unroll
                for (int nt = 0; nt < 8; nt++) {
                    pacc[s][nt][0] *= cc0[nt];
                    pacc[s][nt][1] *= cc1[nt];
                    pacc[s][nt][2] *= cc0[nt];
                    pacc[s][nt][3] *= cc1[nt];
                }
#pragma unroll
            for (int ks = 0; ks < 4; ks++) {
                unsigned ah[2][4], al[2][4];
#pragma unroll
                for (int s = 0; s < 2; s++) {
                    int dbase = ws * 16 + s * 64;
                    ah[s][0] = *(const unsigned*)&Vthi[(dbase + fr) * VTS + ks * 16 + fc2];
                    ah[s][1] = *(const unsigned*)&Vthi[(dbase + fr + 8) * VTS + ks * 16 + fc2];
                    ah[s][2] = *(const unsigned*)&Vthi[(dbase + fr) * VTS + ks * 16 + fc2 + 8];
                    ah[s][3] = *(const unsigned*)&Vthi[(dbase + fr + 8) * VTS + ks * 16 + fc2 + 8];
                    al[s][0] = *(const unsigned*)&Vtlo[(dbase + fr) * VTS + ks * 16 + fc2];
                    al[s][1] = *(const unsigned*)&Vtlo[(dbase + fr + 8) * VTS + ks * 16 + fc2];
                    al[s][2] = *(const unsigned*)&Vtlo[(dbase + fr) * VTS + ks * 16 + fc2 + 8];
                    al[s][3] = *(const unsigned*)&Vtlo[(dbase + fr + 8) * VTS + ks * 16 + fc2 + 8];
                }
#pragma unroll
                for (int nt = 0; nt < 8; nt++) {
                    unsigned bh[2], bl[2];
                    bh[0] = *(const unsigned*)&Ph[(nt * 8 + fr) * PS + ks * 16 + fc2];
                    bh[1] = *(const unsigned*)&Ph[(nt * 8 + fr) * PS + ks * 16 + fc2 + 8];
                    bl[0] = *(const unsigned*)&Pl[(nt * 8 + fr) * PS + ks * 16 + fc2];
                    bl[1] = *(const unsigned*)&Pl[(nt * 8 + fr) * PS + ks * 16 + fc2 + 8];
#pragma unroll
                    for (int s = 0; s < 2; s++) {
                        mma16816(pacc[s][nt], ah[s], bh);
                        mma16816(pacc[s][nt], ah[s], bl);
                        mma16816(pacc[s][nt], al[s], bh);
                    }
                }
            }
        }
    }
    __syncthreads();

    // ---- epilogue: o = O0/l0 - dw * O1/l1 ----
    const float dw = *dwp;
    if (bidx == 1) {
        float i0[8], i1[8];
#pragma unroll
        for (int nt = 0; nt < 8; nt++) {
            i0[nt] = 1.f / l1s[nt * 8 + fc2];
            i1[nt] = 1.f / l1s[nt * 8 + fc2 + 1];
        }
#pragma unroll
        for (int s = 0; s < 2; s++) {
            int dbase = ws * 16 + s * 64;
#pragma unroll
            for (int nt = 0; nt < 8; nt++) {
                int qcol = nt * 8 + fc2;
                *(float2*)&Ot[(dbase + fr) * OTS + qcol] =
                    make_float2(pacc[s][nt][0] * i0[nt], pacc[s][nt][1] * i1[nt]);
                *(float2*)&Ot[(dbase + fr + 8) * OTS + qcol] =
                    make_float2(pacc[s][nt][2] * i0[nt], pacc[s][nt][3] * i1[nt]);
            }
        }
    }
    __syncthreads();
    if (bidx == 0) {
        float i0[8], i1[8];
#pragma unroll
        for (int nt = 0; nt < 8; nt++) {
            i0[nt] = 1.f / l0s[nt * 8 + fc2];
            i1[nt] = 1.f / l0s[nt * 8 + fc2 + 1];
        }
#pragma unroll
        for (int s = 0; s < 2; s++) {
            int dbase = ws * 16 + s * 64;
#pragma unroll
            for (int nt = 0; nt < 8; nt++) {
                int qcol = nt * 8 + fc2;
                int d = dbase + fr;
                float2 t0 = *(float2*)&Ot[d * OTS + qcol];
                float2 t1 = *(float2*)&Ot[(d + 8) * OTS + qcol];
                Of[qcol * OFS + d]           = pacc[s][nt][0] * i0[nt] - dw * t0.x;
                Of[(qcol + 1) * OFS + d]     = pacc[s][nt][1] * i1[nt] - dw * t0.y;
                Of[qcol * OFS + d + 8]       = pacc[s][nt][2] * i0[nt] - dw * t1.x;
                Of[(qcol + 1) * OFS + d + 8] = pacc[s][nt][3] * i1[nt] - dw * t1.y;
            }
        }
    }
    __syncthreads();

    float* og = o + (rowbase + q0) * EDIM + hd * 128;
#pragma unroll
    for (int i = 0; i < 8; i++) {
        int f = tid + i * 256;
        int r = f >> 5, c4 = f & 31;
        *(float4*)(og + (size_t)r * EDIM + c4 * 4) = *(const float4*)&Of[r * OFS + c4 * 4];
    }
}

// ======================================================================
// RMSNorm over 1024-wide rows, fused split-bf16 output
// ======================================================================
__global__ void __launch_bounds__(256) rmsnorm_split_kernel(
    const float* __restrict__ x, const float* __restrict__ w,
    __nv_bfloat16* __restrict__ yhi, __nv_bfloat16* __restrict__ ylo)
{
    __shared__ float red[8];
    __shared__ float rtot;
    const int tid = threadIdx.x;
    const int row = blockIdx.x;
    const float* xr = x + (size_t)row * EDIM;

    float v[4];
    float s = 0.f;
#pragma unroll
    for (int j = 0; j < 4; j++) {
        v[j] = xr[tid + j * 256];
        s = fmaf(v[j], v[j], s);
    }
#pragma unroll
    for (int off = 16; off > 0; off >>= 1)
        s += __shfl_xor_sync(0xffffffffu, s, off);
    if ((tid & 31) == 0) red[tid >> 5] = s;
    __syncthreads();
    if (tid == 0) {
        float t = 0.f;
#pragma unroll
        for (int i = 0; i < 8; i++) t += red[i];
        rtot = rsqrtf(t * (1.0f / 1024.0f) + 1.1920929e-07f);
    }
    __syncthreads();
    float r = rtot;
#pragma unroll
    for (int j = 0; j < 4; j++) {
        int c = tid + j * 256;
        float f = v[j] * r * w[c];
        __nv_bfloat16 h = __float2bfloat16_rn(f);
        __nv_bfloat16 l = __float2bfloat16_rn(f - __bfloat162float(h));
        yhi[(size_t)row * EDIM + c] = h;
        ylo[(size_t)row * EDIM + c] = l;
    }
}

// ======================================================================
// launcher
// ======================================================================
extern "C" void kernel_launch(void* const* d_in, const int* in_sizes, int n_in,
                              void* d_out, int out_size)
{
    const float* x  = (const float*)d_in[0];
    const float* Wq = (const float*)d_in[1];
    const float* Wk = (const float*)d_in[2];
    const float* Wv = (const float*)d_in[3];
    const float* nw = (const float*)d_in[4];
    const float* Wo = (const float*)d_in[5];
    const float* bo = (const float*)d_in[6];
    const float* dw = (const float*)d_in[7];
    float* out = (float*)d_out;

    float* op;
    cudaGetSymbolAddress((void**)&op, g_o);
    __nv_bfloat16 *xh, *xl, *nh, *nl;
    cudaGetSymbolAddress((void**)&xh, g_xhi);
    cudaGetSymbolAddress((void**)&xl, g_xlo);
    cudaGetSymbolAddress((void**)&nh, g_nhi);
    cudaGetSymbolAddress((void**)&nl, g_nlo);
    __nv_bfloat16 *qh, *ql, *kh, *kl, *vh, *vl;
    cudaGetSymbolAddress((void**)&qh, g_qh);
    cudaGetSymbolAddress((void**)&ql, g_ql);
    cudaGetSymbolAddress((void**)&kh, g_kh);
    cudaGetSymbolAddress((void**)&kl, g_kl);
    cudaGetSymbolAddress((void**)&vh, g_vh);
    cudaGetSymbolAddress((void**)&vl, g_vl);
    __nv_bfloat16 *wqh, *wql, *wkh, *wkl, *wvh, *wvl, *woh, *wol;
    cudaGetSymbolAddress((void**)&wqh, g_wqhi);
    cudaGetSymbolAddress((void**)&wql, g_wqlo);
    cudaGetSymbolAddress((void**)&wkh, g_wkhi);
    cudaGetSymbolAddress((void**)&wkl, g_wklo);
    cudaGetSymbolAddress((void**)&wvh, g_wvhi);
    cudaGetSymbolAddress((void**)&wvl, g_wvlo);
    cudaGetSymbolAddress((void**)&woh, g_wohi);
    cudaGetSymbolAddress((void**)&wol, g_wolo);

    cudaFuncSetAttribute(diff_attn_mma_kernel,
                         cudaFuncAttributeMaxDynamicSharedMemorySize, ATT_SMEM_BYTES);

    // split conversions
    const int xn4 = MROWS * EDIM / 4;
    const int wn4 = EDIM * EDIM / 4;
    split_bf16_kernel<<<xn4 / 256, 256>>>(x,  xh, xl, xn4);
    split_bf16_kernel<<<wn4 / 256, 256>>>(Wq, wqh, wql, wn4);
    split_bf16_kernel<<<wn4 / 256, 256>>>(Wk, wkh, wkl, wn4);
    split_bf16_kernel<<<wn4 / 256, 256>>>(Wv, wvh, wvl, wn4);
    split_bf16_kernel<<<wn4 / 256, 256>>>(Wo, woh, wol, wn4);

    // projections (HMMA split-bf16, direct bf16 hi/lo output)
    dim3 gg(EDIM / 128, MROWS / 128);
    mma_gemm_kernel<<<gg, 256>>>(xh, xl, wqh, wql, nullptr, qh, ql, MROWS, EDIM, EDIM, nullptr, nullptr);
    mma_gemm_kernel<<<gg, 256>>>(xh, xl, wkh, wkl, nullptr, kh, kl, MROWS, EDIM, EDIM, nullptr, nullptr);
    mma_gemm_kernel<<<gg, 256>>>(xh, xl, wvh, wvl, nullptr, vh, vl, MROWS, EDIM, EDIM, nullptr, nullptr);

    // attention (HMMA)
    dim3 ga(SLEN / BQ, NHEAD, 2);
    diff_attn_mma_kernel<<<ga, 256, ATT_SMEM_BYTES>>>(qh, ql, kh, kl, vh, vl, op, dw);

    // rmsnorm + split
    rmsnorm_split_kernel<<<MROWS, 256>>>(op, nw, nh, nl);

    // output projection with bias + (1-dw) scale
    mma_gemm_kernel<<<gg, 256>>>(nh, nl, woh, wol, out, nullptr, nullptr, MROWS, EDIM, EDIM, bo, dw);
}

// round 9
// speedup vs baseline: 2.1467x; 1.1467x over previous
#include <cuda_runtime.h>
#include <cuda_bf16.h>
#include <cstdint>
#include <cstddef>
#include <math.h>

#define MROWS 4096           // B*S
#define EDIM  1024
#define SLEN  2048
#define NHEAD 8

// ---------------- warp-level bf16 MMA (m16n8k16, fp32 accum) ----------------
__device__ __forceinline__ void mma16816(
    float* c, const unsigned* a, const unsigned* b)
{
    asm volatile(
        "mma.sync.aligned.m16n8k16.row.col.f32.bf16.bf16.f32 "
        "{%0,%1,%2,%3}, {%4,%5,%6,%7}, {%8,%9}, {%0,%1,%2,%3};"
        : "+f"(c[0]), "+f"(c[1]), "+f"(c[2]), "+f"(c[3])
        : "r"(a[0]), "r"(a[1]), "r"(a[2]), "r"(a[3]), "r"(b[0]), "r"(b[1]));
}
__device__ __forceinline__ void ldsm4(unsigned* r, unsigned addr) {
    asm volatile("ldmatrix.sync.aligned.m8n8.x4.shared.b16 {%0,%1,%2,%3}, [%4];"
        : "=r"(r[0]), "=r"(r[1]), "=r"(r[2]), "=r"(r[3]) : "r"(addr));
}
__device__ __forceinline__ void ldsm4t(unsigned* r, unsigned addr) {
    asm volatile("ldmatrix.sync.aligned.m8n8.x4.trans.shared.b16 {%0,%1,%2,%3}, [%4];"
        : "=r"(r[0]), "=r"(r[1]), "=r"(r[2]), "=r"(r[3]) : "r"(addr));
}
__device__ __forceinline__ unsigned smem_to_u32(const void* p) {
    unsigned a;
    asm("{ .reg .u64 t; cvta.to.shared.u64 t, %1; cvt.u32.u64 %0, t; }" : "=r"(a) : "l"(p));
    return a;
}
#define CP_ASYNC16(dst_u32, src) \
    asm volatile("cp.async.cg.shared.global [%0], [%1], 16;" :: "r"(dst_u32), "l"(src))
#define CP_COMMIT() asm volatile("cp.async.commit_group;" ::: "memory")
#define CP_WAIT0()  asm volatile("cp.async.wait_group 0;" ::: "memory")

// ---------------- scratch (device globals: allocation-free) ----------------
__device__ float g_o[(size_t)MROWS * EDIM];
__device__ __nv_bfloat16 g_xhi[(size_t)MROWS * EDIM];
__device__ __nv_bfloat16 g_xlo[(size_t)MROWS * EDIM];
__device__ __nv_bfloat16 g_nhi[(size_t)MROWS * EDIM];
__device__ __nv_bfloat16 g_nlo[(size_t)MROWS * EDIM];
__device__ __nv_bfloat16 g_qh[(size_t)MROWS * EDIM];
__device__ __nv_bfloat16 g_ql[(size_t)MROWS * EDIM];
__device__ __nv_bfloat16 g_kh[(size_t)MROWS * EDIM];
__device__ __nv_bfloat16 g_kl[(size_t)MROWS * EDIM];
__device__ __nv_bfloat16 g_vh[(size_t)MROWS * EDIM];
__device__ __nv_bfloat16 g_vl[(size_t)MROWS * EDIM];
__device__ __nv_bfloat16 g_wqhi[(size_t)EDIM * EDIM];
__device__ __nv_bfloat16 g_wqlo[(size_t)EDIM * EDIM];
__device__ __nv_bfloat16 g_wkhi[(size_t)EDIM * EDIM];
__device__ __nv_bfloat16 g_wklo[(size_t)EDIM * EDIM];
__device__ __nv_bfloat16 g_wvhi[(size_t)EDIM * EDIM];
__device__ __nv_bfloat16 g_wvlo[(size_t)EDIM * EDIM];
__device__ __nv_bfloat16 g_wohi[(size_t)EDIM * EDIM];
__device__ __nv_bfloat16 g_wolo[(size_t)EDIM * EDIM];

// ======================================================================
// fp32 -> (bf16 hi, bf16 lo) split, vectorized float4
// ======================================================================
__global__ void __launch_bounds__(256) split_bf16_kernel(
    const float* __restrict__ x, __nv_bfloat16* __restrict__ hi,
    __nv_bfloat16* __restrict__ lo, int n4)
{
    int i = blockIdx.x * 256 + threadIdx.x;
    if (i >= n4) return;
    float4 v = ((const float4*)x)[i];
    float vv[4] = { v.x, v.y, v.z, v.w };
    __nv_bfloat16 h[4], l[4];
#pragma unroll
    for (int j = 0; j < 4; j++) {
        h[j] = __float2bfloat16_rn(vv[j]);
        l[j] = __float2bfloat16_rn(vv[j] - __bfloat162float(h[j]));
    }
    __nv_bfloat162* hp = (__nv_bfloat162*)hi;
    __nv_bfloat162* lp = (__nv_bfloat162*)lo;
    hp[i * 2 + 0] = __nv_bfloat162(h[0], h[1]);
    hp[i * 2 + 1] = __nv_bfloat162(h[2], h[3]);
    lp[i * 2 + 0] = __nv_bfloat162(l[0], l[1]);
    lp[i * 2 + 1] = __nv_bfloat162(l[2], l[3]);
}

// ======================================================================
// HMMA split-bf16 GEMM: C = A[M,K] @ B[N,K]^T
// cp.async double-buffered BK=16, ldmatrix fragment loads.
// Output either fp32 (bias + (1-dw) scale) or bf16 hi/lo pair.
// ======================================================================
#define TS 24   // smem row stride in bf16 (48B) -> conflict-free ldmatrix

__global__ void __launch_bounds__(256) mma_gemm_kernel(
    const __nv_bfloat16* __restrict__ Ahi, const __nv_bfloat16* __restrict__ Alo,
    const __nv_bfloat16* __restrict__ Bhi, const __nv_bfloat16* __restrict__ Blo,
    float* __restrict__ Cf, __nv_bfloat16* __restrict__ Chi, __nv_bfloat16* __restrict__ Clo,
    int M, int N, int K,
    const float* __restrict__ bias, const float* __restrict__ dwp)
{
    __shared__ __nv_bfloat16 sA[2][2][128 * TS];   // [buf][hi/lo]
    __shared__ __nv_bfloat16 sB[2][2][128 * TS];

    const int tid = threadIdx.x;
    const int wid = tid >> 5, L = tid & 31;
    const int bm = blockIdx.y * 128, bn = blockIdx.x * 128;
    const int wm = (wid >> 2) * 64, wn = (wid & 3) * 32;

    const int lrow = tid >> 1;            // 0..127
    const int lseg = (tid & 1) * 8;       // 0 or 8 (bf16)

    const int fr = L >> 2;                // 0..7
    const int fc = (L & 3) * 2;           // 0,2,4,6
    const int lm = L >> 3, lr = L & 7;
    // ldmatrix per-lane offsets (bytes), row stride 48B
    const unsigned offA = (unsigned)((lr + ((lm & 1) << 3)) * 48 + ((lm >> 1) << 4));
    const unsigned offB = (unsigned)((lr + ((lm >> 1) << 3)) * 48 + ((lm & 1) << 4));

    float acc[4][4][4];
#pragma unroll
    for (int mt = 0; mt < 4; mt++)
#pragma unroll
        for (int nt = 0; nt < 4; nt++)
#pragma unroll
            for (int e = 0; e < 4; e++) acc[mt][nt][e] = 0.f;

    const int nchunks = K / 16;

    // issue chunk 0 into buf 0
    {
        unsigned d0 = smem_to_u32(&sA[0][0][lrow * TS + lseg]);
        unsigned d1 = smem_to_u32(&sA[0][1][lrow * TS + lseg]);
        unsigned d2 = smem_to_u32(&sB[0][0][lrow * TS + lseg]);
        unsigned d3 = smem_to_u32(&sB[0][1][lrow * TS + lseg]);
        CP_ASYNC16(d0, Ahi + (size_t)(bm + lrow) * K + lseg);
        CP_ASYNC16(d1, Alo + (size_t)(bm + lrow) * K + lseg);
        CP_ASYNC16(d2, Bhi + (size_t)(bn + lrow) * K + lseg);
        CP_ASYNC16(d3, Blo + (size_t)(bn + lrow) * K + lseg);
        CP_COMMIT();
    }

    for (int c = 0; c < nchunks; c++) {
        CP_WAIT0();
        __syncthreads();
        const int buf = c & 1;
        if (c + 1 < nchunks) {
            const int nb = (c + 1) & 1;
            const int kc = (c + 1) * 16;
            unsigned d0 = smem_to_u32(&sA[nb][0][lrow * TS + lseg]);
            unsigned d1 = smem_to_u32(&sA[nb][1][lrow * TS + lseg]);
            unsigned d2 = smem_to_u32(&sB[nb][0][lrow * TS + lseg]);
            unsigned d3 = smem_to_u32(&sB[nb][1][lrow * TS + lseg]);
            CP_ASYNC16(d0, Ahi + (size_t)(bm + lrow) * K + kc + lseg);
            CP_ASYNC16(d1, Alo + (size_t)(bm + lrow) * K + kc + lseg);
            CP_ASYNC16(d2, Bhi + (size_t)(bn + lrow) * K + kc + lseg);
            CP_ASYNC16(d3, Blo + (size_t)(bn + lrow) * K + kc + lseg);
            CP_COMMIT();
        }

        // B fragments (4 n-tiles = 2 x4 loads per hi/lo)
        unsigned bh[4][2], bl[4][2];
#pragma unroll
        for (int ntp = 0; ntp < 2; ntp++) {
            unsigned t[4];
            ldsm4(t, smem_to_u32(&sB[buf][0][(wn + ntp * 16) * TS]) + offB);
            bh[2 * ntp][0] = t[0]; bh[2 * ntp][1] = t[1];
            bh[2 * ntp + 1][0] = t[2]; bh[2 * ntp + 1][1] = t[3];
            ldsm4(t, smem_to_u32(&sB[buf][1][(wn + ntp * 16) * TS]) + offB);
            bl[2 * ntp][0] = t[0]; bl[2 * ntp][1] = t[1];
            bl[2 * ntp + 1][0] = t[2]; bl[2 * ntp + 1][1] = t[3];
        }
#pragma unroll
        for (int mt = 0; mt < 4; mt++) {
            unsigned ah[4], al[4];
            ldsm4(ah, smem_to_u32(&sA[buf][0][(wm + mt * 16) * TS]) + offA);
            ldsm4(al, smem_to_u32(&sA[buf][1][(wm + mt * 16) * TS]) + offA);
#pragma unroll
            for (int nt = 0; nt < 4; nt++) {
                mma16816(acc[mt][nt], ah, bh[nt]);
                mma16816(acc[mt][nt], ah, bl[nt]);
                mma16816(acc[mt][nt], al, bh[nt]);
            }
        }
    }

    if (Cf) {
        float sc = 1.0f;
        if (dwp) sc = 1.0f - *dwp;
#pragma unroll
        for (int mt = 0; mt < 4; mt++) {
#pragma unroll
            for (int nt = 0; nt < 4; nt++) {
                int row = bm + wm + mt * 16 + fr;
                int col = bn + wn + nt * 8 + fc;
                float b0 = 0.f, b1 = 0.f;
                if (bias) { b0 = bias[col]; b1 = bias[col + 1]; }
                float2 r0, r1;
                r0.x = (acc[mt][nt][0] + b0) * sc;
                r0.y = (acc[mt][nt][1] + b1) * sc;
                r1.x = (acc[mt][nt][2] + b0) * sc;
                r1.y = (acc[mt][nt][3] + b1) * sc;
                *(float2*)(Cf + (size_t)row * N + col) = r0;
                *(float2*)(Cf + (size_t)(row + 8) * N + col) = r1;
            }
        }
    } else {
#pragma unroll
        for (int mt = 0; mt < 4; mt++) {
#pragma unroll
            for (int nt = 0; nt < 4; nt++) {
                int row = bm + wm + mt * 16 + fr;
                int col = bn + wn + nt * 8 + fc;
#pragma unroll
                for (int half = 0; half < 2; half++) {
                    float v0 = acc[mt][nt][half * 2 + 0];
                    float v1 = acc[mt][nt][half * 2 + 1];
                    __nv_bfloat16 h0 = __float2bfloat16_rn(v0);
                    __nv_bfloat16 h1 = __float2bfloat16_rn(v1);
                    __nv_bfloat16 l0 = __float2bfloat16_rn(v0 - __bfloat162float(h0));
                    __nv_bfloat16 l1 = __float2bfloat16_rn(v1 - __bfloat162float(h1));
                    size_t off = (size_t)(row + half * 8) * N + col;
                    *(__nv_bfloat162*)(Chi + off) = __nv_bfloat162(h0, h1);
                    *(__nv_bfloat162*)(Clo + off) = __nv_bfloat162(l0, l1);
                }
            }
        }
    }
}

// ======================================================================
// HMMA differential flash attention (ldmatrix fragments, V via ldmatrix.trans)
// CTA: (b, h, 64-q tile), 8 warps. Warps 0-3: branch0, 4-7: branch1.
// QK: warp ws computes 16x64 score strip. PV: O[q][d] natural orientation.
// ======================================================================
#define BQ 64
#define BKT 64
#define QB  272   // byte stride for Q/K/V bf16 tiles (136 bf16)
#define PB  144   // byte stride for P bf16 tiles (72 bf16)
#define SSR 68    // fp32 stride for score tiles
#define OSR 132   // fp32 stride for O staging

#define OFF_QHI  0
#define OFF_QLO  17408
#define OFF_KHI  34816
#define OFF_KLO  52224
#define OFF_VHI  69632
#define OFF_VLO  87040
#define OFF_S0   104448
#define OFF_S1   121856
#define OFF_PHI0 139264
#define OFF_PLO0 148480
#define OFF_PHI1 157696
#define OFF_PLO1 166912
#define OFF_STAT 176128
#define ATT_SMEM_BYTES (OFF_STAT + 6 * 64 * 4)   // 177664

__global__ void __launch_bounds__(256) diff_attn_mma_kernel(
    const __nv_bfloat16* __restrict__ qh_g, const __nv_bfloat16* __restrict__ ql_g,
    const __nv_bfloat16* __restrict__ kh_g, const __nv_bfloat16* __restrict__ kl_g,
    const __nv_bfloat16* __restrict__ vh_g, const __nv_bfloat16* __restrict__ vl_g,
    float* __restrict__ o, const float* __restrict__ dwp)
{
    extern __shared__ char smem[];
    const unsigned su = smem_to_u32(smem);
    float* S0 = (float*)(smem + OFF_S0);
    float* S1 = (float*)(smem + OFF_S1);
    float* m0s = (float*)(smem + OFF_STAT);
    float* l0s = m0s + 64;
    float* m1s = l0s + 64;
    float* l1s = m1s + 64;
    float* c0s = l1s + 64;
    float* c1s = c0s + 64;
    float* Ot = (float*)(smem + OFF_KHI);   // branch1 staging (post-loop)
    float* Of = (float*)(smem + OFF_S0);    // final combine (post-loop)

    const int tid = threadIdx.x;
    const int wid = tid >> 5, L = tid & 31;
    const int fr = L >> 2;           // 0..7
    const int fc2 = (L & 3) * 2;     // 0,2,4,6
    const int lm = L >> 3, lr = L & 7;
    const int qt = blockIdx.x, hd = blockIdx.y, b = blockIdx.z;
    const int q0 = qt * BQ;
    const int bidx = wid >> 2;       // branch
    const int ws = wid & 3;          // warp slot -> q rows ms..ms+15
    const int ms = ws * 16;

    // ldmatrix per-lane byte offsets
    const unsigned offA272 = (unsigned)((lr + ((lm & 1) << 3)) * QB + ((lm >> 1) << 4)); // A-pattern & V-trans
    const unsigned offA144 = (unsigned)((lr + ((lm & 1) << 3)) * PB + ((lm >> 1) << 4)); // A-pattern on P
    const unsigned offB272 = (unsigned)((lr + ((lm >> 1) << 3)) * QB + ((lm & 1) << 4)); // B-pattern on K

    const size_t rowbase = (size_t)b * SLEN;

    // ---- load Q tile (hi/lo), 64 x 128 bf16 each ----
#pragma unroll
    for (int i = 0; i < 4; i++) {
        int f = tid + i * 256;               // 0..1023
        int r = f >> 4, c = f & 15;
        size_t src = (rowbase + q0 + r) * EDIM + hd * 128 + c * 8;
        *(uint4*)(smem + OFF_QHI + r * QB + c * 16) = *(const uint4*)(qh_g + src);
        *(uint4*)(smem + OFF_QLO + r * QB + c * 16) = *(const uint4*)(ql_g + src);
    }
    if (tid < BQ) {
        m0s[tid] = -1e30f; m1s[tid] = -1e30f;
        l0s[tid] = 0.f;    l1s[tid] = 0.f;
    }

    const int rrow = tid >> 2, rpart = tid & 3;   // softmax mapping

    float pacc[16][4];
#pragma unroll
    for (int nt = 0; nt < 16; nt++)
#pragma unroll
        for (int e = 0; e < 4; e++) pacc[nt][e] = 0.f;

    const float scale = 0.125f;

    for (int kt = 0; kt < SLEN; kt += BKT) {
        __syncthreads();
        // ---- load K and V tiles (hi/lo), vectorized ----
#pragma unroll
        for (int i = 0; i < 4; i++) {
            int f = tid + i * 256;
            int r = f >> 4, c = f & 15;
            size_t src = (rowbase + kt + r) * EDIM + hd * 128 + c * 8;
            *(uint4*)(smem + OFF_KHI + r * QB + c * 16) = *(const uint4*)(kh_g + src);
            *(uint4*)(smem + OFF_KLO + r * QB + c * 16) = *(const uint4*)(kl_g + src);
            *(uint4*)(smem + OFF_VHI + r * QB + c * 16) = *(const uint4*)(vh_g + src);
            *(uint4*)(smem + OFF_VLO + r * QB + c * 16) = *(const uint4*)(vl_g + src);
        }
        __syncthreads();

        // ---- QK^T: 16x64 strip per warp, 3-term split ----
        {
            float sacc[8][4];
#pragma unroll
            for (int nt = 0; nt < 8; nt++)
#pragma unroll
                for (int e = 0; e < 4; e++) sacc[nt][e] = 0.f;

#pragma unroll
            for (int ks = 0; ks < 4; ks++) {
                const unsigned kofb = (unsigned)(bidx * 128 + ks * 32);  // k offset bytes
                unsigned ah[4], al[4];
                ldsm4(ah, su + OFF_QHI + ms * QB + kofb + offA272);
                ldsm4(al, su + OFF_QLO + ms * QB + kofb + offA272);
#pragma unroll
                for (int ntp = 0; ntp < 4; ntp++) {
                    unsigned th[4], tl[4];
                    ldsm4(th, su + OFF_KHI + (ntp * 16) * QB + kofb + offB272);
                    ldsm4(tl, su + OFF_KLO + (ntp * 16) * QB + kofb + offB272);
                    mma16816(sacc[2 * ntp], ah, th);
                    mma16816(sacc[2 * ntp], ah, tl);
                    mma16816(sacc[2 * ntp], al, th);
                    mma16816(sacc[2 * ntp + 1], ah, th + 2);
                    mma16816(sacc[2 * ntp + 1], ah, tl + 2);
                    mma16816(sacc[2 * ntp + 1], al, th + 2);
                }
            }
            float* Sb = bidx ? S1 : S0;
#pragma unroll
            for (int nt = 0; nt < 8; nt++) {
                float2 r0 = make_float2(sacc[nt][0] * scale, sacc[nt][1] * scale);
                float2 r1 = make_float2(sacc[nt][2] * scale, sacc[nt][3] * scale);
                *(float2*)&Sb[(ms + fr) * SSR + nt * 8 + fc2] = r0;
                *(float2*)&Sb[(ms + fr + 8) * SSR + nt * 8 + fc2] = r1;
            }
        }
        __syncthreads();

        // ---- online softmax: 4 threads/row, 16 keys each; emit P hi/lo ----
        {
            const int base0 = rrow * SSR + rpart * 16;
            const int pbase = rrow * (PB / 2) + rpart * 16;
            // branch 0
            {
                float pv[16];
                float mloc = -1e30f;
#pragma unroll
                for (int jj = 0; jj < 16; jj++) { pv[jj] = S0[base0 + jj]; mloc = fmaxf(mloc, pv[jj]); }
                mloc = fmaxf(mloc, __shfl_xor_sync(0xffffffffu, mloc, 1));
                mloc = fmaxf(mloc, __shfl_xor_sync(0xffffffffu, mloc, 2));
                float mo = m0s[rrow];
                float mn = fmaxf(mo, mloc);
                float sum = 0.f;
#pragma unroll
                for (int jj = 0; jj < 16; jj++) {
                    pv[jj] = __expf(pv[jj] - mn);
                    sum += pv[jj];
                }
                __nv_bfloat16* Ph = (__nv_bfloat16*)(smem + OFF_PHI0);
                __nv_bfloat16* Pl = (__nv_bfloat16*)(smem + OFF_PLO0);
#pragma unroll
                for (int t = 0; t < 8; t++) {
                    float v0 = pv[2 * t], v1 = pv[2 * t + 1];
                    __nv_bfloat16 h0 = __float2bfloat16_rn(v0);
                    __nv_bfloat16 h1 = __float2bfloat16_rn(v1);
                    __nv_bfloat16 e0 = __float2bfloat16_rn(v0 - __bfloat162float(h0));
                    __nv_bfloat16 e1 = __float2bfloat16_rn(v1 - __bfloat162float(h1));
                    *(__nv_bfloat162*)&Ph[pbase + 2 * t] = __nv_bfloat162(h0, h1);
                    *(__nv_bfloat162*)&Pl[pbase + 2 * t] = __nv_bfloat162(e0, e1);
                }
                sum += __shfl_xor_sync(0xffffffffu, sum, 1);
                sum += __shfl_xor_sync(0xffffffffu, sum, 2);
                if (rpart == 0) {
                    float cc = __expf(mo - mn);
                    c0s[rrow] = cc;
                    l0s[rrow] = l0s[rrow] * cc + sum;
                    m0s[rrow] = mn;
                }
            }
            // branch 1
            {
                float pv[16];
                float mloc = -1e30f;
#pragma unroll
                for (int jj = 0; jj < 16; jj++) { pv[jj] = S1[base0 + jj]; mloc = fmaxf(mloc, pv[jj]); }
                mloc = fmaxf(mloc, __shfl_xor_sync(0xffffffffu, mloc, 1));
                mloc = fmaxf(mloc, __shfl_xor_sync(0xffffffffu, mloc, 2));
                float mo = m1s[rrow];
                float mn = fmaxf(mo, mloc);
                float sum = 0.f;
#pragma unroll
                for (int jj = 0; jj < 16; jj++) {
                    pv[jj] = __expf(pv[jj] - mn);
                    sum += pv[jj];
                }
                __nv_bfloat16* Ph = (__nv_bfloat16*)(smem + OFF_PHI1);
                __nv_bfloat16* Pl = (__nv_bfloat16*)(smem + OFF_PLO1);
#pragma unroll
                for (int t = 0; t < 8; t++) {
                    float v0 = pv[2 * t], v1 = pv[2 * t + 1];
                    __nv_bfloat16 h0 = __float2bfloat16_rn(v0);
                    __nv_bfloat16 h1 = __float2bfloat16_rn(v1);
                    __nv_bfloat16 e0 = __float2bfloat16_rn(v0 - __bfloat162float(h0));
                    __nv_bfloat16 e1 = __float2bfloat16_rn(v1 - __bfloat162float(h1));
                    *(__nv_bfloat162*)&Ph[pbase + 2 * t] = __nv_bfloat162(h0, h1);
                    *(__nv_bfloat162*)&Pl[pbase + 2 * t] = __nv_bfloat162(e0, e1);
                }
                sum += __shfl_xor_sync(0xffffffffu, sum, 1);
                sum += __shfl_xor_sync(0xffffffffu, sum, 2);
                if (rpart == 0) {
                    float cc = __expf(mo - mn);
                    c1s[rrow] = cc;
                    l1s[rrow] = l1s[rrow] * cc + sum;
                    m1s[rrow] = mn;
                }
            }
        }
        __syncthreads();

        // ---- PV: O[q][d] += P[q][k] * V[k][d] via ldmatrix.trans on V ----
        {
            const float* cs = bidx ? c1s : c0s;
            const unsigned phOff = bidx ? OFF_PHI1 : OFF_PHI0;
            const unsigned plOff = bidx ? OFF_PLO1 : OFF_PLO0;
            const float cc0 = cs[ms + fr], cc1 = cs[ms + fr + 8];
#pragma unroll
            for (int nt = 0; nt < 16; nt++) {
                pacc[nt][0] *= cc0; pacc[nt][1] *= cc0;
                pacc[nt][2] *= cc1; pacc[nt][3] *= cc1;
            }
#pragma unroll
            for (int ks = 0; ks < 4; ks++) {
                unsigned ph[4], pl[4];
                ldsm4(ph, su + phOff + ms * PB + ks * 32 + offA144);
                ldsm4(pl, su + plOff + ms * PB + ks * 32 + offA144);
#pragma unroll
                for (int dtp = 0; dtp < 8; dtp++) {
                    unsigned vh[4], vl[4];
                    ldsm4t(vh, su + OFF_VHI + (ks * 16) * QB + dtp * 32 + offA272);
                    ldsm4t(vl, su + OFF_VLO + (ks * 16) * QB + dtp * 32 + offA272);
                    mma16816(pacc[2 * dtp], ph, vh);
                    mma16816(pacc[2 * dtp], ph, vl);
                    mma16816(pacc[2 * dtp], pl, vh);
                    mma16816(pacc[2 * dtp + 1], ph, vh + 2);
                    mma16816(pacc[2 * dtp + 1], ph, vl + 2);
                    mma16816(pacc[2 * dtp + 1], pl, vh + 2);
                }
            }
        }
    }
    __syncthreads();

    // ---- epilogue: o = O0/l0 - dw * O1/l1 ----
    const float dw = *dwp;
    if (bidx == 1) {
        const float i0 = 1.f / l1s[ms + fr], i1 = 1.f / l1s[ms + fr + 8];
#pragma unroll
        for (int nt = 0; nt < 16; nt++) {
            int d = nt * 8 + fc2;
            *(float2*)&Ot[(ms + fr) * OSR + d] =
                make_float2(pacc[nt][0] * i0, pacc[nt][1] * i0);
            *(float2*)&Ot[(ms + fr + 8) * OSR + d] =
                make_float2(pacc[nt][2] * i1, pacc[nt][3] * i1);
        }
    }
    __syncthreads();
    if (bidx == 0) {
        const float i0 = 1.f / l0s[ms + fr], i1 = 1.f / l0s[ms + fr + 8];
#pragma unroll
        for (int nt = 0; nt < 16; nt++) {
            int d = nt * 8 + fc2;
            float2 t0 = *(float2*)&Ot[(ms + fr) * OSR + d];
            float2 t1 = *(float2*)&Ot[(ms + fr + 8) * OSR + d];
            *(float2*)&Of[(ms + fr) * OSR + d] =
                make_float2(pacc[nt][0] * i0 - dw * t0.x, pacc[nt][1] * i0 - dw * t0.y);
            *(float2*)&Of[(ms + fr + 8) * OSR + d] =
                make_float2(pacc[nt][2] * i1 - dw * t1.x, pacc[nt][3] * i1 - dw * t1.y);
        }
    }
    __syncthreads();

    float* og = o + (rowbase + q0) * EDIM + hd * 128;
#pragma unroll
    for (int i = 0; i < 8; i++) {
        int f = tid + i * 256;
        int r = f >> 5, c4 = f & 31;
        *(float4*)(og + (size_t)r * EDIM + c4 * 4) = *(const float4*)&Of[r * OSR + c4 * 4];
    }
}

// ======================================================================
// RMSNorm over 1024-wide rows, fused split-bf16 output
// ======================================================================
__global__ void __launch_bounds__(256) rmsnorm_split_kernel(
    const float* __restrict__ x, const float* __restrict__ w,
    __nv_bfloat16* __restrict__ yhi, __nv_bfloat16* __restrict__ ylo)
{
    __shared__ float red[8];
    __shared__ float rtot;
    const int tid = threadIdx.x;
    const int row = blockIdx.x;
    const float* xr = x + (size_t)row * EDIM;

    float v[4];
    float s = 0.f;
#pragma unroll
    for (int j = 0; j < 4; j++) {
        v[j] = xr[tid + j * 256];
        s = fmaf(v[j], v[j], s);
    }
#pragma unroll
    for (int off = 16; off > 0; off >>= 1)
        s += __shfl_xor_sync(0xffffffffu, s, off);
    if ((tid & 31) == 0) red[tid >> 5] = s;
    __syncthreads();
    if (tid == 0) {
        float t = 0.f;
#pragma unroll
        for (int i = 0; i < 8; i++) t += red[i];
        rtot = rsqrtf(t * (1.0f / 1024.0f) + 1.1920929e-07f);
    }
    __syncthreads();
    float r = rtot;
#pragma unroll
    for (int j = 0; j < 4; j++) {
        int c = tid + j * 256;
        float f = v[j] * r * w[c];
        __nv_bfloat16 h = __float2bfloat16_rn(f);
        __nv_bfloat16 l = __float2bfloat16_rn(f - __bfloat162float(h));
        yhi[(size_t)row * EDIM + c] = h;
        ylo[(size_t)row * EDIM + c] = l;
    }
}

// ======================================================================
// launcher
// ======================================================================
extern "C" void kernel_launch(void* const* d_in, const int* in_sizes, int n_in,
                              void* d_out, int out_size)
{
    const float* x  = (const float*)d_in[0];
    const float* Wq = (const float*)d_in[1];
    const float* Wk = (const float*)d_in[2];
    const float* Wv = (const float*)d_in[3];
    const float* nw = (const float*)d_in[4];
    const float* Wo = (const float*)d_in[5];
    const float* bo = (const float*)d_in[6];
    const float* dw = (const float*)d_in[7];
    float* out = (float*)d_out;

    float* op;
    cudaGetSymbolAddress((void**)&op, g_o);
    __nv_bfloat16 *xh, *xl, *nh, *nl;
    cudaGetSymbolAddress((void**)&xh, g_xhi);
    cudaGetSymbolAddress((void**)&xl, g_xlo);
    cudaGetSymbolAddress((void**)&nh, g_nhi);
    cudaGetSymbolAddress((void**)&nl, g_nlo);
    __nv_bfloat16 *qh, *ql, *kh, *kl, *vh, *vl;
    cudaGetSymbolAddress((void**)&qh, g_qh);
    cudaGetSymbolAddress((void**)&ql, g_ql);
    cudaGetSymbolAddress((void**)&kh, g_kh);
    cudaGetSymbolAddress((void**)&kl, g_kl);
    cudaGetSymbolAddress((void**)&vh, g_vh);
    cudaGetSymbolAddress((void**)&vl, g_vl);
    __nv_bfloat16 *wqh, *wql, *wkh, *wkl, *wvh, *wvl, *woh, *wol;
    cudaGetSymbolAddress((void**)&wqh, g_wqhi);
    cudaGetSymbolAddress((void**)&wql, g_wqlo);
    cudaGetSymbolAddress((void**)&wkh, g_wkhi);
    cudaGetSymbolAddress((void**)&wkl, g_wklo);
    cudaGetSymbolAddress((void**)&wvh, g_wvhi);
    cudaGetSymbolAddress((void**)&wvl, g_wvlo);
    cudaGetSymbolAddress((void**)&woh, g_wohi);
    cudaGetSymbolAddress((void**)&wol, g_wolo);

    cudaFuncSetAttribute(diff_attn_mma_kernel,
                         cudaFuncAttributeMaxDynamicSharedMemorySize, ATT_SMEM_BYTES);

    // split conversions
    const int xn4 = MROWS * EDIM / 4;
    const int wn4 = EDIM * EDIM / 4;
    split_bf16_kernel<<<xn4 / 256, 256>>>(x,  xh, xl, xn4);
    split_bf16_kernel<<<wn4 / 256, 256>>>(Wq, wqh, wql, wn4);
    split_bf16_kernel<<<wn4 / 256, 256>>>(Wk, wkh, wkl, wn4);
    split_bf16_kernel<<<wn4 / 256, 256>>>(Wv, wvh, wvl, wn4);
    split_bf16_kernel<<<wn4 / 256, 256>>>(Wo, woh, wol, wn4);

    // projections (HMMA split-bf16, direct bf16 hi/lo output)
    dim3 gg(EDIM / 128, MROWS / 128);
    mma_gemm_kernel<<<gg, 256>>>(xh, xl, wqh, wql, nullptr, qh, ql, MROWS, EDIM, EDIM, nullptr, nullptr);
    mma_gemm_kernel<<<gg, 256>>>(xh, xl, wkh, wkl, nullptr, kh, kl, MROWS, EDIM, EDIM, nullptr, nullptr);
    mma_gemm_kernel<<<gg, 256>>>(xh, xl, wvh, wvl, nullptr, vh, vl, MROWS, EDIM, EDIM, nullptr, nullptr);

    // attention (HMMA + ldmatrix)
    dim3 ga(SLEN / BQ, NHEAD, 2);
    diff_attn_mma_kernel<<<ga, 256, ATT_SMEM_BYTES>>>(qh, ql, kh, kl, vh, vl, op, dw);

    // rmsnorm + split
    rmsnorm_split_kernel<<<MROWS, 256>>>(op, nw, nh, nl);

    // output projection with bias + (1-dw) scale
    mma_gemm_kernel<<<gg, 256>>>(nh, nl, woh, wol, out, nullptr, nullptr, MROWS, EDIM, EDIM, bo, dw);
}

// round 10
// speedup vs baseline: 2.4550x; 1.1436x over previous
#include <cuda_runtime.h>
#include <cuda_bf16.h>
#include <cstdint>
#include <cstddef>
#include <math.h>

#define MROWS 4096           // B*S
#define EDIM  1024
#define SLEN  2048
#define NHEAD 8

// ---------------- warp-level bf16 MMA (m16n8k16, fp32 accum) ----------------
__device__ __forceinline__ void mma16816(
    float* c, const unsigned* a, const unsigned* b)
{
    asm volatile(
        "mma.sync.aligned.m16n8k16.row.col.f32.bf16.bf16.f32 "
        "{%0,%1,%2,%3}, {%4,%5,%6,%7}, {%8,%9}, {%0,%1,%2,%3};"
        : "+f"(c[0]), "+f"(c[1]), "+f"(c[2]), "+f"(c[3])
        : "r"(a[0]), "r"(a[1]), "r"(a[2]), "r"(a[3]), "r"(b[0]), "r"(b[1]));
}
__device__ __forceinline__ void ldsm4(unsigned* r, unsigned addr) {
    asm volatile("ldmatrix.sync.aligned.m8n8.x4.shared.b16 {%0,%1,%2,%3}, [%4];"
        : "=r"(r[0]), "=r"(r[1]), "=r"(r[2]), "=r"(r[3]) : "r"(addr));
}
__device__ __forceinline__ void ldsm4t(unsigned* r, unsigned addr) {
    asm volatile("ldmatrix.sync.aligned.m8n8.x4.trans.shared.b16 {%0,%1,%2,%3}, [%4];"
        : "=r"(r[0]), "=r"(r[1]), "=r"(r[2]), "=r"(r[3]) : "r"(addr));
}
__device__ __forceinline__ unsigned smem_to_u32(const void* p) {
    unsigned a;
    asm("{ .reg .u64 t; cvta.to.shared.u64 t, %1; cvt.u32.u64 %0, t; }" : "=r"(a) : "l"(p));
    return a;
}
// pack two fp32 into bf16x2: low half = lo, high half = hi
__device__ __forceinline__ unsigned cvt2(float hi, float lo) {
    unsigned r; asm("cvt.rn.bf16x2.f32 %0, %1, %2;" : "=r"(r) : "f"(hi), "f"(lo));
    return r;
}
#define CP_ASYNC16(dst_u32, src) \
    asm volatile("cp.async.cg.shared.global [%0], [%1], 16;" :: "r"(dst_u32), "l"(src))
#define CP_COMMIT() asm volatile("cp.async.commit_group;" ::: "memory")
#define CP_WAIT0()  asm volatile("cp.async.wait_group 0;" ::: "memory")

// ---------------- scratch (device globals: allocation-free) ----------------
__device__ float g_o[(size_t)MROWS * EDIM];
__device__ __nv_bfloat16 g_xhi[(size_t)MROWS * EDIM];
__device__ __nv_bfloat16 g_xlo[(size_t)MROWS * EDIM];
__device__ __nv_bfloat16 g_nhi[(size_t)MROWS * EDIM];
__device__ __nv_bfloat16 g_nlo[(size_t)MROWS * EDIM];
__device__ __nv_bfloat16 g_qh[(size_t)MROWS * EDIM];
__device__ __nv_bfloat16 g_ql[(size_t)MROWS * EDIM];
__device__ __nv_bfloat16 g_kh[(size_t)MROWS * EDIM];
__device__ __nv_bfloat16 g_kl[(size_t)MROWS * EDIM];
__device__ __nv_bfloat16 g_vh[(size_t)MROWS * EDIM];
__device__ __nv_bfloat16 g_vl[(size_t)MROWS * EDIM];
__device__ __nv_bfloat16 g_wqhi[(size_t)EDIM * EDIM];
__device__ __nv_bfloat16 g_wqlo[(size_t)EDIM * EDIM];
__device__ __nv_bfloat16 g_wkhi[(size_t)EDIM * EDIM];
__device__ __nv_bfloat16 g_wklo[(size_t)EDIM * EDIM];
__device__ __nv_bfloat16 g_wvhi[(size_t)EDIM * EDIM];
__device__ __nv_bfloat16 g_wvlo[(size_t)EDIM * EDIM];
__device__ __nv_bfloat16 g_wohi[(size_t)EDIM * EDIM];
__device__ __nv_bfloat16 g_wolo[(size_t)EDIM * EDIM];

// ======================================================================
// fp32 -> (bf16 hi, bf16 lo) split, vectorized float4
// ======================================================================
__global__ void __launch_bounds__(256) split_bf16_kernel(
    const float* __restrict__ x, __nv_bfloat16* __restrict__ hi,
    __nv_bfloat16* __restrict__ lo, int n4)
{
    int i = blockIdx.x * 256 + threadIdx.x;
    if (i >= n4) return;
    float4 v = ((const float4*)x)[i];
    float vv[4] = { v.x, v.y, v.z, v.w };
    __nv_bfloat16 h[4], l[4];
#pragma unroll
    for (int j = 0; j < 4; j++) {
        h[j] = __float2bfloat16_rn(vv[j]);
        l[j] = __float2bfloat16_rn(vv[j] - __bfloat162float(h[j]));
    }
    __nv_bfloat162* hp = (__nv_bfloat162*)hi;
    __nv_bfloat162* lp = (__nv_bfloat162*)lo;
    hp[i * 2 + 0] = __nv_bfloat162(h[0], h[1]);
    hp[i * 2 + 1] = __nv_bfloat162(h[2], h[3]);
    lp[i * 2 + 0] = __nv_bfloat162(l[0], l[1]);
    lp[i * 2 + 1] = __nv_bfloat162(l[2], l[3]);
}

// ======================================================================
// HMMA split-bf16 GEMM: C = A[M,K] @ B[N,K]^T
// cp.async double-buffered BK=16, ldmatrix fragment loads.
// ======================================================================
#define TS 24   // smem row stride in bf16 (48B) -> conflict-free ldmatrix

__global__ void __launch_bounds__(256) mma_gemm_kernel(
    const __nv_bfloat16* __restrict__ Ahi, const __nv_bfloat16* __restrict__ Alo,
    const __nv_bfloat16* __restrict__ Bhi, const __nv_bfloat16* __restrict__ Blo,
    float* __restrict__ Cf, __nv_bfloat16* __restrict__ Chi, __nv_bfloat16* __restrict__ Clo,
    int M, int N, int K,
    const float* __restrict__ bias, const float* __restrict__ dwp)
{
    __shared__ __nv_bfloat16 sA[2][2][128 * TS];   // [buf][hi/lo]
    __shared__ __nv_bfloat16 sB[2][2][128 * TS];

    const int tid = threadIdx.x;
    const int wid = tid >> 5, L = tid & 31;
    const int bm = blockIdx.y * 128, bn = blockIdx.x * 128;
    const int wm = (wid >> 2) * 64, wn = (wid & 3) * 32;

    const int lrow = tid >> 1;            // 0..127
    const int lseg = (tid & 1) * 8;       // 0 or 8 (bf16)

    const int fr = L >> 2;                // 0..7
    const int fc = (L & 3) * 2;           // 0,2,4,6
    const int lm = L >> 3, lr = L & 7;
    const unsigned offA = (unsigned)((lr + ((lm & 1) << 3)) * 48 + ((lm >> 1) << 4));
    const unsigned offB = (unsigned)((lr + ((lm >> 1) << 3)) * 48 + ((lm & 1) << 4));

    float acc[4][4][4];
#pragma unroll
    for (int mt = 0; mt < 4; mt++)
#pragma unroll
        for (int nt = 0; nt < 4; nt++)
#pragma unroll
            for (int e = 0; e < 4; e++) acc[mt][nt][e] = 0.f;

    const int nchunks = K / 16;

    {
        unsigned d0 = smem_to_u32(&sA[0][0][lrow * TS + lseg]);
        unsigned d1 = smem_to_u32(&sA[0][1][lrow * TS + lseg]);
        unsigned d2 = smem_to_u32(&sB[0][0][lrow * TS + lseg]);
        unsigned d3 = smem_to_u32(&sB[0][1][lrow * TS + lseg]);
        CP_ASYNC16(d0, Ahi + (size_t)(bm + lrow) * K + lseg);
        CP_ASYNC16(d1, Alo + (size_t)(bm + lrow) * K + lseg);
        CP_ASYNC16(d2, Bhi + (size_t)(bn + lrow) * K + lseg);
        CP_ASYNC16(d3, Blo + (size_t)(bn + lrow) * K + lseg);
        CP_COMMIT();
    }

    for (int c = 0; c < nchunks; c++) {
        CP_WAIT0();
        __syncthreads();
        const int buf = c & 1;
        if (c + 1 < nchunks) {
            const int nb = (c + 1) & 1;
            const int kc = (c + 1) * 16;
            unsigned d0 = smem_to_u32(&sA[nb][0][lrow * TS + lseg]);
            unsigned d1 = smem_to_u32(&sA[nb][1][lrow * TS + lseg]);
            unsigned d2 = smem_to_u32(&sB[nb][0][lrow * TS + lseg]);
            unsigned d3 = smem_to_u32(&sB[nb][1][lrow * TS + lseg]);
            CP_ASYNC16(d0, Ahi + (size_t)(bm + lrow) * K + kc + lseg);
            CP_ASYNC16(d1, Alo + (size_t)(bm + lrow) * K + kc + lseg);
            CP_ASYNC16(d2, Bhi + (size_t)(bn + lrow) * K + kc + lseg);
            CP_ASYNC16(d3, Blo + (size_t)(bn + lrow) * K + kc + lseg);
            CP_COMMIT();
        }

        unsigned bh[4][2], bl[4][2];
#pragma unroll
        for (int ntp = 0; ntp < 2; ntp++) {
            unsigned t[4];
            ldsm4(t, smem_to_u32(&sB[buf][0][(wn + ntp * 16) * TS]) + offB);
            bh[2 * ntp][0] = t[0]; bh[2 * ntp][1] = t[1];
            bh[2 * ntp + 1][0] = t[2]; bh[2 * ntp + 1][1] = t[3];
            ldsm4(t, smem_to_u32(&sB[buf][1][(wn + ntp * 16) * TS]) + offB);
            bl[2 * ntp][0] = t[0]; bl[2 * ntp][1] = t[1];
            bl[2 * ntp + 1][0] = t[2]; bl[2 * ntp + 1][1] = t[3];
        }
#pragma unroll
        for (int mt = 0; mt < 4; mt++) {
            unsigned ah[4], al[4];
            ldsm4(ah, smem_to_u32(&sA[buf][0][(wm + mt * 16) * TS]) + offA);
            ldsm4(al, smem_to_u32(&sA[buf][1][(wm + mt * 16) * TS]) + offA);
#pragma unroll
            for (int nt = 0; nt < 4; nt++) {
                mma16816(acc[mt][nt], ah, bh[nt]);
                mma16816(acc[mt][nt], ah, bl[nt]);
                mma16816(acc[mt][nt], al, bh[nt]);
            }
        }
    }

    if (Cf) {
        float sc = 1.0f;
        if (dwp) sc = 1.0f - *dwp;
#pragma unroll
        for (int mt = 0; mt < 4; mt++) {
#pragma unroll
            for (int nt = 0; nt < 4; nt++) {
                int row = bm + wm + mt * 16 + fr;
                int col = bn + wn + nt * 8 + fc;
                float b0 = 0.f, b1 = 0.f;
                if (bias) { b0 = bias[col]; b1 = bias[col + 1]; }
                float2 r0, r1;
                r0.x = (acc[mt][nt][0] + b0) * sc;
                r0.y = (acc[mt][nt][1] + b1) * sc;
                r1.x = (acc[mt][nt][2] + b0) * sc;
                r1.y = (acc[mt][nt][3] + b1) * sc;
                *(float2*)(Cf + (size_t)row * N + col) = r0;
                *(float2*)(Cf + (size_t)(row + 8) * N + col) = r1;
            }
        }
    } else {
#pragma unroll
        for (int mt = 0; mt < 4; mt++) {
#pragma unroll
            for (int nt = 0; nt < 4; nt++) {
                int row = bm + wm + mt * 16 + fr;
                int col = bn + wn + nt * 8 + fc;
#pragma unroll
                for (int half = 0; half < 2; half++) {
                    float v0 = acc[mt][nt][half * 2 + 0];
                    float v1 = acc[mt][nt][half * 2 + 1];
                    __nv_bfloat16 h0 = __float2bfloat16_rn(v0);
                    __nv_bfloat16 h1 = __float2bfloat16_rn(v1);
                    __nv_bfloat16 l0 = __float2bfloat16_rn(v0 - __bfloat162float(h0));
                    __nv_bfloat16 l1 = __float2bfloat16_rn(v1 - __bfloat162float(h1));
                    size_t off = (size_t)(row + half * 8) * N + col;
                    *(__nv_bfloat162*)(Chi + off) = __nv_bfloat162(h0, h1);
                    *(__nv_bfloat162*)(Clo + off) = __nv_bfloat162(l0, l1);
                }
            }
        }
    }
}

// ======================================================================
// HMMA differential flash attention, register-resident softmax.
// CTA: (b, h, 64-q tile), 8 warps. Warps 0-3: branch0, 4-7: branch1.
// QK accumulator fragments are repacked in-register into PV A-fragments;
// online softmax state (m, l) lives in registers (4 lanes share a row).
// ======================================================================
#define BQ 64
#define BKT 64
#define QB  272   // byte stride for Q/K/V bf16 tiles (136 bf16)
#define OSR 132   // fp32 stride for O staging

#define OFF_QHI  0
#define OFF_QLO  17408
#define OFF_KHI  34816
#define OFF_KLO  52224
#define OFF_VHI  69632
#define OFF_VLO  87040
#define ATT_SMEM_BYTES 104448

__global__ void __launch_bounds__(256) diff_attn_mma_kernel(
    const __nv_bfloat16* __restrict__ qh_g, const __nv_bfloat16* __restrict__ ql_g,
    const __nv_bfloat16* __restrict__ kh_g, const __nv_bfloat16* __restrict__ kl_g,
    const __nv_bfloat16* __restrict__ vh_g, const __nv_bfloat16* __restrict__ vl_g,
    float* __restrict__ o, const float* __restrict__ dwp)
{
    extern __shared__ char smem[];
    const unsigned su = smem_to_u32(smem);
    float* Ot = (float*)(smem + OFF_KHI);   // branch1 staging (post-loop, K region)
    float* Of = (float*)(smem + OFF_VHI);   // final combine (post-loop, V region)

    const int tid = threadIdx.x;
    const int wid = tid >> 5, L = tid & 31;
    const int fr = L >> 2;           // 0..7
    const int lm = L >> 3, lr = L & 7;
    const int qt = blockIdx.x, hd = blockIdx.y, b = blockIdx.z;
    const int q0 = qt * BQ;
    const int bidx = wid >> 2;       // branch
    const int ws = wid & 3;          // warp slot -> q rows ms..ms+15
    const int ms = ws * 16;
    const int fc2 = (L & 3) * 2;

    const unsigned offA272 = (unsigned)((lr + ((lm & 1) << 3)) * QB + ((lm >> 1) << 4));
    const unsigned offB272 = (unsigned)((lr + ((lm >> 1) << 3)) * QB + ((lm & 1) << 4));

    const size_t rowbase = (size_t)b * SLEN;

    // ---- load Q tile (hi/lo), 64 x 128 bf16 each ----
#pragma unroll
    for (int i = 0; i < 4; i++) {
        int f = tid + i * 256;               // 0..1023
        int r = f >> 4, c = f & 15;
        size_t src = (rowbase + q0 + r) * EDIM + hd * 128 + c * 8;
        *(uint4*)(smem + OFF_QHI + r * QB + c * 16) = *(const uint4*)(qh_g + src);
        *(uint4*)(smem + OFF_QLO + r * QB + c * 16) = *(const uint4*)(ql_g + src);
    }

    float m_a = -1e30f, m_b = -1e30f, l_a = 0.f, l_b = 0.f;
    float pacc[16][4];
#pragma unroll
    for (int nt = 0; nt < 16; nt++)
#pragma unroll
        for (int e = 0; e < 4; e++) pacc[nt][e] = 0.f;

    const float scale = 0.125f;

    for (int kt = 0; kt < SLEN; kt += BKT) {
        __syncthreads();   // previous tile's QK/PV done before overwriting K/V
        // ---- cp.async K and V tiles (hi/lo) ----
#pragma unroll
        for (int i = 0; i < 4; i++) {
            int f = tid + i * 256;
            int r = f >> 4, c = f & 15;
            size_t src = (rowbase + kt + r) * EDIM + hd * 128 + c * 8;
            unsigned dsm = su + r * QB + c * 16;
            CP_ASYNC16(dsm + OFF_KHI, kh_g + src);
            CP_ASYNC16(dsm + OFF_KLO, kl_g + src);
            CP_ASYNC16(dsm + OFF_VHI, vh_g + src);
            CP_ASYNC16(dsm + OFF_VLO, vl_g + src);
        }
        CP_COMMIT();
        CP_WAIT0();
        __syncthreads();

        // ---- QK^T: 16x64 strip per warp, 3-term split ----
        float sacc[8][4];
#pragma unroll
        for (int nt = 0; nt < 8; nt++)
#pragma unroll
            for (int e = 0; e < 4; e++) sacc[nt][e] = 0.f;

#pragma unroll
        for (int ks = 0; ks < 4; ks++) {
            const unsigned kofb = (unsigned)(bidx * 128 + ks * 32);
            unsigned ah[4], al[4];
            ldsm4(ah, su + OFF_QHI + ms * QB + kofb + offA272);
            ldsm4(al, su + OFF_QLO + ms * QB + kofb + offA272);
#pragma unroll
            for (int ntp = 0; ntp < 4; ntp++) {
                unsigned th[4], tl[4];
                ldsm4(th, su + OFF_KHI + (ntp * 16) * QB + kofb + offB272);
                ldsm4(tl, su + OFF_KLO + (ntp * 16) * QB + kofb + offB272);
                mma16816(sacc[2 * ntp], ah, th);
                mma16816(sacc[2 * ntp], ah, tl);
                mma16816(sacc[2 * ntp], al, th);
                mma16816(sacc[2 * ntp + 1], ah, th + 2);
                mma16816(sacc[2 * ntp + 1], ah, tl + 2);
                mma16816(sacc[2 * ntp + 1], al, th + 2);
            }
        }
#pragma unroll
        for (int nt = 0; nt < 8; nt++)
#pragma unroll
            for (int e = 0; e < 4; e++) sacc[nt][e] *= scale;

        // ---- register-resident online softmax ----
        {
            float ra = -1e30f, rb = -1e30f;
#pragma unroll
            for (int nt = 0; nt < 8; nt++) {
                ra = fmaxf(ra, fmaxf(sacc[nt][0], sacc[nt][1]));
                rb = fmaxf(rb, fmaxf(sacc[nt][2], sacc[nt][3]));
            }
            ra = fmaxf(ra, __shfl_xor_sync(0xffffffffu, ra, 1));
            ra = fmaxf(ra, __shfl_xor_sync(0xffffffffu, ra, 2));
            rb = fmaxf(rb, __shfl_xor_sync(0xffffffffu, rb, 1));
            rb = fmaxf(rb, __shfl_xor_sync(0xffffffffu, rb, 2));
            float mna = fmaxf(m_a, ra), mnb = fmaxf(m_b, rb);
            float cca = __expf(m_a - mna), ccb = __expf(m_b - mnb);
            m_a = mna; m_b = mnb;
            float suma = 0.f, sumb = 0.f;
#pragma unroll
            for (int nt = 0; nt < 8; nt++) {
                sacc[nt][0] = __expf(sacc[nt][0] - mna); suma += sacc[nt][0];
                sacc[nt][1] = __expf(sacc[nt][1] - mna); suma += sacc[nt][1];
                sacc[nt][2] = __expf(sacc[nt][2] - mnb); sumb += sacc[nt][2];
                sacc[nt][3] = __expf(sacc[nt][3] - mnb); sumb += sacc[nt][3];
            }
            suma += __shfl_xor_sync(0xffffffffu, suma, 1);
            suma += __shfl_xor_sync(0xffffffffu, suma, 2);
            sumb += __shfl_xor_sync(0xffffffffu, sumb, 1);
            sumb += __shfl_xor_sync(0xffffffffu, sumb, 2);
            l_a = l_a * cca + suma;
            l_b = l_b * ccb + sumb;
#pragma unroll
            for (int nt = 0; nt < 16; nt++) {
                pacc[nt][0] *= cca; pacc[nt][1] *= cca;
                pacc[nt][2] *= ccb; pacc[nt][3] *= ccb;
            }
        }

        // ---- PV: pack P from QK accumulator (C-frag == A-frag layout) ----
#pragma unroll
        for (int ks = 0; ks < 4; ks++) {
            unsigned ph[4], pl[4];
#pragma unroll
            for (int half = 0; half < 2; half++) {
                const float* s0 = sacc[2 * ks + half];
                unsigned p01 = cvt2(s0[1], s0[0]);
                unsigned p23 = cvt2(s0[3], s0[2]);
                float r0 = s0[0] - __uint_as_float(p01 << 16);
                float r1 = s0[1] - __uint_as_float(p01 & 0xFFFF0000u);
                float r2 = s0[2] - __uint_as_float(p23 << 16);
                float r3 = s0[3] - __uint_as_float(p23 & 0xFFFF0000u);
                ph[2 * half + 0] = p01;
                ph[2 * half + 1] = p23;
                pl[2 * half + 0] = cvt2(r1, r0);
                pl[2 * half + 1] = cvt2(r3, r2);
            }
            // reorder: a0=(fr,k0-7), a1=(fr+8,k0-7), a2=(fr,k8-15), a3=(fr+8,k8-15)
            unsigned phf[4] = { ph[0], ph[1], ph[2], ph[3] };
            unsigned plf[4] = { pl[0], pl[1], pl[2], pl[3] };
#pragma unroll
            for (int dtp = 0; dtp < 8; dtp++) {
                unsigned vh[4], vl[4];
                ldsm4t(vh, su + OFF_VHI + (ks * 16) * QB + dtp * 32 + offA272);
                ldsm4t(vl, su + OFF_VLO + (ks * 16) * QB + dtp * 32 + offA272);
                mma16816(pacc[2 * dtp], phf, vh);
                mma16816(pacc[2 * dtp], phf, vl);
                mma16816(pacc[2 * dtp], plf, vh);
                mma16816(pacc[2 * dtp + 1], phf, vh + 2);
                mma16816(pacc[2 * dtp + 1], phf, vl + 2);
                mma16816(pacc[2 * dtp + 1], plf, vh + 2);
            }
        }
    }
    __syncthreads();

    // ---- epilogue: o = O0/l0 - dw * O1/l1 ----
    const float dw = *dwp;
    if (bidx == 1) {
        const float i0 = 1.f / l_a, i1 = 1.f / l_b;
#pragma unroll
        for (int nt = 0; nt < 16; nt++) {
            int d = nt * 8 + fc2;
            *(float2*)&Ot[(ms + fr) * OSR + d] =
                make_float2(pacc[nt][0] * i0, pacc[nt][1] * i0);
            *(float2*)&Ot[(ms + fr + 8) * OSR + d] =
                make_float2(pacc[nt][2] * i1, pacc[nt][3] * i1);
        }
    }
    __syncthreads();
    if (bidx == 0) {
        const float i0 = 1.f / l_a, i1 = 1.f / l_b;
#pragma unroll
        for (int nt = 0; nt < 16; nt++) {
            int d = nt * 8 + fc2;
            float2 t0 = *(float2*)&Ot[(ms + fr) * OSR + d];
            float2 t1 = *(float2*)&Ot[(ms + fr + 8) * OSR + d];
            *(float2*)&Of[(ms + fr) * OSR + d] =
                make_float2(pacc[nt][0] * i0 - dw * t0.x, pacc[nt][1] * i0 - dw * t0.y);
            *(float2*)&Of[(ms + fr + 8) * OSR + d] =
                make_float2(pacc[nt][2] * i1 - dw * t1.x, pacc[nt][3] * i1 - dw * t1.y);
        }
    }
    __syncthreads();

    float* og = o + (rowbase + q0) * EDIM + hd * 128;
#pragma unroll
    for (int i = 0; i < 8; i++) {
        int f = tid + i * 256;
        int r = f >> 5, c4 = f & 31;
        *(float4*)(og + (size_t)r * EDIM + c4 * 4) = *(const float4*)&Of[r * OSR + c4 * 4];
    }
}

// ======================================================================
// RMSNorm over 1024-wide rows, fused split-bf16 output
// ======================================================================
__global__ void __launch_bounds__(256) rmsnorm_split_kernel(
    const float* __restrict__ x, const float* __restrict__ w,
    __nv_bfloat16* __restrict__ yhi, __nv_bfloat16* __restrict__ ylo)
{
    __shared__ float red[8];
    __shared__ float rtot;
    const int tid = threadIdx.x;
    const int row = blockIdx.x;
    const float* xr = x + (size_t)row * EDIM;

    float v[4];
    float s = 0.f;
#pragma unroll
    for (int j = 0; j < 4; j++) {
        v[j] = xr[tid + j * 256];
        s = fmaf(v[j], v[j], s);
    }
#pragma unroll
    for (int off = 16; off > 0; off >>= 1)
        s += __shfl_xor_sync(0xffffffffu, s, off);
    if ((tid & 31) == 0) red[tid >> 5] = s;
    __syncthreads();
    if (tid == 0) {
        float t = 0.f;
#pragma unroll
        for (int i = 0; i < 8; i++) t += red[i];
        rtot = rsqrtf(t * (1.0f / 1024.0f) + 1.1920929e-07f);
    }
    __syncthreads();
    float r = rtot;
#pragma unroll
    for (int j = 0; j < 4; j++) {
        int c = tid + j * 256;
        float f = v[j] * r * w[c];
        __nv_bfloat16 h = __float2bfloat16_rn(f);
        __nv_bfloat16 l = __float2bfloat16_rn(f - __bfloat162float(h));
        yhi[(size_t)row * EDIM + c] = h;
        ylo[(size_t)row * EDIM + c] = l;
    }
}

// ======================================================================
// launcher
// ======================================================================
extern "C" void kernel_launch(void* const* d_in, const int* in_sizes, int n_in,
                              void* d_out, int out_size)
{
    const float* x  = (const float*)d_in[0];
    const float* Wq = (const float*)d_in[1];
    const float* Wk = (const float*)d_in[2];
    const float* Wv = (const float*)d_in[3];
    const float* nw = (const float*)d_in[4];
    const float* Wo = (const float*)d_in[5];
    const float* bo = (const float*)d_in[6];
    const float* dw = (const float*)d_in[7];
    float* out = (float*)d_out;

    float* op;
    cudaGetSymbolAddress((void**)&op, g_o);
    __nv_bfloat16 *xh, *xl, *nh, *nl;
    cudaGetSymbolAddress((void**)&xh, g_xhi);
    cudaGetSymbolAddress((void**)&xl, g_xlo);
    cudaGetSymbolAddress((void**)&nh, g_nhi);
    cudaGetSymbolAddress((void**)&nl, g_nlo);
    __nv_bfloat16 *qh, *ql, *kh, *kl, *vh, *vl;
    cudaGetSymbolAddress((void**)&qh, g_qh);
    cudaGetSymbolAddress((void**)&ql, g_ql);
    cudaGetSymbolAddress((void**)&kh, g_kh);
    cudaGetSymbolAddress((void**)&kl, g_kl);
    cudaGetSymbolAddress((void**)&vh, g_vh);
    cudaGetSymbolAddress((void**)&vl, g_vl);
    __nv_bfloat16 *wqh, *wql, *wkh, *wkl, *wvh, *wvl, *woh, *wol;
    cudaGetSymbolAddress((void**)&wqh, g_wqhi);
    cudaGetSymbolAddress((void**)&wql, g_wqlo);
    cudaGetSymbolAddress((void**)&wkh, g_wkhi);
    cudaGetSymbolAddress((void**)&wkl, g_wklo);
    cudaGetSymbolAddress((void**)&wvh, g_wvhi);
    cudaGetSymbolAddress((void**)&wvl, g_wvlo);
    cudaGetSymbolAddress((void**)&woh, g_wohi);
    cudaGetSymbolAddress((void**)&wol, g_wolo);

    cudaFuncSetAttribute(diff_attn_mma_kernel,
                         cudaFuncAttributeMaxDynamicSharedMemorySize, ATT_SMEM_BYTES);

    // split conversions
    const int xn4 = MROWS * EDIM / 4;
    const int wn4 = EDIM * EDIM / 4;
    split_bf16_kernel<<<xn4 / 256, 256>>>(x,  xh, xl, xn4);
    split_bf16_kernel<<<wn4 / 256, 256>>>(Wq, wqh, wql, wn4);
    split_bf16_kernel<<<wn4 / 256, 256>>>(Wk, wkh, wkl, wn4);
    split_bf16_kernel<<<wn4 / 256, 256>>>(Wv, wvh, wvl, wn4);
    split_bf16_kernel<<<wn4 / 256, 256>>>(Wo, woh, wol, wn4);

    // projections (HMMA split-bf16, direct bf16 hi/lo output)
    dim3 gg(EDIM / 128, MROWS / 128);
    mma_gemm_kernel<<<gg, 256>>>(xh, xl, wqh, wql, nullptr, qh, ql, MROWS, EDIM, EDIM, nullptr, nullptr);
    mma_gemm_kernel<<<gg, 256>>>(xh, xl, wkh, wkl, nullptr, kh, kl, MROWS, EDIM, EDIM, nullptr, nullptr);
    mma_gemm_kernel<<<gg, 256>>>(xh, xl, wvh, wvl, nullptr, vh, vl, MROWS, EDIM, EDIM, nullptr, nullptr);

    // attention (HMMA, register softmax)
    dim3 ga(SLEN / BQ, NHEAD, 2);
    diff_attn_mma_kernel<<<ga, 256, ATT_SMEM_BYTES>>>(qh, ql, kh, kl, vh, vl, op, dw);

    // rmsnorm + split
    rmsnorm_split_kernel<<<MROWS, 256>>>(op, nw, nh, nl);

    // output projection with bias + (1-dw) scale
    mma_gemm_kernel<<<gg, 256>>>(nh, nl, woh, wol, out, nullptr, nullptr, MROWS, EDIM, EDIM, bo, dw);
}

// round 11
// speedup vs baseline: 2.5365x; 1.0332x over previous
#include <cuda_runtime.h>
#include <cuda_bf16.h>
#include <cstdint>
#include <cstddef>
#include <math.h>

#define MROWS 4096           // B*S
#define EDIM  1024
#define SLEN  2048
#define NHEAD 8

// ---------------- warp-level bf16 MMA (m16n8k16, fp32 accum) ----------------
__device__ __forceinline__ void mma16816(
    float* c, const unsigned* a, const unsigned* b)
{
    asm volatile(
        "mma.sync.aligned.m16n8k16.row.col.f32.bf16.bf16.f32 "
        "{%0,%1,%2,%3}, {%4,%5,%6,%7}, {%8,%9}, {%0,%1,%2,%3};"
        : "+f"(c[0]), "+f"(c[1]), "+f"(c[2]), "+f"(c[3])
        : "r"(a[0]), "r"(a[1]), "r"(a[2]), "r"(a[3]), "r"(b[0]), "r"(b[1]));
}
__device__ __forceinline__ void ldsm4(unsigned* r, unsigned addr) {
    asm volatile("ldmatrix.sync.aligned.m8n8.x4.shared.b16 {%0,%1,%2,%3}, [%4];"
        : "=r"(r[0]), "=r"(r[1]), "=r"(r[2]), "=r"(r[3]) : "r"(addr));
}
__device__ __forceinline__ void ldsm4t(unsigned* r, unsigned addr) {
    asm volatile("ldmatrix.sync.aligned.m8n8.x4.trans.shared.b16 {%0,%1,%2,%3}, [%4];"
        : "=r"(r[0]), "=r"(r[1]), "=r"(r[2]), "=r"(r[3]) : "r"(addr));
}
__device__ __forceinline__ unsigned smem_to_u32(const void* p) {
    unsigned a;
    asm("{ .reg .u64 t; cvta.to.shared.u64 t, %1; cvt.u32.u64 %0, t; }" : "=r"(a) : "l"(p));
    return a;
}
// pack two fp32 into bf16x2: low half = lo, high half = hi
__device__ __forceinline__ unsigned cvt2(float hi, float lo) {
    unsigned r; asm("cvt.rn.bf16x2.f32 %0, %1, %2;" : "=r"(r) : "f"(hi), "f"(lo));
    return r;
}
#define CP_ASYNC16(dst_u32, src) \
    asm volatile("cp.async.cg.shared.global [%0], [%1], 16;" :: "r"(dst_u32), "l"(src))
#define CP_COMMIT() asm volatile("cp.async.commit_group;" ::: "memory")
#define CP_WAIT0()  asm volatile("cp.async.wait_group 0;" ::: "memory")
#define CP_WAIT1()  asm volatile("cp.async.wait_group 1;" ::: "memory")

// ---------------- scratch (device globals: allocation-free) ----------------
__device__ float g_o[(size_t)MROWS * EDIM];
__device__ __nv_bfloat16 g_xhi[(size_t)MROWS * EDIM];
__device__ __nv_bfloat16 g_xlo[(size_t)MROWS * EDIM];
__device__ __nv_bfloat16 g_nhi[(size_t)MROWS * EDIM];
__device__ __nv_bfloat16 g_nlo[(size_t)MROWS * EDIM];
__device__ __nv_bfloat16 g_qh[(size_t)MROWS * EDIM];
__device__ __nv_bfloat16 g_ql[(size_t)MROWS * EDIM];
__device__ __nv_bfloat16 g_kh[(size_t)MROWS * EDIM];
__device__ __nv_bfloat16 g_kl[(size_t)MROWS * EDIM];
__device__ __nv_bfloat16 g_vh[(size_t)MROWS * EDIM];
__device__ __nv_bfloat16 g_vl[(size_t)MROWS * EDIM];
__device__ __nv_bfloat16 g_wqhi[(size_t)EDIM * EDIM];
__device__ __nv_bfloat16 g_wqlo[(size_t)EDIM * EDIM];
__device__ __nv_bfloat16 g_wkhi[(size_t)EDIM * EDIM];
__device__ __nv_bfloat16 g_wklo[(size_t)EDIM * EDIM];
__device__ __nv_bfloat16 g_wvhi[(size_t)EDIM * EDIM];
__device__ __nv_bfloat16 g_wvlo[(size_t)EDIM * EDIM];
__device__ __nv_bfloat16 g_wohi[(size_t)EDIM * EDIM];
__device__ __nv_bfloat16 g_wolo[(size_t)EDIM * EDIM];

// ======================================================================
// fp32 -> (bf16 hi, bf16 lo) split, vectorized float4
// ======================================================================
__global__ void __launch_bounds__(256) split_bf16_kernel(
    const float* __restrict__ x, __nv_bfloat16* __restrict__ hi,
    __nv_bfloat16* __restrict__ lo, int n4)
{
    int i = blockIdx.x * 256 + threadIdx.x;
    if (i >= n4) return;
    float4 v = ((const float4*)x)[i];
    float vv[4] = { v.x, v.y, v.z, v.w };
    __nv_bfloat16 h[4], l[4];
#pragma unroll
    for (int j = 0; j < 4; j++) {
        h[j] = __float2bfloat16_rn(vv[j]);
        l[j] = __float2bfloat16_rn(vv[j] - __bfloat162float(h[j]));
    }
    __nv_bfloat162* hp = (__nv_bfloat162*)hi;
    __nv_bfloat162* lp = (__nv_bfloat162*)lo;
    hp[i * 2 + 0] = __nv_bfloat162(h[0], h[1]);
    hp[i * 2 + 1] = __nv_bfloat162(h[2], h[3]);
    lp[i * 2 + 0] = __nv_bfloat162(l[0], l[1]);
    lp[i * 2 + 1] = __nv_bfloat162(l[2], l[3]);
}

// ======================================================================
// HMMA split-bf16 GEMM: C = A[M,K] @ B[N,K]^T
// cp.async double-buffered BK=16, ldmatrix fragment loads.
// ======================================================================
#define TS 24   // smem row stride in bf16 (48B) -> conflict-free ldmatrix

__global__ void __launch_bounds__(256) mma_gemm_kernel(
    const __nv_bfloat16* __restrict__ Ahi, const __nv_bfloat16* __restrict__ Alo,
    const __nv_bfloat16* __restrict__ Bhi, const __nv_bfloat16* __restrict__ Blo,
    float* __restrict__ Cf, __nv_bfloat16* __restrict__ Chi, __nv_bfloat16* __restrict__ Clo,
    int M, int N, int K,
    const float* __restrict__ bias, const float* __restrict__ dwp)
{
    __shared__ __nv_bfloat16 sA[2][2][128 * TS];   // [buf][hi/lo]
    __shared__ __nv_bfloat16 sB[2][2][128 * TS];

    const int tid = threadIdx.x;
    const int wid = tid >> 5, L = tid & 31;
    const int bm = blockIdx.y * 128, bn = blockIdx.x * 128;
    const int wm = (wid >> 2) * 64, wn = (wid & 3) * 32;

    const int lrow = tid >> 1;            // 0..127
    const int lseg = (tid & 1) * 8;       // 0 or 8 (bf16)

    const int fr = L >> 2;                // 0..7
    const int fc = (L & 3) * 2;           // 0,2,4,6
    const int lm = L >> 3, lr = L & 7;
    const unsigned offA = (unsigned)((lr + ((lm & 1) << 3)) * 48 + ((lm >> 1) << 4));
    const unsigned offB = (unsigned)((lr + ((lm >> 1) << 3)) * 48 + ((lm & 1) << 4));

    float acc[4][4][4];
#pragma unroll
    for (int mt = 0; mt < 4; mt++)
#pragma unroll
        for (int nt = 0; nt < 4; nt++)
#pragma unroll
            for (int e = 0; e < 4; e++) acc[mt][nt][e] = 0.f;

    const int nchunks = K / 16;

    {
        unsigned d0 = smem_to_u32(&sA[0][0][lrow * TS + lseg]);
        unsigned d1 = smem_to_u32(&sA[0][1][lrow * TS + lseg]);
        unsigned d2 = smem_to_u32(&sB[0][0][lrow * TS + lseg]);
        unsigned d3 = smem_to_u32(&sB[0][1][lrow * TS + lseg]);
        CP_ASYNC16(d0, Ahi + (size_t)(bm + lrow) * K + lseg);
        CP_ASYNC16(d1, Alo + (size_t)(bm + lrow) * K + lseg);
        CP_ASYNC16(d2, Bhi + (size_t)(bn + lrow) * K + lseg);
        CP_ASYNC16(d3, Blo + (size_t)(bn + lrow) * K + lseg);
        CP_COMMIT();
    }

    for (int c = 0; c < nchunks; c++) {
        CP_WAIT0();
        __syncthreads();
        const int buf = c & 1;
        if (c + 1 < nchunks) {
            const int nb = (c + 1) & 1;
            const int kc = (c + 1) * 16;
            unsigned d0 = smem_to_u32(&sA[nb][0][lrow * TS + lseg]);
            unsigned d1 = smem_to_u32(&sA[nb][1][lrow * TS + lseg]);
            unsigned d2 = smem_to_u32(&sB[nb][0][lrow * TS + lseg]);
            unsigned d3 = smem_to_u32(&sB[nb][1][lrow * TS + lseg]);
            CP_ASYNC16(d0, Ahi + (size_t)(bm + lrow) * K + kc + lseg);
            CP_ASYNC16(d1, Alo + (size_t)(bm + lrow) * K + kc + lseg);
            CP_ASYNC16(d2, Bhi + (size_t)(bn + lrow) * K + kc + lseg);
            CP_ASYNC16(d3, Blo + (size_t)(bn + lrow) * K + kc + lseg);
            CP_COMMIT();
        }

        unsigned bh[4][2], bl[4][2];
#pragma unroll
        for (int ntp = 0; ntp < 2; ntp++) {
            unsigned t[4];
            ldsm4(t, smem_to_u32(&sB[buf][0][(wn + ntp * 16) * TS]) + offB);
            bh[2 * ntp][0] = t[0]; bh[2 * ntp][1] = t[1];
            bh[2 * ntp + 1][0] = t[2]; bh[2 * ntp + 1][1] = t[3];
            ldsm4(t, smem_to_u32(&sB[buf][1][(wn + ntp * 16) * TS]) + offB);
            bl[2 * ntp][0] = t[0]; bl[2 * ntp][1] = t[1];
            bl[2 * ntp + 1][0] = t[2]; bl[2 * ntp + 1][1] = t[3];
        }
#pragma unroll
        for (int mt = 0; mt < 4; mt++) {
            unsigned ah[4], al[4];
            ldsm4(ah, smem_to_u32(&sA[buf][0][(wm + mt * 16) * TS]) + offA);
            ldsm4(al, smem_to_u32(&sA[buf][1][(wm + mt * 16) * TS]) + offA);
#pragma unroll
            for (int nt = 0; nt < 4; nt++) {
                mma16816(acc[mt][nt], ah, bh[nt]);
                mma16816(acc[mt][nt], ah, bl[nt]);
                mma16816(acc[mt][nt], al, bh[nt]);
            }
        }
    }

    if (Cf) {
        float sc = 1.0f;
        if (dwp) sc = 1.0f - *dwp;
#pragma unroll
        for (int mt = 0; mt < 4; mt++) {
#pragma unroll
            for (int nt = 0; nt < 4; nt++) {
                int row = bm + wm + mt * 16 + fr;
                int col = bn + wn + nt * 8 + fc;
                float b0 = 0.f, b1 = 0.f;
                if (bias) { b0 = bias[col]; b1 = bias[col + 1]; }
                float2 r0, r1;
                r0.x = (acc[mt][nt][0] + b0) * sc;
                r0.y = (acc[mt][nt][1] + b1) * sc;
                r1.x = (acc[mt][nt][2] + b0) * sc;
                r1.y = (acc[mt][nt][3] + b1) * sc;
                *(float2*)(Cf + (size_t)row * N + col) = r0;
                *(float2*)(Cf + (size_t)(row + 8) * N + col) = r1;
            }
        }
    } else {
#pragma unroll
        for (int mt = 0; mt < 4; mt++) {
#pragma unroll
            for (int nt = 0; nt < 4; nt++) {
                int row = bm + wm + mt * 16 + fr;
                int col = bn + wn + nt * 8 + fc;
#pragma unroll
                for (int half = 0; half < 2; half++) {
                    float v0 = acc[mt][nt][half * 2 + 0];
                    float v1 = acc[mt][nt][half * 2 + 1];
                    __nv_bfloat16 h0 = __float2bfloat16_rn(v0);
                    __nv_bfloat16 h1 = __float2bfloat16_rn(v1);
                    __nv_bfloat16 l0 = __float2bfloat16_rn(v0 - __bfloat162float(h0));
                    __nv_bfloat16 l1 = __float2bfloat16_rn(v1 - __bfloat162float(h1));
                    size_t off = (size_t)(row + half * 8) * N + col;
                    *(__nv_bfloat162*)(Chi + off) = __nv_bfloat162(h0, h1);
                    *(__nv_bfloat162*)(Clo + off) = __nv_bfloat162(l0, l1);
                }
            }
        }
    }
}

// ======================================================================
// HMMA differential flash attention, register-resident softmax,
// double-buffered cp.async K/V pipeline.
// CTA: (b, h, 64-q tile), 8 warps. Warps 0-3: branch0, 4-7: branch1.
// ======================================================================
#define BQ 64
#define BKT 64
#define QB  272   // byte stride for Q/K/V bf16 tiles (136 bf16)
#define OSR 132   // fp32 stride for O staging

#define OFF_QHI  0
#define OFF_QLO  17408
#define OFF_KV   34816       // 2 buffers x 4 tiles x 17408 bytes
#define KV_BUF   69632       // bytes per buffer set
#define KV_KHI   0
#define KV_KLO   17408
#define KV_VHI   34816
#define KV_VLO   52224
#define ATT_SMEM_BYTES (OFF_KV + 2 * KV_BUF)   // 174080

__global__ void __launch_bounds__(256) diff_attn_mma_kernel(
    const __nv_bfloat16* __restrict__ qh_g, const __nv_bfloat16* __restrict__ ql_g,
    const __nv_bfloat16* __restrict__ kh_g, const __nv_bfloat16* __restrict__ kl_g,
    const __nv_bfloat16* __restrict__ vh_g, const __nv_bfloat16* __restrict__ vl_g,
    float* __restrict__ o, const float* __restrict__ dwp)
{
    extern __shared__ char smem[];
    const unsigned su = smem_to_u32(smem);
    float* Ot = (float*)(smem + OFF_KV);              // post-loop staging (buf0 K)
    float* Of = (float*)(smem + OFF_KV + KV_VHI);     // post-loop combine (buf0 V)

    const int tid = threadIdx.x;
    const int wid = tid >> 5, L = tid & 31;
    const int fr = L >> 2;           // 0..7
    const int lm = L >> 3, lr = L & 7;
    const int qt = blockIdx.x, hd = blockIdx.y, b = blockIdx.z;
    const int q0 = qt * BQ;
    const int bidx = wid >> 2;       // branch
    const int ws = wid & 3;          // warp slot -> q rows ms..ms+15
    const int ms = ws * 16;
    const int fc2 = (L & 3) * 2;

    const unsigned offA272 = (unsigned)((lr + ((lm & 1) << 3)) * QB + ((lm >> 1) << 4));
    const unsigned offB272 = (unsigned)((lr + ((lm >> 1) << 3)) * QB + ((lm & 1) << 4));

    const size_t rowbase = (size_t)b * SLEN;

    // ---- load Q tile (hi/lo), 64 x 128 bf16 each ----
#pragma unroll
    for (int i = 0; i < 4; i++) {
        int f = tid + i * 256;               // 0..1023
        int r = f >> 4, c = f & 15;
        size_t src = (rowbase + q0 + r) * EDIM + hd * 128 + c * 8;
        *(uint4*)(smem + OFF_QHI + r * QB + c * 16) = *(const uint4*)(qh_g + src);
        *(uint4*)(smem + OFF_QLO + r * QB + c * 16) = *(const uint4*)(ql_g + src);
    }

    float m_a = -1e30f, m_b = -1e30f, l_a = 0.f, l_b = 0.f;
    float pacc[16][4];
#pragma unroll
    for (int nt = 0; nt < 16; nt++)
#pragma unroll
        for (int e = 0; e < 4; e++) pacc[nt][e] = 0.f;

    const float scale = 0.125f;
    const int NT = SLEN / BKT;   // 32... actually 2048/64 = 32 tiles

    // issue tile 0 into buffer 0
    {
        const unsigned kvb = su + OFF_KV;
#pragma unroll
        for (int i = 0; i < 4; i++) {
            int f = tid + i * 256;
            int r = f >> 4, c = f & 15;
            size_t src = (rowbase + r) * EDIM + hd * 128 + c * 8;
            unsigned dsm = kvb + r * QB + c * 16;
            CP_ASYNC16(dsm + KV_KHI, kh_g + src);
            CP_ASYNC16(dsm + KV_KLO, kl_g + src);
            CP_ASYNC16(dsm + KV_VHI, vh_g + src);
            CP_ASYNC16(dsm + KV_VLO, vl_g + src);
        }
        CP_COMMIT();
    }

    for (int t = 0; t < NT; t++) {
        if (t > 0) __syncthreads();   // all warps done reading buf[(t+1)&1] (tile t-1)
        if (t + 1 < NT) {
            const unsigned kvb = su + OFF_KV + ((t + 1) & 1) * KV_BUF;
            const int kt1 = (t + 1) * BKT;
#pragma unroll
            for (int i = 0; i < 4; i++) {
                int f = tid + i * 256;
                int r = f >> 4, c = f & 15;
                size_t src = (rowbase + kt1 + r) * EDIM + hd * 128 + c * 8;
                unsigned dsm = kvb + r * QB + c * 16;
                CP_ASYNC16(dsm + KV_KHI, kh_g + src);
                CP_ASYNC16(dsm + KV_KLO, kl_g + src);
                CP_ASYNC16(dsm + KV_VHI, vh_g + src);
                CP_ASYNC16(dsm + KV_VLO, vl_g + src);
            }
            CP_COMMIT();
            CP_WAIT1();   // tile t complete; tile t+1 still in flight
        } else {
            CP_WAIT0();
        }
        __syncthreads();

        const unsigned kvb = su + OFF_KV + (t & 1) * KV_BUF;

        // ---- QK^T: 16x64 strip per warp, 3-term split ----
        float sacc[8][4];
#pragma unroll
        for (int nt = 0; nt < 8; nt++)
#pragma unroll
            for (int e = 0; e < 4; e++) sacc[nt][e] = 0.f;

#pragma unroll
        for (int ks = 0; ks < 4; ks++) {
            const unsigned kofb = (unsigned)(bidx * 128 + ks * 32);
            unsigned ah[4], al[4];
            ldsm4(ah, su + OFF_QHI + ms * QB + kofb + offA272);
            ldsm4(al, su + OFF_QLO + ms * QB + kofb + offA272);
#pragma unroll
            for (int ntp = 0; ntp < 4; ntp++) {
                unsigned th[4], tl[4];
                ldsm4(th, kvb + KV_KHI + (ntp * 16) * QB + kofb + offB272);
                ldsm4(tl, kvb + KV_KLO + (ntp * 16) * QB + kofb + offB272);
                mma16816(sacc[2 * ntp], ah, th);
                mma16816(sacc[2 * ntp], ah, tl);
                mma16816(sacc[2 * ntp], al, th);
                mma16816(sacc[2 * ntp + 1], ah, th + 2);
                mma16816(sacc[2 * ntp + 1], ah, tl + 2);
                mma16816(sacc[2 * ntp + 1], al, th + 2);
            }
        }
#pragma unroll
        for (int nt = 0; nt < 8; nt++)
#pragma unroll
            for (int e = 0; e < 4; e++) sacc[nt][e] *= scale;

        // ---- register-resident online softmax ----
        {
            float ra = -1e30f, rb = -1e30f;
#pragma unroll
            for (int nt = 0; nt < 8; nt++) {
                ra = fmaxf(ra, fmaxf(sacc[nt][0], sacc[nt][1]));
                rb = fmaxf(rb, fmaxf(sacc[nt][2], sacc[nt][3]));
            }
            ra = fmaxf(ra, __shfl_xor_sync(0xffffffffu, ra, 1));
            ra = fmaxf(ra, __shfl_xor_sync(0xffffffffu, ra, 2));
            rb = fmaxf(rb, __shfl_xor_sync(0xffffffffu, rb, 1));
            rb = fmaxf(rb, __shfl_xor_sync(0xffffffffu, rb, 2));
            float mna = fmaxf(m_a, ra), mnb = fmaxf(m_b, rb);
            float cca = __expf(m_a - mna), ccb = __expf(m_b - mnb);
            m_a = mna; m_b = mnb;
            float suma = 0.f, sumb = 0.f;
#pragma unroll
            for (int nt = 0; nt < 8; nt++) {
                sacc[nt][0] = __expf(sacc[nt][0] - mna); suma += sacc[nt][0];
                sacc[nt][1] = __expf(sacc[nt][1] - mna); suma += sacc[nt][1];
                sacc[nt][2] = __expf(sacc[nt][2] - mnb); sumb += sacc[nt][2];
                sacc[nt][3] = __expf(sacc[nt][3] - mnb); sumb += sacc[nt][3];
            }
            suma += __shfl_xor_sync(0xffffffffu, suma, 1);
            suma += __shfl_xor_sync(0xffffffffu, suma, 2);
            sumb += __shfl_xor_sync(0xffffffffu, sumb, 1);
            sumb += __shfl_xor_sync(0xffffffffu, sumb, 2);
            l_a = l_a * cca + suma;
            l_b = l_b * ccb + sumb;
#pragma unroll
            for (int nt = 0; nt < 16; nt++) {
                pacc[nt][0] *= cca; pacc[nt][1] *= cca;
                pacc[nt][2] *= ccb; pacc[nt][3] *= ccb;
            }
        }

        // ---- PV: pack P from QK accumulator (C-frag == A-frag layout) ----
#pragma unroll
        for (int ks = 0; ks < 4; ks++) {
            unsigned ph[4], pl[4];
#pragma unroll
            for (int half = 0; half < 2; half++) {
                const float* s0 = sacc[2 * ks + half];
                unsigned p01 = cvt2(s0[1], s0[0]);
                unsigned p23 = cvt2(s0[3], s0[2]);
                float r0 = s0[0] - __uint_as_float(p01 << 16);
                float r1 = s0[1] - __uint_as_float(p01 & 0xFFFF0000u);
                float r2 = s0[2] - __uint_as_float(p23 << 16);
                float r3 = s0[3] - __uint_as_float(p23 & 0xFFFF0000u);
                ph[2 * half + 0] = p01;
                ph[2 * half + 1] = p23;
                pl[2 * half + 0] = cvt2(r1, r0);
                pl[2 * half + 1] = cvt2(r3, r2);
            }
            unsigned phf[4] = { ph[0], ph[1], ph[2], ph[3] };
            unsigned plf[4] = { pl[0], pl[1], pl[2], pl[3] };
#pragma unroll
            for (int dtp = 0; dtp < 8; dtp++) {
                unsigned vh[4], vl[4];
                ldsm4t(vh, kvb + KV_VHI + (ks * 16) * QB + dtp * 32 + offA272);
                ldsm4t(vl, kvb + KV_VLO + (ks * 16) * QB + dtp * 32 + offA272);
                mma16816(pacc[2 * dtp], phf, vh);
                mma16816(pacc[2 * dtp], phf, vl);
                mma16816(pacc[2 * dtp], plf, vh);
                mma16816(pacc[2 * dtp + 1], phf, vh + 2);
                mma16816(pacc[2 * dtp + 1], phf, vl + 2);
                mma16816(pacc[2 * dtp + 1], plf, vh + 2);
            }
        }
    }
    __syncthreads();

    // ---- epilogue: o = O0/l0 - dw * O1/l1 ----
    const float dw = *dwp;
    if (bidx == 1) {
        const float i0 = 1.f / l_a, i1 = 1.f / l_b;
#pragma unroll
        for (int nt = 0; nt < 16; nt++) {
            int d = nt * 8 + fc2;
            *(float2*)&Ot[(ms + fr) * OSR + d] =
                make_float2(pacc[nt][0] * i0, pacc[nt][1] * i0);
            *(float2*)&Ot[(ms + fr + 8) * OSR + d] =
                make_float2(pacc[nt][2] * i1, pacc[nt][3] * i1);
        }
    }
    __syncthreads();
    if (bidx == 0) {
        const float i0 = 1.f / l_a, i1 = 1.f / l_b;
#pragma unroll
        for (int nt = 0; nt < 16; nt++) {
            int d = nt * 8 + fc2;
            float2 t0 = *(float2*)&Ot[(ms + fr) * OSR + d];
            float2 t1 = *(float2*)&Ot[(ms + fr + 8) * OSR + d];
            *(float2*)&Of[(ms + fr) * OSR + d] =
                make_float2(pacc[nt][0] * i0 - dw * t0.x, pacc[nt][1] * i0 - dw * t0.y);
            *(float2*)&Of[(ms + fr + 8) * OSR + d] =
                make_float2(pacc[nt][2] * i1 - dw * t1.x, pacc[nt][3] * i1 - dw * t1.y);
        }
    }
    __syncthreads();

    float* og = o + (rowbase + q0) * EDIM + hd * 128;
#pragma unroll
    for (int i = 0; i < 8; i++) {
        int f = tid + i * 256;
        int r = f >> 5, c4 = f & 31;
        *(float4*)(og + (size_t)r * EDIM + c4 * 4) = *(const float4*)&Of[r * OSR + c4 * 4];
    }
}

// ======================================================================
// RMSNorm over 1024-wide rows, fused split-bf16 output
// ======================================================================
__global__ void __launch_bounds__(256) rmsnorm_split_kernel(
    const float* __restrict__ x, const float* __restrict__ w,
    __nv_bfloat16* __restrict__ yhi, __nv_bfloat16* __restrict__ ylo)
{
    __shared__ float red[8];
    __shared__ float rtot;
    const int tid = threadIdx.x;
    const int row = blockIdx.x;
    const float* xr = x + (size_t)row * EDIM;

    float v[4];
    float s = 0.f;
#pragma unroll
    for (int j = 0; j < 4; j++) {
        v[j] = xr[tid + j * 256];
        s = fmaf(v[j], v[j], s);
    }
#pragma unroll
    for (int off = 16; off > 0; off >>= 1)
        s += __shfl_xor_sync(0xffffffffu, s, off);
    if ((tid & 31) == 0) red[tid >> 5] = s;
    __syncthreads();
    if (tid == 0) {
        float t = 0.f;
#pragma unroll
        for (int i = 0; i < 8; i++) t += red[i];
        rtot = rsqrtf(t * (1.0f / 1024.0f) + 1.1920929e-07f);
    }
    __syncthreads();
    float r = rtot;
#pragma unroll
    for (int j = 0; j < 4; j++) {
        int c = tid + j * 256;
        float f = v[j] * r * w[c];
        __nv_bfloat16 h = __float2bfloat16_rn(f);
        __nv_bfloat16 l = __float2bfloat16_rn(f - __bfloat162float(h));
        yhi[(size_t)row * EDIM + c] = h;
        ylo[(size_t)row * EDIM + c] = l;
    }
}

// ======================================================================
// launcher
// ======================================================================
extern "C" void kernel_launch(void* const* d_in, const int* in_sizes, int n_in,
                              void* d_out, int out_size)
{
    const float* x  = (const float*)d_in[0];
    const float* Wq = (const float*)d_in[1];
    const float* Wk = (const float*)d_in[2];
    const float* Wv = (const float*)d_in[3];
    const float* nw = (const float*)d_in[4];
    const float* Wo = (const float*)d_in[5];
    const float* bo = (const float*)d_in[6];
    const float* dw = (const float*)d_in[7];
    float* out = (float*)d_out;

    float* op;
    cudaGetSymbolAddress((void**)&op, g_o);
    __nv_bfloat16 *xh, *xl, *nh, *nl;
    cudaGetSymbolAddress((void**)&xh, g_xhi);
    cudaGetSymbolAddress((void**)&xl, g_xlo);
    cudaGetSymbolAddress((void**)&nh, g_nhi);
    cudaGetSymbolAddress((void**)&nl, g_nlo);
    __nv_bfloat16 *qh, *ql, *kh, *kl, *vh, *vl;
    cudaGetSymbolAddress((void**)&qh, g_qh);
    cudaGetSymbolAddress((void**)&ql, g_ql);
    cudaGetSymbolAddress((void**)&kh, g_kh);
    cudaGetSymbolAddress((void**)&kl, g_kl);
    cudaGetSymbolAddress((void**)&vh, g_vh);
    cudaGetSymbolAddress((void**)&vl, g_vl);
    __nv_bfloat16 *wqh, *wql, *wkh, *wkl, *wvh, *wvl, *woh, *wol;
    cudaGetSymbolAddress((void**)&wqh, g_wqhi);
    cudaGetSymbolAddress((void**)&wql, g_wqlo);
    cudaGetSymbolAddress((void**)&wkh, g_wkhi);
    cudaGetSymbolAddress((void**)&wkl, g_wklo);
    cudaGetSymbolAddress((void**)&wvh, g_wvhi);
    cudaGetSymbolAddress((void**)&wvl, g_wvlo);
    cudaGetSymbolAddress((void**)&woh, g_wohi);
    cudaGetSymbolAddress((void**)&wol, g_wolo);

    cudaFuncSetAttribute(diff_attn_mma_kernel,
                         cudaFuncAttributeMaxDynamicSharedMemorySize, ATT_SMEM_BYTES);

    // split conversions
    const int xn4 = MROWS * EDIM / 4;
    const int wn4 = EDIM * EDIM / 4;
    split_bf16_kernel<<<xn4 / 256, 256>>>(x,  xh, xl, xn4);
    split_bf16_kernel<<<wn4 / 256, 256>>>(Wq, wqh, wql, wn4);
    split_bf16_kernel<<<wn4 / 256, 256>>>(Wk, wkh, wkl, wn4);
    split_bf16_kernel<<<wn4 / 256, 256>>>(Wv, wvh, wvl, wn4);
    split_bf16_kernel<<<wn4 / 256, 256>>>(Wo, woh, wol, wn4);

    // projections (HMMA split-bf16, direct bf16 hi/lo output)
    dim3 gg(EDIM / 128, MROWS / 128);
    mma_gemm_kernel<<<gg, 256>>>(xh, xl, wqh, wql, nullptr, qh, ql, MROWS, EDIM, EDIM, nullptr, nullptr);
    mma_gemm_kernel<<<gg, 256>>>(xh, xl, wkh, wkl, nullptr, kh, kl, MROWS, EDIM, EDIM, nullptr, nullptr);
    mma_gemm_kernel<<<gg, 256>>>(xh, xl, wvh, wvl, nullptr, vh, vl, MROWS, EDIM, EDIM, nullptr, nullptr);

    // attention (HMMA, register softmax, double-buffered K/V)
    dim3 ga(SLEN / BQ, NHEAD, 2);
    diff_attn_mma_kernel<<<ga, 256, ATT_SMEM_BYTES>>>(qh, ql, kh, kl, vh, vl, op, dw);

    // rmsnorm + split
    rmsnorm_split_kernel<<<MROWS, 256>>>(op, nw, nh, nl);

    // output projection with bias + (1-dw) scale
    mma_gemm_kernel<<<gg, 256>>>(nh, nl, woh, wol, out, nullptr, nullptr, MROWS, EDIM, EDIM, bo, dw);
}

// round 12
// speedup vs baseline: 2.7327x; 1.0773x over previous
#include <cuda_runtime.h>
#include <cuda_bf16.h>
#include <cstdint>
#include <cstddef>
#include <math.h>

#define MROWS 4096           // B*S
#define EDIM  1024
#define SLEN  2048
#define NHEAD 8

// ---------------- warp-level bf16 MMA (m16n8k16, fp32 accum) ----------------
__device__ __forceinline__ void mma16816(
    float* c, const unsigned* a, const unsigned* b)
{
    asm volatile(
        "mma.sync.aligned.m16n8k16.row.col.f32.bf16.bf16.f32 "
        "{%0,%1,%2,%3}, {%4,%5,%6,%7}, {%8,%9}, {%0,%1,%2,%3};"
        : "+f"(c[0]), "+f"(c[1]), "+f"(c[2]), "+f"(c[3])
        : "r"(a[0]), "r"(a[1]), "r"(a[2]), "r"(a[3]), "r"(b[0]), "r"(b[1]));
}
__device__ __forceinline__ void ldsm4(unsigned* r, unsigned addr) {
    asm volatile("ldmatrix.sync.aligned.m8n8.x4.shared.b16 {%0,%1,%2,%3}, [%4];"
        : "=r"(r[0]), "=r"(r[1]), "=r"(r[2]), "=r"(r[3]) : "r"(addr));
}
__device__ __forceinline__ void ldsm4t(unsigned* r, unsigned addr) {
    asm volatile("ldmatrix.sync.aligned.m8n8.x4.trans.shared.b16 {%0,%1,%2,%3}, [%4];"
        : "=r"(r[0]), "=r"(r[1]), "=r"(r[2]), "=r"(r[3]) : "r"(addr));
}
__device__ __forceinline__ unsigned smem_to_u32(const void* p) {
    unsigned a;
    asm("{ .reg .u64 t; cvta.to.shared.u64 t, %1; cvt.u32.u64 %0, t; }" : "=r"(a) : "l"(p));
    return a;
}
// pack two fp32 into bf16x2: low half = lo, high half = hi
__device__ __forceinline__ unsigned cvt2(float hi, float lo) {
    unsigned r; asm("cvt.rn.bf16x2.f32 %0, %1, %2;" : "=r"(r) : "f"(hi), "f"(lo));
    return r;
}
#define CP_ASYNC16(dst_u32, src) \
    asm volatile("cp.async.cg.shared.global [%0], [%1], 16;" :: "r"(dst_u32), "l"(src))
#define CP_COMMIT() asm volatile("cp.async.commit_group;" ::: "memory")
#define CP_WAIT0()  asm volatile("cp.async.wait_group 0;" ::: "memory")
#define CP_WAIT1()  asm volatile("cp.async.wait_group 1;" ::: "memory")

// ---------------- scratch (device globals: allocation-free) ----------------
__device__ float g_o[(size_t)MROWS * EDIM];
__device__ __nv_bfloat16 g_xhi[(size_t)MROWS * EDIM];
__device__ __nv_bfloat16 g_xlo[(size_t)MROWS * EDIM];
__device__ __nv_bfloat16 g_nhi[(size_t)MROWS * EDIM];
__device__ __nv_bfloat16 g_nlo[(size_t)MROWS * EDIM];
__device__ __nv_bfloat16 g_qh[(size_t)MROWS * EDIM];
__device__ __nv_bfloat16 g_ql[(size_t)MROWS * EDIM];
__device__ __nv_bfloat16 g_kh[(size_t)MROWS * EDIM];
__device__ __nv_bfloat16 g_kl[(size_t)MROWS * EDIM];
__device__ __nv_bfloat16 g_vh[(size_t)MROWS * EDIM];
__device__ __nv_bfloat16 g_vl[(size_t)MROWS * EDIM];
__device__ __nv_bfloat16 g_wqhi[(size_t)EDIM * EDIM];
__device__ __nv_bfloat16 g_wqlo[(size_t)EDIM * EDIM];
__device__ __nv_bfloat16 g_wkhi[(size_t)EDIM * EDIM];
__device__ __nv_bfloat16 g_wklo[(size_t)EDIM * EDIM];
__device__ __nv_bfloat16 g_wvhi[(size_t)EDIM * EDIM];
__device__ __nv_bfloat16 g_wvlo[(size_t)EDIM * EDIM];
__device__ __nv_bfloat16 g_wohi[(size_t)EDIM * EDIM];
__device__ __nv_bfloat16 g_wolo[(size_t)EDIM * EDIM];

// ======================================================================
// fp32 -> (bf16 hi, bf16 lo) split, vectorized float4
// ======================================================================
__global__ void __launch_bounds__(256) split_bf16_kernel(
    const float* __restrict__ x, __nv_bfloat16* __restrict__ hi,
    __nv_bfloat16* __restrict__ lo, int n4)
{
    int i = blockIdx.x * 256 + threadIdx.x;
    if (i >= n4) return;
    float4 v = ((const float4*)x)[i];
    float vv[4] = { v.x, v.y, v.z, v.w };
    __nv_bfloat16 h[4], l[4];
#pragma unroll
    for (int j = 0; j < 4; j++) {
        h[j] = __float2bfloat16_rn(vv[j]);
        l[j] = __float2bfloat16_rn(vv[j] - __bfloat162float(h[j]));
    }
    __nv_bfloat162* hp = (__nv_bfloat162*)hi;
    __nv_bfloat162* lp = (__nv_bfloat162*)lo;
    hp[i * 2 + 0] = __nv_bfloat162(h[0], h[1]);
    hp[i * 2 + 1] = __nv_bfloat162(h[2], h[3]);
    lp[i * 2 + 0] = __nv_bfloat162(l[0], l[1]);
    lp[i * 2 + 1] = __nv_bfloat162(l[2], l[3]);
}

// ======================================================================
// HMMA split-bf16 GEMM: C = A[M,K] @ B[N,K]^T
// cp.async double-buffered BK=16, ldmatrix fragment loads.
// ======================================================================
#define TS 24   // smem row stride in bf16 (48B) -> conflict-free ldmatrix

__global__ void __launch_bounds__(256) mma_gemm_kernel(
    const __nv_bfloat16* __restrict__ Ahi, const __nv_bfloat16* __restrict__ Alo,
    const __nv_bfloat16* __restrict__ Bhi, const __nv_bfloat16* __restrict__ Blo,
    float* __restrict__ Cf, __nv_bfloat16* __restrict__ Chi, __nv_bfloat16* __restrict__ Clo,
    int M, int N, int K,
    const float* __restrict__ bias, const float* __restrict__ dwp)
{
    __shared__ __nv_bfloat16 sA[2][2][128 * TS];   // [buf][hi/lo]
    __shared__ __nv_bfloat16 sB[2][2][128 * TS];

    const int tid = threadIdx.x;
    const int wid = tid >> 5, L = tid & 31;
    const int bm = blockIdx.y * 128, bn = blockIdx.x * 128;
    const int wm = (wid >> 2) * 64, wn = (wid & 3) * 32;

    const int lrow = tid >> 1;            // 0..127
    const int lseg = (tid & 1) * 8;       // 0 or 8 (bf16)

    const int fr = L >> 2;                // 0..7
    const int fc = (L & 3) * 2;           // 0,2,4,6
    const int lm = L >> 3, lr = L & 7;
    const unsigned offA = (unsigned)((lr + ((lm & 1) << 3)) * 48 + ((lm >> 1) << 4));
    const unsigned offB = (unsigned)((lr + ((lm >> 1) << 3)) * 48 + ((lm & 1) << 4));

    float acc[4][4][4];
#pragma unroll
    for (int mt = 0; mt < 4; mt++)
#pragma unroll
        for (int nt = 0; nt < 4; nt++)
#pragma unroll
            for (int e = 0; e < 4; e++) acc[mt][nt][e] = 0.f;

    const int nchunks = K / 16;

    {
        unsigned d0 = smem_to_u32(&sA[0][0][lrow * TS + lseg]);
        unsigned d1 = smem_to_u32(&sA[0][1][lrow * TS + lseg]);
        unsigned d2 = smem_to_u32(&sB[0][0][lrow * TS + lseg]);
        unsigned d3 = smem_to_u32(&sB[0][1][lrow * TS + lseg]);
        CP_ASYNC16(d0, Ahi + (size_t)(bm + lrow) * K + lseg);
        CP_ASYNC16(d1, Alo + (size_t)(bm + lrow) * K + lseg);
        CP_ASYNC16(d2, Bhi + (size_t)(bn + lrow) * K + lseg);
        CP_ASYNC16(d3, Blo + (size_t)(bn + lrow) * K + lseg);
        CP_COMMIT();
    }

    for (int c = 0; c < nchunks; c++) {
        CP_WAIT0();
        __syncthreads();
        const int buf = c & 1;
        if (c + 1 < nchunks) {
            const int nb = (c + 1) & 1;
            const int kc = (c + 1) * 16;
            unsigned d0 = smem_to_u32(&sA[nb][0][lrow * TS + lseg]);
            unsigned d1 = smem_to_u32(&sA[nb][1][lrow * TS + lseg]);
            unsigned d2 = smem_to_u32(&sB[nb][0][lrow * TS + lseg]);
            unsigned d3 = smem_to_u32(&sB[nb][1][lrow * TS + lseg]);
            CP_ASYNC16(d0, Ahi + (size_t)(bm + lrow) * K + kc + lseg);
            CP_ASYNC16(d1, Alo + (size_t)(bm + lrow) * K + kc + lseg);
            CP_ASYNC16(d2, Bhi + (size_t)(bn + lrow) * K + kc + lseg);
            CP_ASYNC16(d3, Blo + (size_t)(bn + lrow) * K + kc + lseg);
            CP_COMMIT();
        }

        unsigned bh[4][2], bl[4][2];
#pragma unroll
        for (int ntp = 0; ntp < 2; ntp++) {
            unsigned t[4];
            ldsm4(t, smem_to_u32(&sB[buf][0][(wn + ntp * 16) * TS]) + offB);
            bh[2 * ntp][0] = t[0]; bh[2 * ntp][1] = t[1];
            bh[2 * ntp + 1][0] = t[2]; bh[2 * ntp + 1][1] = t[3];
            ldsm4(t, smem_to_u32(&sB[buf][1][(wn + ntp * 16) * TS]) + offB);
            bl[2 * ntp][0] = t[0]; bl[2 * ntp][1] = t[1];
            bl[2 * ntp + 1][0] = t[2]; bl[2 * ntp + 1][1] = t[3];
        }
#pragma unroll
        for (int mt = 0; mt < 4; mt++) {
            unsigned ah[4], al[4];
            ldsm4(ah, smem_to_u32(&sA[buf][0][(wm + mt * 16) * TS]) + offA);
            ldsm4(al, smem_to_u32(&sA[buf][1][(wm + mt * 16) * TS]) + offA);
#pragma unroll
            for (int nt = 0; nt < 4; nt++) {
                mma16816(acc[mt][nt], ah, bh[nt]);
                mma16816(acc[mt][nt], ah, bl[nt]);
                mma16816(acc[mt][nt], al, bh[nt]);
            }
        }
    }

    if (Cf) {
        float sc = 1.0f;
        if (dwp) sc = 1.0f - *dwp;
#pragma unroll
        for (int mt = 0; mt < 4; mt++) {
#pragma unroll
            for (int nt = 0; nt < 4; nt++) {
                int row = bm + wm + mt * 16 + fr;
                int col = bn + wn + nt * 8 + fc;
                float b0 = 0.f, b1 = 0.f;
                if (bias) { b0 = bias[col]; b1 = bias[col + 1]; }
                float2 r0, r1;
                r0.x = (acc[mt][nt][0] + b0) * sc;
                r0.y = (acc[mt][nt][1] + b1) * sc;
                r1.x = (acc[mt][nt][2] + b0) * sc;
                r1.y = (acc[mt][nt][3] + b1) * sc;
                *(float2*)(Cf + (size_t)row * N + col) = r0;
                *(float2*)(Cf + (size_t)(row + 8) * N + col) = r1;
            }
        }
    } else {
#pragma unroll
        for (int mt = 0; mt < 4; mt++) {
#pragma unroll
            for (int nt = 0; nt < 4; nt++) {
                int row = bm + wm + mt * 16 + fr;
                int col = bn + wn + nt * 8 + fc;
#pragma unroll
                for (int half = 0; half < 2; half++) {
                    float v0 = acc[mt][nt][half * 2 + 0];
                    float v1 = acc[mt][nt][half * 2 + 1];
                    __nv_bfloat16 h0 = __float2bfloat16_rn(v0);
                    __nv_bfloat16 h1 = __float2bfloat16_rn(v1);
                    __nv_bfloat16 l0 = __float2bfloat16_rn(v0 - __bfloat162float(h0));
                    __nv_bfloat16 l1 = __float2bfloat16_rn(v1 - __bfloat162float(h1));
                    size_t off = (size_t)(row + half * 8) * N + col;
                    *(__nv_bfloat162*)(Chi + off) = __nv_bfloat162(h0, h1);
                    *(__nv_bfloat162*)(Clo + off) = __nv_bfloat162(l0, l1);
                }
            }
        }
    }
}

// ======================================================================
// HMMA differential flash attention, BQ=128 (two 64-row q strips per CTA),
// register-resident softmax, double-buffered cp.async K/V, V-fragment reuse.
// CTA: (b, h, 128-q tile), 8 warps. Warps 0-3: branch0, 4-7: branch1.
// ======================================================================
#define BQ 128
#define BKT 64
#define QB  272   // byte stride for Q/K/V bf16 tiles (136 bf16)
#define OSR 132   // fp32 stride for O staging

#define OFF_QHI  0
#define OFF_QLO  34816
#define OFF_KV   69632       // 2 buffers x 4 tiles x 17408 bytes
#define KV_BUF   69632       // bytes per buffer set
#define KV_KHI   0
#define KV_KLO   17408
#define KV_VHI   34816
#define KV_VLO   52224
#define ATT_SMEM_BYTES (OFF_KV + 2 * KV_BUF)   // 208896

__global__ void __launch_bounds__(256) diff_attn_mma_kernel(
    const __nv_bfloat16* __restrict__ qh_g, const __nv_bfloat16* __restrict__ ql_g,
    const __nv_bfloat16* __restrict__ kh_g, const __nv_bfloat16* __restrict__ kl_g,
    const __nv_bfloat16* __restrict__ vh_g, const __nv_bfloat16* __restrict__ vl_g,
    float* __restrict__ o, const float* __restrict__ dwp)
{
    extern __shared__ char smem[];
    const unsigned su = smem_to_u32(smem);
    float* Ot = (float*)(smem + OFF_KV);              // post-loop staging (buf0)
    float* Of = (float*)(smem + OFF_KV + KV_BUF);     // post-loop combine (buf1)

    const int tid = threadIdx.x;
    const int wid = tid >> 5, L = tid & 31;
    const int fr = L >> 2;           // 0..7
    const int lm = L >> 3, lr = L & 7;
    const int qt = blockIdx.x, hd = blockIdx.y, b = blockIdx.z;
    const int q0 = qt * BQ;
    const int bidx = wid >> 2;       // branch
    const int ws = wid & 3;          // warp slot -> q rows ms..ms+15 within strip
    const int ms = ws * 16;
    const int fc2 = (L & 3) * 2;

    const unsigned offA272 = (unsigned)((lr + ((lm & 1) << 3)) * QB + ((lm >> 1) << 4));
    const unsigned offB272 = (unsigned)((lr + ((lm >> 1) << 3)) * QB + ((lm & 1) << 4));

    const size_t rowbase = (size_t)b * SLEN;

    // ---- load Q tile (hi/lo), 128 x 128 bf16 each ----
#pragma unroll
    for (int i = 0; i < 8; i++) {
        int f = tid + i * 256;               // 0..2047
        int r = f >> 4, c = f & 15;
        size_t src = (rowbase + q0 + r) * EDIM + hd * 128 + c * 8;
        *(uint4*)(smem + OFF_QHI + r * QB + c * 16) = *(const uint4*)(qh_g + src);
        *(uint4*)(smem + OFF_QLO + r * QB + c * 16) = *(const uint4*)(ql_g + src);
    }

    float mA[2] = { -1e30f, -1e30f }, mB[2] = { -1e30f, -1e30f };
    float lA[2] = { 0.f, 0.f }, lB[2] = { 0.f, 0.f };
    float pacc[2][16][4];
#pragma unroll
    for (int s = 0; s < 2; s++)
#pragma unroll
        for (int nt = 0; nt < 16; nt++)
#pragma unroll
            for (int e = 0; e < 4; e++) pacc[s][nt][e] = 0.f;

    unsigned Pfh[2][4][4], Pfl[2][4][4];

    const float scale = 0.125f;
    const int NT = SLEN / BKT;   // 32

    // issue tile 0 into buffer 0
    {
        const unsigned kvb = su + OFF_KV;
#pragma unroll
        for (int i = 0; i < 4; i++) {
            int f = tid + i * 256;
            int r = f >> 4, c = f & 15;
            size_t src = (rowbase + r) * EDIM + hd * 128 + c * 8;
            unsigned dsm = kvb + r * QB + c * 16;
            CP_ASYNC16(dsm + KV_KHI, kh_g + src);
            CP_ASYNC16(dsm + KV_KLO, kl_g + src);
            CP_ASYNC16(dsm + KV_VHI, vh_g + src);
            CP_ASYNC16(dsm + KV_VLO, vl_g + src);
        }
        CP_COMMIT();
    }

    for (int t = 0; t < NT; t++) {
        if (t > 0) __syncthreads();
        if (t + 1 < NT) {
            const unsigned kvb = su + OFF_KV + ((t + 1) & 1) * KV_BUF;
            const int kt1 = (t + 1) * BKT;
#pragma unroll
            for (int i = 0; i < 4; i++) {
                int f = tid + i * 256;
                int r = f >> 4, c = f & 15;
                size_t src = (rowbase + kt1 + r) * EDIM + hd * 128 + c * 8;
                unsigned dsm = kvb + r * QB + c * 16;
                CP_ASYNC16(dsm + KV_KHI, kh_g + src);
                CP_ASYNC16(dsm + KV_KLO, kl_g + src);
                CP_ASYNC16(dsm + KV_VHI, vh_g + src);
                CP_ASYNC16(dsm + KV_VLO, vl_g + src);
            }
            CP_COMMIT();
            CP_WAIT1();
        } else {
            CP_WAIT0();
        }
        __syncthreads();

        const unsigned kvb = su + OFF_KV + (t & 1) * KV_BUF;

        // ---- per strip: QK^T + softmax + P pack ----
#pragma unroll
        for (int s = 0; s < 2; s++) {
            float sacc[8][4];
#pragma unroll
            for (int nt = 0; nt < 8; nt++)
#pragma unroll
                for (int e = 0; e < 4; e++) sacc[nt][e] = 0.f;

            const unsigned qrow = (unsigned)((s * 64 + ms) * QB);
#pragma unroll
            for (int ks = 0; ks < 4; ks++) {
                const unsigned kofb = (unsigned)(bidx * 128 + ks * 32);
                unsigned ah[4], al[4];
                ldsm4(ah, su + OFF_QHI + qrow + kofb + offA272);
                ldsm4(al, su + OFF_QLO + qrow + kofb + offA272);
#pragma unroll
                for (int ntp = 0; ntp < 4; ntp++) {
                    unsigned th[4], tl[4];
                    ldsm4(th, kvb + KV_KHI + (ntp * 16) * QB + kofb + offB272);
                    ldsm4(tl, kvb + KV_KLO + (ntp * 16) * QB + kofb + offB272);
                    mma16816(sacc[2 * ntp], ah, th);
                    mma16816(sacc[2 * ntp], ah, tl);
                    mma16816(sacc[2 * ntp], al, th);
                    mma16816(sacc[2 * ntp + 1], ah, th + 2);
                    mma16816(sacc[2 * ntp + 1], ah, tl + 2);
                    mma16816(sacc[2 * ntp + 1], al, th + 2);
                }
            }
#pragma unroll
            for (int nt = 0; nt < 8; nt++)
#pragma unroll
                for (int e = 0; e < 4; e++) sacc[nt][e] *= scale;

            // register-resident online softmax for this strip
            {
                float ra = -1e30f, rb = -1e30f;
#pragma unroll
                for (int nt = 0; nt < 8; nt++) {
                    ra = fmaxf(ra, fmaxf(sacc[nt][0], sacc[nt][1]));
                    rb = fmaxf(rb, fmaxf(sacc[nt][2], sacc[nt][3]));
                }
                ra = fmaxf(ra, __shfl_xor_sync(0xffffffffu, ra, 1));
                ra = fmaxf(ra, __shfl_xor_sync(0xffffffffu, ra, 2));
                rb = fmaxf(rb, __shfl_xor_sync(0xffffffffu, rb, 1));
                rb = fmaxf(rb, __shfl_xor_sync(0xffffffffu, rb, 2));
                float mna = fmaxf(mA[s], ra), mnb = fmaxf(mB[s], rb);
                float cca = __expf(mA[s] - mna), ccb = __expf(mB[s] - mnb);
                mA[s] = mna; mB[s] = mnb;
                float suma = 0.f, sumb = 0.f;
#pragma unroll
                for (int nt = 0; nt < 8; nt++) {
                    sacc[nt][0] = __expf(sacc[nt][0] - mna); suma += sacc[nt][0];
                    sacc[nt][1] = __expf(sacc[nt][1] - mna); suma += sacc[nt][1];
                    sacc[nt][2] = __expf(sacc[nt][2] - mnb); sumb += sacc[nt][2];
                    sacc[nt][3] = __expf(sacc[nt][3] - mnb); sumb += sacc[nt][3];
                }
                suma += __shfl_xor_sync(0xffffffffu, suma, 1);
                suma += __shfl_xor_sync(0xffffffffu, suma, 2);
                sumb += __shfl_xor_sync(0xffffffffu, sumb, 1);
                sumb += __shfl_xor_sync(0xffffffffu, sumb, 2);
                lA[s] = lA[s] * cca + suma;
                lB[s] = lB[s] * ccb + sumb;
#pragma unroll
                for (int nt = 0; nt < 16; nt++) {
                    pacc[s][nt][0] *= cca; pacc[s][nt][1] *= cca;
                    pacc[s][nt][2] *= ccb; pacc[s][nt][3] *= ccb;
                }
            }

            // pack P into register A-fragments (C-frag == A-frag layout)
#pragma unroll
            for (int ks = 0; ks < 4; ks++) {
#pragma unroll
                for (int half = 0; half < 2; half++) {
                    const float* s0 = sacc[2 * ks + half];
                    unsigned p01 = cvt2(s0[1], s0[0]);
                    unsigned p23 = cvt2(s0[3], s0[2]);
                    float r0 = s0[0] - __uint_as_float(p01 << 16);
                    float r1 = s0[1] - __uint_as_float(p01 & 0xFFFF0000u);
                    float r2 = s0[2] - __uint_as_float(p23 << 16);
                    float r3 = s0[3] - __uint_as_float(p23 & 0xFFFF0000u);
                    Pfh[s][ks][2 * half + 0] = p01;
                    Pfh[s][ks][2 * half + 1] = p23;
                    Pfl[s][ks][2 * half + 0] = cvt2(r1, r0);
                    Pfl[s][ks][2 * half + 1] = cvt2(r3, r2);
                }
            }
        }

        // ---- PV: V fragments shared across both strips ----
#pragma unroll
        for (int ks = 0; ks < 4; ks++) {
#pragma unroll
            for (int dtp = 0; dtp < 8; dtp++) {
                unsigned vh[4], vl[4];
                ldsm4t(vh, kvb + KV_VHI + (ks * 16) * QB + dtp * 32 + offA272);
                ldsm4t(vl, kvb + KV_VLO + (ks * 16) * QB + dtp * 32 + offA272);
#pragma unroll
                for (int s = 0; s < 2; s++) {
                    mma16816(pacc[s][2 * dtp], Pfh[s][ks], vh);
                    mma16816(pacc[s][2 * dtp], Pfh[s][ks], vl);
                    mma16816(pacc[s][2 * dtp], Pfl[s][ks], vh);
                    mma16816(pacc[s][2 * dtp + 1], Pfh[s][ks], vh + 2);
                    mma16816(pacc[s][2 * dtp + 1], Pfh[s][ks], vl + 2);
                    mma16816(pacc[s][2 * dtp + 1], Pfl[s][ks], vh + 2);
                }
            }
        }
    }
    __syncthreads();

    // ---- epilogue: o = O0/l0 - dw * O1/l1 ----
    const float dw = *dwp;
    if (bidx == 1) {
#pragma unroll
        for (int s = 0; s < 2; s++) {
            const float i0 = 1.f / lA[s], i1 = 1.f / lB[s];
            const int r0 = s * 64 + ms + fr;
#pragma unroll
            for (int nt = 0; nt < 16; nt++) {
                int d = nt * 8 + fc2;
                *(float2*)&Ot[r0 * OSR + d] =
                    make_float2(pacc[s][nt][0] * i0, pacc[s][nt][1] * i0);
                *(float2*)&Ot[(r0 + 8) * OSR + d] =
                    make_float2(pacc[s][nt][2] * i1, pacc[s][nt][3] * i1);
            }
        }
    }
    __syncthreads();
    if (bidx == 0) {
#pragma unroll
        for (int s = 0; s < 2; s++) {
            const float i0 = 1.f / lA[s], i1 = 1.f / lB[s];
            const int r0 = s * 64 + ms + fr;
#pragma unroll
            for (int nt = 0; nt < 16; nt++) {
                int d = nt * 8 + fc2;
                float2 t0 = *(float2*)&Ot[r0 * OSR + d];
                float2 t1 = *(float2*)&Ot[(r0 + 8) * OSR + d];
                *(float2*)&Of[r0 * OSR + d] =
                    make_float2(pacc[s][nt][0] * i0 - dw * t0.x,
                                pacc[s][nt][1] * i0 - dw * t0.y);
                *(float2*)&Of[(r0 + 8) * OSR + d] =
                    make_float2(pacc[s][nt][2] * i1 - dw * t1.x,
                                pacc[s][nt][3] * i1 - dw * t1.y);
            }
        }
    }
    __syncthreads();

    float* og = o + (rowbase + q0) * EDIM + hd * 128;
#pragma unroll
    for (int i = 0; i < 16; i++) {
        int f = tid + i * 256;
        int r = f >> 5, c4 = f & 31;
        *(float4*)(og + (size_t)r * EDIM + c4 * 4) = *(const float4*)&Of[r * OSR + c4 * 4];
    }
}

// ======================================================================
// RMSNorm over 1024-wide rows, fused split-bf16 output
// ======================================================================
__global__ void __launch_bounds__(256) rmsnorm_split_kernel(
    const float* __restrict__ x, const float* __restrict__ w,
    __nv_bfloat16* __restrict__ yhi, __nv_bfloat16* __restrict__ ylo)
{
    __shared__ float red[8];
    __shared__ float rtot;
    const int tid = threadIdx.x;
    const int row = blockIdx.x;
    const float* xr = x + (size_t)row * EDIM;

    float v[4];
    float s = 0.f;
#pragma unroll
    for (int j = 0; j < 4; j++) {
        v[j] = xr[tid + j * 256];
        s = fmaf(v[j], v[j], s);
    }
#pragma unroll
    for (int off = 16; off > 0; off >>= 1)
        s += __shfl_xor_sync(0xffffffffu, s, off);
    if ((tid & 31) == 0) red[tid >> 5] = s;
    __syncthreads();
    if (tid == 0) {
        float t = 0.f;
#pragma unroll
        for (int i = 0; i < 8; i++) t += red[i];
        rtot = rsqrtf(t * (1.0f / 1024.0f) + 1.1920929e-07f);
    }
    __syncthreads();
    float r = rtot;
#pragma unroll
    for (int j = 0; j < 4; j++) {
        int c = tid + j * 256;
        float f = v[j] * r * w[c];
        __nv_bfloat16 h = __float2bfloat16_rn(f);
        __nv_bfloat16 l = __float2bfloat16_rn(f - __bfloat162float(h));
        yhi[(size_t)row * EDIM + c] = h;
        ylo[(size_t)row * EDIM + c] = l;
    }
}

// ======================================================================
// launcher
// ======================================================================
extern "C" void kernel_launch(void* const* d_in, const int* in_sizes, int n_in,
                              void* d_out, int out_size)
{
    const float* x  = (const float*)d_in[0];
    const float* Wq = (const float*)d_in[1];
    const float* Wk = (const float*)d_in[2];
    const float* Wv = (const float*)d_in[3];
    const float* nw = (const float*)d_in[4];
    const float* Wo = (const float*)d_in[5];
    const float* bo = (const float*)d_in[6];
    const float* dw = (const float*)d_in[7];
    float* out = (float*)d_out;

    float* op;
    cudaGetSymbolAddress((void**)&op, g_o);
    __nv_bfloat16 *xh, *xl, *nh, *nl;
    cudaGetSymbolAddress((void**)&xh, g_xhi);
    cudaGetSymbolAddress((void**)&xl, g_xlo);
    cudaGetSymbolAddress((void**)&nh, g_nhi);
    cudaGetSymbolAddress((void**)&nl, g_nlo);
    __nv_bfloat16 *qh, *ql, *kh, *kl, *vh, *vl;
    cudaGetSymbolAddress((void**)&qh, g_qh);
    cudaGetSymbolAddress((void**)&ql, g_ql);
    cudaGetSymbolAddress((void**)&kh, g_kh);
    cudaGetSymbolAddress((void**)&kl, g_kl);
    cudaGetSymbolAddress((void**)&vh, g_vh);
    cudaGetSymbolAddress((void**)&vl, g_vl);
    __nv_bfloat16 *wqh, *wql, *wkh, *wkl, *wvh, *wvl, *woh, *wol;
    cudaGetSymbolAddress((void**)&wqh, g_wqhi);
    cudaGetSymbolAddress((void**)&wql, g_wqlo);
    cudaGetSymbolAddress((void**)&wkh, g_wkhi);
    cudaGetSymbolAddress((void**)&wkl, g_wklo);
    cudaGetSymbolAddress((void**)&wvh, g_wvhi);
    cudaGetSymbolAddress((void**)&wvl, g_wvlo);
    cudaGetSymbolAddress((void**)&woh, g_wohi);
    cudaGetSymbolAddress((void**)&wol, g_wolo);

    cudaFuncSetAttribute(diff_attn_mma_kernel,
                         cudaFuncAttributeMaxDynamicSharedMemorySize, ATT_SMEM_BYTES);

    // split conversions
    const int xn4 = MROWS * EDIM / 4;
    const int wn4 = EDIM * EDIM / 4;
    split_bf16_kernel<<<xn4 / 256, 256>>>(x,  xh, xl, xn4);
    split_bf16_kernel<<<wn4 / 256, 256>>>(Wq, wqh, wql, wn4);
    split_bf16_kernel<<<wn4 / 256, 256>>>(Wk, wkh, wkl, wn4);
    split_bf16_kernel<<<wn4 / 256, 256>>>(Wv, wvh, wvl, wn4);
    split_bf16_kernel<<<wn4 / 256, 256>>>(Wo, woh, wol, wn4);

    // projections (HMMA split-bf16, direct bf16 hi/lo output)
    dim3 gg(EDIM / 128, MROWS / 128);
    mma_gemm_kernel<<<gg, 256>>>(xh, xl, wqh, wql, nullptr, qh, ql, MROWS, EDIM, EDIM, nullptr, nullptr);
    mma_gemm_kernel<<<gg, 256>>>(xh, xl, wkh, wkl, nullptr, kh, kl, MROWS, EDIM, EDIM, nullptr, nullptr);
    mma_gemm_kernel<<<gg, 256>>>(xh, xl, wvh, wvl, nullptr, vh, vl, MROWS, EDIM, EDIM, nullptr, nullptr);

    // attention (HMMA, BQ=128, register softmax, double-buffered K/V)
    dim3 ga(SLEN / BQ, NHEAD, 2);
    diff_attn_mma_kernel<<<ga, 256, ATT_SMEM_BYTES>>>(qh, ql, kh, kl, vh, vl, op, dw);

    // rmsnorm + split
    rmsnorm_split_kernel<<<MROWS, 256>>>(op, nw, nh, nl);

    // output projection with bias + (1-dw) scale
    mma_gemm_kernel<<<gg, 256>>>(nh, nl, woh, wol, out, nullptr, nullptr, MROWS, EDIM, EDIM, bo, dw);
}

// round 13
// speedup vs baseline: 3.1015x; 1.1350x over previous
#include <cuda_runtime.h>
#include <cuda_bf16.h>
#include <cstdint>
#include <cstddef>
#include <math.h>

#define MROWS 4096           // B*S
#define EDIM  1024
#define SLEN  2048
#define NHEAD 8

// ---------------- warp-level bf16 MMA (m16n8k16, fp32 accum) ----------------
__device__ __forceinline__ void mma16816(
    float* c, const unsigned* a, const unsigned* b)
{
    asm volatile(
        "mma.sync.aligned.m16n8k16.row.col.f32.bf16.bf16.f32 "
        "{%0,%1,%2,%3}, {%4,%5,%6,%7}, {%8,%9}, {%0,%1,%2,%3};"
        : "+f"(c[0]), "+f"(c[1]), "+f"(c[2]), "+f"(c[3])
        : "r"(a[0]), "r"(a[1]), "r"(a[2]), "r"(a[3]), "r"(b[0]), "r"(b[1]));
}
__device__ __forceinline__ void ldsm4(unsigned* r, unsigned addr) {
    asm volatile("ldmatrix.sync.aligned.m8n8.x4.shared.b16 {%0,%1,%2,%3}, [%4];"
        : "=r"(r[0]), "=r"(r[1]), "=r"(r[2]), "=r"(r[3]) : "r"(addr));
}
__device__ __forceinline__ void ldsm4t(unsigned* r, unsigned addr) {
    asm volatile("ldmatrix.sync.aligned.m8n8.x4.trans.shared.b16 {%0,%1,%2,%3}, [%4];"
        : "=r"(r[0]), "=r"(r[1]), "=r"(r[2]), "=r"(r[3]) : "r"(addr));
}
__device__ __forceinline__ unsigned smem_to_u32(const void* p) {
    unsigned a;
    asm("{ .reg .u64 t; cvta.to.shared.u64 t, %1; cvt.u32.u64 %0, t; }" : "=r"(a) : "l"(p));
    return a;
}
// pack two fp32 into bf16x2: low half = lo, high half = hi
__device__ __forceinline__ unsigned cvt2(float hi, float lo) {
    unsigned r; asm("cvt.rn.bf16x2.f32 %0, %1, %2;" : "=r"(r) : "f"(hi), "f"(lo));
    return r;
}
#define CP_ASYNC16(dst_u32, src) \
    asm volatile("cp.async.cg.shared.global [%0], [%1], 16;" :: "r"(dst_u32), "l"(src))
#define CP_COMMIT() asm volatile("cp.async.commit_group;" ::: "memory")
#define CP_WAIT0()  asm volatile("cp.async.wait_group 0;" ::: "memory")
#define CP_WAIT1()  asm volatile("cp.async.wait_group 1;" ::: "memory")

// ---------------- scratch (device globals: allocation-free) ----------------
__device__ float g_o[(size_t)MROWS * EDIM];
__device__ __nv_bfloat16 g_xhi[(size_t)MROWS * EDIM];
__device__ __nv_bfloat16 g_xlo[(size_t)MROWS * EDIM];
__device__ __nv_bfloat16 g_nhi[(size_t)MROWS * EDIM];
__device__ __nv_bfloat16 g_nlo[(size_t)MROWS * EDIM];
__device__ __nv_bfloat16 g_qh[(size_t)MROWS * EDIM];
__device__ __nv_bfloat16 g_ql[(size_t)MROWS * EDIM];
__device__ __nv_bfloat16 g_kh[(size_t)MROWS * EDIM];
__device__ __nv_bfloat16 g_kl[(size_t)MROWS * EDIM];
__device__ __nv_bfloat16 g_vh[(size_t)MROWS * EDIM];
__device__ __nv_bfloat16 g_vl[(size_t)MROWS * EDIM];
__device__ __nv_bfloat16 g_wqhi[(size_t)EDIM * EDIM];
__device__ __nv_bfloat16 g_wqlo[(size_t)EDIM * EDIM];
__device__ __nv_bfloat16 g_wkhi[(size_t)EDIM * EDIM];
__device__ __nv_bfloat16 g_wklo[(size_t)EDIM * EDIM];
__device__ __nv_bfloat16 g_wvhi[(size_t)EDIM * EDIM];
__device__ __nv_bfloat16 g_wvlo[(size_t)EDIM * EDIM];
__device__ __nv_bfloat16 g_wohi[(size_t)EDIM * EDIM];
__device__ __nv_bfloat16 g_wolo[(size_t)EDIM * EDIM];

struct QKVPtrs {
    const __nv_bfloat16* Bh[3];
    const __nv_bfloat16* Bl[3];
    __nv_bfloat16* Ch[3];
    __nv_bfloat16* Cl[3];
};

// ======================================================================
// fp32 -> (bf16 hi, bf16 lo) split, vectorized float4
// ======================================================================
__global__ void __launch_bounds__(256) split_bf16_kernel(
    const float* __restrict__ x, __nv_bfloat16* __restrict__ hi,
    __nv_bfloat16* __restrict__ lo, int n4)
{
    int i = blockIdx.x * 256 + threadIdx.x;
    if (i >= n4) return;
    float4 v = ((const float4*)x)[i];
    float vv[4] = { v.x, v.y, v.z, v.w };
    __nv_bfloat16 h[4], l[4];
#pragma unroll
    for (int j = 0; j < 4; j++) {
        h[j] = __float2bfloat16_rn(vv[j]);
        l[j] = __float2bfloat16_rn(vv[j] - __bfloat162float(h[j]));
    }
    __nv_bfloat162* hp = (__nv_bfloat162*)hi;
    __nv_bfloat162* lp = (__nv_bfloat162*)lo;
    hp[i * 2 + 0] = __nv_bfloat162(h[0], h[1]);
    hp[i * 2 + 1] = __nv_bfloat162(h[2], h[3]);
    lp[i * 2 + 0] = __nv_bfloat162(l[0], l[1]);
    lp[i * 2 + 1] = __nv_bfloat162(l[2], l[3]);
}

// ======================================================================
// HMMA split-bf16 GEMM, BK=32, cp.async double-buffered, dynamic smem.
// Fused multi-weight: sel = blockIdx.x>>3 picks (B, C) pair. Optional fp32
// epilogue (bias + (1-dw) scale) when Cf != nullptr (uses pair 0).
// ======================================================================
#define GTS   40                    // bf16 row stride (80 B)
#define GTILE (128 * GTS * 2)       // 10240 bytes per tile
#define GBUF  (4 * GTILE)           // 40960 bytes per buffer (Ah, Al, Bh, Bl)
#define GSMEM_BYTES (2 * GBUF)      // 81920

__global__ void __launch_bounds__(256, 2) mma_gemm_kernel(
    const __nv_bfloat16* __restrict__ Ahi, const __nv_bfloat16* __restrict__ Alo,
    QKVPtrs p, float* __restrict__ Cf,
    const float* __restrict__ bias, const float* __restrict__ dwp)
{
    extern __shared__ char gsm[];
    const unsigned su = smem_to_u32(gsm);

    const int tid = threadIdx.x;
    const int wid = tid >> 5, L = tid & 31;
    const int sel = blockIdx.x >> 3;
    const int bm = blockIdx.y * 128, bn = (blockIdx.x & 7) * 128;
    const int wm = (wid >> 2) * 64, wn = (wid & 3) * 32;
    const __nv_bfloat16* __restrict__ Bhi = p.Bh[sel];
    const __nv_bfloat16* __restrict__ Blo = p.Bl[sel];

    const int lrow = tid >> 1;                 // 0..127
    const int lcol = (tid & 1) * 16;           // bf16 offset within 32
    const unsigned soff = (unsigned)(lrow * 80 + (tid & 1) * 32);

    const int fr = L >> 2, fc = (L & 3) * 2;
    const int lm = L >> 3, lr = L & 7;
    const unsigned offA = (unsigned)((lr + ((lm & 1) << 3)) * 80 + ((lm >> 1) << 4));
    const unsigned offB = (unsigned)((lr + ((lm >> 1) << 3)) * 80 + ((lm & 1) << 4));

    float acc[4][4][4];
#pragma unroll
    for (int mt = 0; mt < 4; mt++)
#pragma unroll
        for (int nt = 0; nt < 4; nt++)
#pragma unroll
            for (int e = 0; e < 4; e++) acc[mt][nt][e] = 0.f;

    const int K = EDIM;
    const int nchunks = K / 32;   // 32

    // issue chunk 0
    {
        const unsigned base = su;
        const size_t arow = (size_t)(bm + lrow) * K + lcol;
        const size_t brow = (size_t)(bn + lrow) * K + lcol;
        CP_ASYNC16(base + 0 * GTILE + soff,      Ahi + arow);
        CP_ASYNC16(base + 0 * GTILE + soff + 16, Ahi + arow + 8);
        CP_ASYNC16(base + 1 * GTILE + soff,      Alo + arow);
        CP_ASYNC16(base + 1 * GTILE + soff + 16, Alo + arow + 8);
        CP_ASYNC16(base + 2 * GTILE + soff,      Bhi + brow);
        CP_ASYNC16(base + 2 * GTILE + soff + 16, Bhi + brow + 8);
        CP_ASYNC16(base + 3 * GTILE + soff,      Blo + brow);
        CP_ASYNC16(base + 3 * GTILE + soff + 16, Blo + brow + 8);
        CP_COMMIT();
    }

    for (int c = 0; c < nchunks; c++) {
        CP_WAIT0();
        __syncthreads();
        const unsigned base = su + (unsigned)((c & 1) * GBUF);
        if (c + 1 < nchunks) {
            const unsigned nbase = su + (unsigned)(((c + 1) & 1) * GBUF);
            const size_t arow = (size_t)(bm + lrow) * K + (c + 1) * 32 + lcol;
            const size_t brow = (size_t)(bn + lrow) * K + (c + 1) * 32 + lcol;
            CP_ASYNC16(nbase + 0 * GTILE + soff,      Ahi + arow);
            CP_ASYNC16(nbase + 0 * GTILE + soff + 16, Ahi + arow + 8);
            CP_ASYNC16(nbase + 1 * GTILE + soff,      Alo + arow);
            CP_ASYNC16(nbase + 1 * GTILE + soff + 16, Alo + arow + 8);
            CP_ASYNC16(nbase + 2 * GTILE + soff,      Bhi + brow);
            CP_ASYNC16(nbase + 2 * GTILE + soff + 16, Bhi + brow + 8);
            CP_ASYNC16(nbase + 3 * GTILE + soff,      Blo + brow);
            CP_ASYNC16(nbase + 3 * GTILE + soff + 16, Blo + brow + 8);
            CP_COMMIT();
        }

#pragma unroll
        for (int ks = 0; ks < 2; ks++) {
            const unsigned koff = (unsigned)(ks * 32);
            unsigned bh[4][2], bl[4][2];
#pragma unroll
            for (int ntp = 0; ntp < 2; ntp++) {
                unsigned t[4];
                ldsm4(t, base + 2 * GTILE + (wn + ntp * 16) * 80 + koff + offB);
                bh[2 * ntp][0] = t[0]; bh[2 * ntp][1] = t[1];
                bh[2 * ntp + 1][0] = t[2]; bh[2 * ntp + 1][1] = t[3];
                ldsm4(t, base + 3 * GTILE + (wn + ntp * 16) * 80 + koff + offB);
                bl[2 * ntp][0] = t[0]; bl[2 * ntp][1] = t[1];
                bl[2 * ntp + 1][0] = t[2]; bl[2 * ntp + 1][1] = t[3];
            }
#pragma unroll
            for (int mt = 0; mt < 4; mt++) {
                unsigned ah[4], al[4];
                ldsm4(ah, base + 0 * GTILE + (wm + mt * 16) * 80 + koff + offA);
                ldsm4(al, base + 1 * GTILE + (wm + mt * 16) * 80 + koff + offA);
#pragma unroll
                for (int nt = 0; nt < 4; nt++) {
                    mma16816(acc[mt][nt], ah, bh[nt]);
                    mma16816(acc[mt][nt], ah, bl[nt]);
                    mma16816(acc[mt][nt], al, bh[nt]);
                }
            }
        }
    }

    if (Cf) {
        float sc = 1.0f;
        if (dwp) sc = 1.0f - *dwp;
#pragma unroll
        for (int mt = 0; mt < 4; mt++) {
#pragma unroll
            for (int nt = 0; nt < 4; nt++) {
                int row = bm + wm + mt * 16 + fr;
                int col = bn + wn + nt * 8 + fc;
                float b0 = 0.f, b1 = 0.f;
                if (bias) { b0 = bias[col]; b1 = bias[col + 1]; }
                float2 r0, r1;
                r0.x = (acc[mt][nt][0] + b0) * sc;
                r0.y = (acc[mt][nt][1] + b1) * sc;
                r1.x = (acc[mt][nt][2] + b0) * sc;
                r1.y = (acc[mt][nt][3] + b1) * sc;
                *(float2*)(Cf + (size_t)row * EDIM + col) = r0;
                *(float2*)(Cf + (size_t)(row + 8) * EDIM + col) = r1;
            }
        }
    } else {
        __nv_bfloat16* __restrict__ Chi = p.Ch[sel];
        __nv_bfloat16* __restrict__ Clo = p.Cl[sel];
#pragma unroll
        for (int mt = 0; mt < 4; mt++) {
#pragma unroll
            for (int nt = 0; nt < 4; nt++) {
                int row = bm + wm + mt * 16 + fr;
                int col = bn + wn + nt * 8 + fc;
#pragma unroll
                for (int half = 0; half < 2; half++) {
                    float v0 = acc[mt][nt][half * 2 + 0];
                    float v1 = acc[mt][nt][half * 2 + 1];
                    __nv_bfloat16 h0 = __float2bfloat16_rn(v0);
                    __nv_bfloat16 h1 = __float2bfloat16_rn(v1);
                    __nv_bfloat16 l0 = __float2bfloat16_rn(v0 - __bfloat162float(h0));
                    __nv_bfloat16 l1 = __float2bfloat16_rn(v1 - __bfloat162float(h1));
                    size_t off = (size_t)(row + half * 8) * EDIM + col;
                    *(__nv_bfloat162*)(Chi + off) = __nv_bfloat162(h0, h1);
                    *(__nv_bfloat162*)(Clo + off) = __nv_bfloat162(l0, l1);
                }
            }
        }
    }
}

// ======================================================================
// HMMA differential flash attention, BQ=128 (two 64-row q strips per CTA),
// register-resident softmax, double-buffered cp.async K/V, V-fragment reuse.
// CTA: (b, h, 128-q tile), 8 warps. Warps 0-3: branch0, 4-7: branch1.
// ======================================================================
#define BQ 128
#define BKT 64
#define QB  272   // byte stride for Q/K/V bf16 tiles (136 bf16)
#define OSR 132   // fp32 stride for O staging

#define OFF_QHI  0
#define OFF_QLO  34816
#define OFF_KV   69632       // 2 buffers x 4 tiles x 17408 bytes
#define KV_BUF   69632       // bytes per buffer set
#define KV_KHI   0
#define KV_KLO   17408
#define KV_VHI   34816
#define KV_VLO   52224
#define ATT_SMEM_BYTES (OFF_KV + 2 * KV_BUF)   // 208896

__global__ void __launch_bounds__(256) diff_attn_mma_kernel(
    const __nv_bfloat16* __restrict__ qh_g, const __nv_bfloat16* __restrict__ ql_g,
    const __nv_bfloat16* __restrict__ kh_g, const __nv_bfloat16* __restrict__ kl_g,
    const __nv_bfloat16* __restrict__ vh_g, const __nv_bfloat16* __restrict__ vl_g,
    float* __restrict__ o, const float* __restrict__ dwp)
{
    extern __shared__ char smem[];
    const unsigned su = smem_to_u32(smem);
    float* Ot = (float*)(smem + OFF_KV);              // post-loop staging (buf0)
    float* Of = (float*)(smem + OFF_KV + KV_BUF);     // post-loop combine (buf1)

    const int tid = threadIdx.x;
    const int wid = tid >> 5, L = tid & 31;
    const int fr = L >> 2;           // 0..7
    const int lm = L >> 3, lr = L & 7;
    const int qt = blockIdx.x, hd = blockIdx.y, b = blockIdx.z;
    const int q0 = qt * BQ;
    const int bidx = wid >> 2;       // branch
    const int ws = wid & 3;          // warp slot -> q rows ms..ms+15 within strip
    const int ms = ws * 16;
    const int fc2 = (L & 3) * 2;

    const unsigned offA272 = (unsigned)((lr + ((lm & 1) << 3)) * QB + ((lm >> 1) << 4));
    const unsigned offB272 = (unsigned)((lr + ((lm >> 1) << 3)) * QB + ((lm & 1) << 4));

    const size_t rowbase = (size_t)b * SLEN;

    // ---- load Q tile (hi/lo), 128 x 128 bf16 each ----
#pragma unroll
    for (int i = 0; i < 8; i++) {
        int f = tid + i * 256;               // 0..2047
        int r = f >> 4, c = f & 15;
        size_t src = (rowbase + q0 + r) * EDIM + hd * 128 + c * 8;
        *(uint4*)(smem + OFF_QHI + r * QB + c * 16) = *(const uint4*)(qh_g + src);
        *(uint4*)(smem + OFF_QLO + r * QB + c * 16) = *(const uint4*)(ql_g + src);
    }

    float mA[2] = { -1e30f, -1e30f }, mB[2] = { -1e30f, -1e30f };
    float lA[2] = { 0.f, 0.f }, lB[2] = { 0.f, 0.f };
    float pacc[2][16][4];
#pragma unroll
    for (int s = 0; s < 2; s++)
#pragma unroll
        for (int nt = 0; nt < 16; nt++)
#pragma unroll
            for (int e = 0; e < 4; e++) pacc[s][nt][e] = 0.f;

    unsigned Pfh[2][4][4], Pfl[2][4][4];

    const float scale = 0.125f;
    const int NT = SLEN / BKT;   // 32

    // issue tile 0 into buffer 0
    {
        const unsigned kvb = su + OFF_KV;
#pragma unroll
        for (int i = 0; i < 4; i++) {
            int f = tid + i * 256;
            int r = f >> 4, c = f & 15;
            size_t src = (rowbase + r) * EDIM + hd * 128 + c * 8;
            unsigned dsm = kvb + r * QB + c * 16;
            CP_ASYNC16(dsm + KV_KHI, kh_g + src);
            CP_ASYNC16(dsm + KV_KLO, kl_g + src);
            CP_ASYNC16(dsm + KV_VHI, vh_g + src);
            CP_ASYNC16(dsm + KV_VLO, vl_g + src);
        }
        CP_COMMIT();
    }

    for (int t = 0; t < NT; t++) {
        if (t > 0) __syncthreads();
        if (t + 1 < NT) {
            const unsigned kvb = su + OFF_KV + ((t + 1) & 1) * KV_BUF;
            const int kt1 = (t + 1) * BKT;
#pragma unroll
            for (int i = 0; i < 4; i++) {
                int f = tid + i * 256;
                int r = f >> 4, c = f & 15;
                size_t src = (rowbase + kt1 + r) * EDIM + hd * 128 + c * 8;
                unsigned dsm = kvb + r * QB + c * 16;
                CP_ASYNC16(dsm + KV_KHI, kh_g + src);
                CP_ASYNC16(dsm + KV_KLO, kl_g + src);
                CP_ASYNC16(dsm + KV_VHI, vh_g + src);
                CP_ASYNC16(dsm + KV_VLO, vl_g + src);
            }
            CP_COMMIT();
            CP_WAIT1();
        } else {
            CP_WAIT0();
        }
        __syncthreads();

        const unsigned kvb = su + OFF_KV + (t & 1) * KV_BUF;

        // ---- per strip: QK^T + softmax + P pack ----
#pragma unroll
        for (int s = 0; s < 2; s++) {
            float sacc[8][4];
#pragma unroll
            for (int nt = 0; nt < 8; nt++)
#pragma unroll
                for (int e = 0; e < 4; e++) sacc[nt][e] = 0.f;

            const unsigned qrow = (unsigned)((s * 64 + ms) * QB);
#pragma unroll
            for (int ks = 0; ks < 4; ks++) {
                const unsigned kofb = (unsigned)(bidx * 128 + ks * 32);
                unsigned ah[4], al[4];
                ldsm4(ah, su + OFF_QHI + qrow + kofb + offA272);
                ldsm4(al, su + OFF_QLO + qrow + kofb + offA272);
#pragma unroll
                for (int ntp = 0; ntp < 4; ntp++) {
                    unsigned th[4], tl[4];
                    ldsm4(th, kvb + KV_KHI + (ntp * 16) * QB + kofb + offB272);
                    ldsm4(tl, kvb + KV_KLO + (ntp * 16) * QB + kofb + offB272);
                    mma16816(sacc[2 * ntp], ah, th);
                    mma16816(sacc[2 * ntp], ah, tl);
                    mma16816(sacc[2 * ntp], al, th);
                    mma16816(sacc[2 * ntp + 1], ah, th + 2);
                    mma16816(sacc[2 * ntp + 1], ah, tl + 2);
                    mma16816(sacc[2 * ntp + 1], al, th + 2);
                }
            }
#pragma unroll
            for (int nt = 0; nt < 8; nt++)
#pragma unroll
                for (int e = 0; e < 4; e++) sacc[nt][e] *= scale;

            // register-resident online softmax for this strip
            {
                float ra = -1e30f, rb = -1e30f;
#pragma unroll
                for (int nt = 0; nt < 8; nt++) {
                    ra = fmaxf(ra, fmaxf(sacc[nt][0], sacc[nt][1]));
                    rb = fmaxf(rb, fmaxf(sacc[nt][2], sacc[nt][3]));
                }
                ra = fmaxf(ra, __shfl_xor_sync(0xffffffffu, ra, 1));
                ra = fmaxf(ra, __shfl_xor_sync(0xffffffffu, ra, 2));
                rb = fmaxf(rb, __shfl_xor_sync(0xffffffffu, rb, 1));
                rb = fmaxf(rb, __shfl_xor_sync(0xffffffffu, rb, 2));
                float mna = fmaxf(mA[s], ra), mnb = fmaxf(mB[s], rb);
                float cca = __expf(mA[s] - mna), ccb = __expf(mB[s] - mnb);
                mA[s] = mna; mB[s] = mnb;
                float suma = 0.f, sumb = 0.f;
#pragma unroll
                for (int nt = 0; nt < 8; nt++) {
                    sacc[nt][0] = __expf(sacc[nt][0] - mna); suma += sacc[nt][0];
                    sacc[nt][1] = __expf(sacc[nt][1] - mna); suma += sacc[nt][1];
                    sacc[nt][2] = __expf(sacc[nt][2] - mnb); sumb += sacc[nt][2];
                    sacc[nt][3] = __expf(sacc[nt][3] - mnb); sumb += sacc[nt][3];
                }
                suma += __shfl_xor_sync(0xffffffffu, suma, 1);
                suma += __shfl_xor_sync(0xffffffffu, suma, 2);
                sumb += __shfl_xor_sync(0xffffffffu, sumb, 1);
                sumb += __shfl_xor_sync(0xffffffffu, sumb, 2);
                lA[s] = lA[s] * cca + suma;
                lB[s] = lB[s] * ccb + sumb;
#pragma unroll
                for (int nt = 0; nt < 16; nt++) {
                    pacc[s][nt][0] *= cca; pacc[s][nt][1] *= cca;
                    pacc[s][nt][2] *= ccb; pacc[s][nt][3] *= ccb;
                }
            }

            // pack P into register A-fragments (C-frag == A-frag layout)
#pragma unroll
            for (int ks = 0; ks < 4; ks++) {
#pragma unroll
                for (int half = 0; half < 2; half++) {
                    const float* s0 = sacc[2 * ks + half];
                    unsigned p01 = cvt2(s0[1], s0[0]);
                    unsigned p23 = cvt2(s0[3], s0[2]);
                    float r0 = s0[0] - __uint_as_float(p01 << 16);
                    float r1 = s0[1] - __uint_as_float(p01 & 0xFFFF0000u);
                    float r2 = s0[2] - __uint_as_float(p23 << 16);
                    float r3 = s0[3] - __uint_as_float(p23 & 0xFFFF0000u);
                    Pfh[s][ks][2 * half + 0] = p01;
                    Pfh[s][ks][2 * half + 1] = p23;
                    Pfl[s][ks][2 * half + 0] = cvt2(r1, r0);
                    Pfl[s][ks][2 * half + 1] = cvt2(r3, r2);
                }
            }
        }

        // ---- PV: V fragments shared across both strips ----
#pragma unroll
        for (int ks = 0; ks < 4; ks++) {
#pragma unroll
            for (int dtp = 0; dtp < 8; dtp++) {
                unsigned vh[4], vl[4];
                ldsm4t(vh, kvb + KV_VHI + (ks * 16) * QB + dtp * 32 + offA272);
                ldsm4t(vl, kvb + KV_VLO + (ks * 16) * QB + dtp * 32 + offA272);
#pragma unroll
                for (int s = 0; s < 2; s++) {
                    mma16816(pacc[s][2 * dtp], Pfh[s][ks], vh);
                    mma16816(pacc[s][2 * dtp], Pfh[s][ks], vl);
                    mma16816(pacc[s][2 * dtp], Pfl[s][ks], vh);
                    mma16816(pacc[s][2 * dtp + 1], Pfh[s][ks], vh + 2);
                    mma16816(pacc[s][2 * dtp + 1], Pfh[s][ks], vl + 2);
                    mma16816(pacc[s][2 * dtp + 1], Pfl[s][ks], vh + 2);
                }
            }
        }
    }
    __syncthreads();

    // ---- epilogue: o = O0/l0 - dw * O1/l1 ----
    const float dw = *dwp;
    if (bidx == 1) {
#pragma unroll
        for (int s = 0; s < 2; s++) {
            const float i0 = 1.f / lA[s], i1 = 1.f / lB[s];
            const int r0 = s * 64 + ms + fr;
#pragma unroll
            for (int nt = 0; nt < 16; nt++) {
                int d = nt * 8 + fc2;
                *(float2*)&Ot[r0 * OSR + d] =
                    make_float2(pacc[s][nt][0] * i0, pacc[s][nt][1] * i0);
                *(float2*)&Ot[(r0 + 8) * OSR + d] =
                    make_float2(pacc[s][nt][2] * i1, pacc[s][nt][3] * i1);
            }
        }
    }
    __syncthreads();
    if (bidx == 0) {
#pragma unroll
        for (int s = 0; s < 2; s++) {
            const float i0 = 1.f / lA[s], i1 = 1.f / lB[s];
            const int r0 = s * 64 + ms + fr;
#pragma unroll
            for (int nt = 0; nt < 16; nt++) {
                int d = nt * 8 + fc2;
                float2 t0 = *(float2*)&Ot[r0 * OSR + d];
                float2 t1 = *(float2*)&Ot[(r0 + 8) * OSR + d];
                *(float2*)&Of[r0 * OSR + d] =
                    make_float2(pacc[s][nt][0] * i0 - dw * t0.x,
                                pacc[s][nt][1] * i0 - dw * t0.y);
                *(float2*)&Of[(r0 + 8) * OSR + d] =
                    make_float2(pacc[s][nt][2] * i1 - dw * t1.x,
                                pacc[s][nt][3] * i1 - dw * t1.y);
            }
        }
    }
    __syncthreads();

    float* og = o + (rowbase + q0) * EDIM + hd * 128;
#pragma unroll
    for (int i = 0; i < 16; i++) {
        int f = tid + i * 256;
        int r = f >> 5, c4 = f & 31;
        *(float4*)(og + (size_t)r * EDIM + c4 * 4) = *(const float4*)&Of[r * OSR + c4 * 4];
    }
}

// ======================================================================
// RMSNorm over 1024-wide rows, fused split-bf16 output
// ======================================================================
__global__ void __launch_bounds__(256) rmsnorm_split_kernel(
    const float* __restrict__ x, const float* __restrict__ w,
    __nv_bfloat16* __restrict__ yhi, __nv_bfloat16* __restrict__ ylo)
{
    __shared__ float red[8];
    __shared__ float rtot;
    const int tid = threadIdx.x;
    const int row = blockIdx.x;
    const float* xr = x + (size_t)row * EDIM;

    float v[4];
    float s = 0.f;
#pragma unroll
    for (int j = 0; j < 4; j++) {
        v[j] = xr[tid + j * 256];
        s = fmaf(v[j], v[j], s);
    }
#pragma unroll
    for (int off = 16; off > 0; off >>= 1)
        s += __shfl_xor_sync(0xffffffffu, s, off);
    if ((tid & 31) == 0) red[tid >> 5] = s;
    __syncthreads();
    if (tid == 0) {
        float t = 0.f;
#pragma unroll
        for (int i = 0; i < 8; i++) t += red[i];
        rtot = rsqrtf(t * (1.0f / 1024.0f) + 1.1920929e-07f);
    }
    __syncthreads();
    float r = rtot;
#pragma unroll
    for (int j = 0; j < 4; j++) {
        int c = tid + j * 256;
        float f = v[j] * r * w[c];
        __nv_bfloat16 h = __float2bfloat16_rn(f);
        __nv_bfloat16 l = __float2bfloat16_rn(f - __bfloat162float(h));
        yhi[(size_t)row * EDIM + c] = h;
        ylo[(size_t)row * EDIM + c] = l;
    }
}

// ======================================================================
// launcher
// ======================================================================
extern "C" void kernel_launch(void* const* d_in, const int* in_sizes, int n_in,
                              void* d_out, int out_size)
{
    const float* x  = (const float*)d_in[0];
    const float* Wq = (const float*)d_in[1];
    const float* Wk = (const float*)d_in[2];
    const float* Wv = (const float*)d_in[3];
    const float* nw = (const float*)d_in[4];
    const float* Wo = (const float*)d_in[5];
    const float* bo = (const float*)d_in[6];
    const float* dw = (const float*)d_in[7];
    float* out = (float*)d_out;

    float* op;
    cudaGetSymbolAddress((void**)&op, g_o);
    __nv_bfloat16 *xh, *xl, *nh, *nl;
    cudaGetSymbolAddress((void**)&xh, g_xhi);
    cudaGetSymbolAddress((void**)&xl, g_xlo);
    cudaGetSymbolAddress((void**)&nh, g_nhi);
    cudaGetSymbolAddress((void**)&nl, g_nlo);
    __nv_bfloat16 *qh, *ql, *kh, *kl, *vh, *vl;
    cudaGetSymbolAddress((void**)&qh, g_qh);
    cudaGetSymbolAddress((void**)&ql, g_ql);
    cudaGetSymbolAddress((void**)&kh, g_kh);
    cudaGetSymbolAddress((void**)&kl, g_kl);
    cudaGetSymbolAddress((void**)&vh, g_vh);
    cudaGetSymbolAddress((void**)&vl, g_vl);
    __nv_bfloat16 *wqh, *wql, *wkh, *wkl, *wvh, *wvl, *woh, *wol;
    cudaGetSymbolAddress((void**)&wqh, g_wqhi);
    cudaGetSymbolAddress((void**)&wql, g_wqlo);
    cudaGetSymbolAddress((void**)&wkh, g_wkhi);
    cudaGetSymbolAddress((void**)&wkl, g_wklo);
    cudaGetSymbolAddress((void**)&wvh, g_wvhi);
    cudaGetSymbolAddress((void**)&wvl, g_wvlo);
    cudaGetSymbolAddress((void**)&woh, g_wohi);
    cudaGetSymbolAddress((void**)&wol, g_wolo);

    cudaFuncSetAttribute(diff_attn_mma_kernel,
                         cudaFuncAttributeMaxDynamicSharedMemorySize, ATT_SMEM_BYTES);
    cudaFuncSetAttribute(mma_gemm_kernel,
                         cudaFuncAttributeMaxDynamicSharedMemorySize, GSMEM_BYTES);

    // split conversions
    const int xn4 = MROWS * EDIM / 4;
    const int wn4 = EDIM * EDIM / 4;
    split_bf16_kernel<<<xn4 / 256, 256>>>(x,  xh, xl, xn4);
    split_bf16_kernel<<<wn4 / 256, 256>>>(Wq, wqh, wql, wn4);
    split_bf16_kernel<<<wn4 / 256, 256>>>(Wk, wkh, wkl, wn4);
    split_bf16_kernel<<<wn4 / 256, 256>>>(Wv, wvh, wvl, wn4);
    split_bf16_kernel<<<wn4 / 256, 256>>>(Wo, woh, wol, wn4);

    // fused QKV projections (HMMA split-bf16, BK=32, bf16 hi/lo output)
    QKVPtrs pq;
    pq.Bh[0] = wqh; pq.Bl[0] = wql; pq.Ch[0] = qh; pq.Cl[0] = ql;
    pq.Bh[1] = wkh; pq.Bl[1] = wkl; pq.Ch[1] = kh; pq.Cl[1] = kl;
    pq.Bh[2] = wvh; pq.Bl[2] = wvl; pq.Ch[2] = vh; pq.Cl[2] = vl;
    dim3 gq(24, MROWS / 128);
    mma_gemm_kernel<<<gq, 256, GSMEM_BYTES>>>(xh, xl, pq, nullptr, nullptr, nullptr);

    // attention (HMMA, BQ=128, register softmax, double-buffered K/V)
    dim3 ga(SLEN / BQ, NHEAD, 2);
    diff_attn_mma_kernel<<<ga, 256, ATT_SMEM_BYTES>>>(qh, ql, kh, kl, vh, vl, op, dw);

    // rmsnorm + split
    rmsnorm_split_kernel<<<MROWS, 256>>>(op, nw, nh, nl);

    // output projection with bias + (1-dw) scale
    QKVPtrs po;
    po.Bh[0] = woh; po.Bl[0] = wol; po.Ch[0] = nullptr; po.Cl[0] = nullptr;
    po.Bh[1] = woh; po.Bl[1] = wol; po.Ch[1] = nullptr; po.Cl[1] = nullptr;
    po.Bh[2] = woh; po.Bl[2] = wol; po.Ch[2] = nullptr; po.Cl[2] = nullptr;
    dim3 go(8, MROWS / 128);
    mma_gemm_kernel<<<go, 256, GSMEM_BYTES>>>(nh, nl, po, out, bo, dw);
}